// round 4
// baseline (speedup 1.0000x reference)
#include <cuda_runtime.h>
#include <math.h>
#include <float.h>

// Problem dims
#define B_   2
#define N_   2048
#define D_   1024
#define H_   16
#define DH_  64
#define C_   64
#define NK_  2049            // N+1 (null kv prepended)
#define BH_  (B_*H_)         // 32
#define ROWS_ (B_*N_)        // 4096
#define LDBIAS_ (C_+N_)      // 2112

// Scratch (device globals: allocation-free rule)
__device__ float g_xn[ROWS_*D_];        // layernormed x
__device__ float g_q [BH_*N_ *DH_];     // head-major q (tf32-rounded)
__device__ float g_k [BH_*NK_*DH_];     // head-major k (row 0 = null, tf32-rounded)
__device__ float g_v [BH_*NK_*DH_];     // head-major v (row 0 = null, tf32-rounded)
__device__ float g_ao[ROWS_*D_];        // attention output (tf32-rounded)
__device__ int   g_mask_mode;           // 1 = 1-byte mask, 0 = 4-byte mask

// ---------------------------------------------------------------------------
// tf32 helpers
// ---------------------------------------------------------------------------
__device__ __forceinline__ unsigned f2tf(float f) {
    unsigned u;
    asm("cvt.rna.tf32.f32 %0, %1;" : "=r"(u) : "f"(f));
    return u;
}
__device__ __forceinline__ float f2tff(float f) { return __uint_as_float(f2tf(f)); }

__device__ __forceinline__ void mma8(float* c, const unsigned* a, const unsigned* b) {
    asm volatile(
        "mma.sync.aligned.m16n8k8.row.col.f32.tf32.tf32.f32 "
        "{%0,%1,%2,%3}, {%4,%5,%6,%7}, {%8,%9}, {%0,%1,%2,%3};"
        : "+f"(c[0]), "+f"(c[1]), "+f"(c[2]), "+f"(c[3])
        : "r"(a[0]), "r"(a[1]), "r"(a[2]), "r"(a[3]), "r"(b[0]), "r"(b[1]));
}

__device__ __forceinline__ void cpa16(unsigned dst, const void* src, int ok) {
    asm volatile("cp.async.ca.shared.global [%0], [%1], 16, %2;"
                 :: "r"(dst), "l"(src), "r"(ok ? 16 : 0));
}
__device__ __forceinline__ void cpa_commit() {
    asm volatile("cp.async.commit_group;");
}
__device__ __forceinline__ void cpa_wait1() {
    asm volatile("cp.async.wait_group 1;");
}

// ---------------------------------------------------------------------------
// Mask dtype detection (bool may be 1-byte or 4-byte serialized)
// ---------------------------------------------------------------------------
__global__ void detect_mask_kernel(const unsigned char* __restrict__ cm) {
    __shared__ int flag;
    if (threadIdx.x == 0) flag = 0;
    __syncthreads();
    int any = 0;
    for (int i = threadIdx.x; i < 1024; i += blockDim.x)
        if (cm[4*i + 1] != 0) any = 1;
    if (any) atomicOr(&flag, 1);
    __syncthreads();
    if (threadIdx.x == 0) g_mask_mode = flag;
}

// ---------------------------------------------------------------------------
// LayerNorm
// ---------------------------------------------------------------------------
__global__ void ln_kernel(const float* __restrict__ x,
                          const float* __restrict__ gamma) {
    const int row = blockIdx.x;
    const int tid = threadIdx.x;
    const float4 a = ((const float4*)(x + (size_t)row * D_))[tid];
    float s  = a.x + a.y + a.z + a.w;
    float s2 = a.x*a.x + a.y*a.y + a.z*a.z + a.w*a.w;
    #pragma unroll
    for (int o = 16; o > 0; o >>= 1) {
        s  += __shfl_xor_sync(0xFFFFFFFFu, s,  o);
        s2 += __shfl_xor_sync(0xFFFFFFFFu, s2, o);
    }
    __shared__ float rs[8], rs2[8];
    if ((tid & 31) == 0) { rs[tid >> 5] = s; rs2[tid >> 5] = s2; }
    __syncthreads();
    float S = 0.f, S2 = 0.f;
    #pragma unroll
    for (int i = 0; i < 8; i++) { S += rs[i]; S2 += rs2[i]; }
    const float mu  = S * (1.0f / D_);
    const float var = S2 * (1.0f / D_) - mu * mu;
    const float inv = rsqrtf(var + 1e-5f);
    const float4 g = ((const float4*)gamma)[tid];
    float4 o;
    o.x = (a.x - mu) * inv * g.x;
    o.y = (a.y - mu) * inv * g.y;
    o.z = (a.z - mu) * inv * g.z;
    o.w = (a.w - mu) * inv * g.w;
    ((float4*)(g_xn + (size_t)row * D_))[tid] = o;
}

// ---------------------------------------------------------------------------
// tf32 tensor-core GEMM core: 128x128 tile, BK=16, 256 threads (8 warps 4x2).
// ---------------------------------------------------------------------------
#define AS_STR 20
#define BS_STR2 136

struct GemmSmem {
    float As[2][128*AS_STR];
    float Bs[2][16*BS_STR2];
};

__device__ __forceinline__ void gemm_core_compute(
    const GemmSmem* sm, int buf, int wm, int wn, int gid, int tig,
    float acc[2][8][4])
{
    const unsigned* ab = (const unsigned*)sm->As[buf];
    const unsigned* bb = (const unsigned*)sm->Bs[buf];
    #pragma unroll
    for (int kk = 0; kk < 2; kk++) {
        unsigned afr[2][4];
        #pragma unroll
        for (int mt = 0; mt < 2; mt++) {
            const int r = wm*32 + mt*16 + gid;
            const int c = kk*8 + tig;
            afr[mt][0] = ab[(size_t)r*AS_STR + c];
            afr[mt][1] = ab[(size_t)(r+8)*AS_STR + c];
            afr[mt][2] = ab[(size_t)r*AS_STR + c + 4];
            afr[mt][3] = ab[(size_t)(r+8)*AS_STR + c + 4];
        }
        unsigned bfr[8][2];
        #pragma unroll
        for (int nt = 0; nt < 8; nt++) {
            const int k = kk*8 + tig;
            const int n = wn*64 + nt*8 + gid;
            bfr[nt][0] = bb[(size_t)k*BS_STR2 + n];
            bfr[nt][1] = bb[(size_t)(k+4)*BS_STR2 + n];
        }
        #pragma unroll
        for (int mt = 0; mt < 2; mt++)
            #pragma unroll
            for (int nt = 0; nt < 8; nt++)
                mma8(acc[mt][nt], afr[mt], bfr[nt]);
    }
}

__device__ __forceinline__ void gemm_main_loop(
    const float* __restrict__ A, const float* __restrict__ Bp,
    int ldb, int cb, int bm, GemmSmem* sm,
    int wm, int wn, int gid, int tig, float acc[2][8][4])
{
    const int tid = threadIdx.x;
    const int ar = tid >> 2, akc = (tid & 3) * 4;
    const int bk = tid >> 5, bnc = (tid & 31) * 4;

    float4 ra0, ra1, rb0, rb1;
    ra0 = *(const float4*)(A + (size_t)(bm + ar) * 1024 + akc);
    ra1 = *(const float4*)(A + (size_t)(bm + ar + 64) * 1024 + akc);
    rb0 = *(const float4*)(Bp + (size_t)bk * ldb + cb + bnc);
    rb1 = *(const float4*)(Bp + (size_t)(bk + 8) * ldb + cb + bnc);
    {
        unsigned* d0 = (unsigned*)&sm->As[0][ar*AS_STR + akc];
        d0[0]=f2tf(ra0.x); d0[1]=f2tf(ra0.y); d0[2]=f2tf(ra0.z); d0[3]=f2tf(ra0.w);
        unsigned* d1 = (unsigned*)&sm->As[0][(ar+64)*AS_STR + akc];
        d1[0]=f2tf(ra1.x); d1[1]=f2tf(ra1.y); d1[2]=f2tf(ra1.z); d1[3]=f2tf(ra1.w);
        unsigned* e0 = (unsigned*)&sm->Bs[0][bk*BS_STR2 + bnc];
        e0[0]=f2tf(rb0.x); e0[1]=f2tf(rb0.y); e0[2]=f2tf(rb0.z); e0[3]=f2tf(rb0.w);
        unsigned* e1 = (unsigned*)&sm->Bs[0][(bk+8)*BS_STR2 + bnc];
        e1[0]=f2tf(rb1.x); e1[1]=f2tf(rb1.y); e1[2]=f2tf(rb1.z); e1[3]=f2tf(rb1.w);
    }
    __syncthreads();

    int buf = 0;
    for (int kt = 0; kt < 64; kt++) {
        if (kt < 63) {
            const int k0 = (kt + 1) * 16;
            ra0 = *(const float4*)(A + (size_t)(bm + ar) * 1024 + k0 + akc);
            ra1 = *(const float4*)(A + (size_t)(bm + ar + 64) * 1024 + k0 + akc);
            rb0 = *(const float4*)(Bp + (size_t)(k0 + bk) * ldb + cb + bnc);
            rb1 = *(const float4*)(Bp + (size_t)(k0 + bk + 8) * ldb + cb + bnc);
        }
        gemm_core_compute(sm, buf, wm, wn, gid, tig, acc);
        if (kt < 63) {
            const int nb = buf ^ 1;
            unsigned* d0 = (unsigned*)&sm->As[nb][ar*AS_STR + akc];
            d0[0]=f2tf(ra0.x); d0[1]=f2tf(ra0.y); d0[2]=f2tf(ra0.z); d0[3]=f2tf(ra0.w);
            unsigned* d1 = (unsigned*)&sm->As[nb][(ar+64)*AS_STR + akc];
            d1[0]=f2tf(ra1.x); d1[1]=f2tf(ra1.y); d1[2]=f2tf(ra1.z); d1[3]=f2tf(ra1.w);
            unsigned* e0 = (unsigned*)&sm->Bs[nb][bk*BS_STR2 + bnc];
            e0[0]=f2tf(rb0.x); e0[1]=f2tf(rb0.y); e0[2]=f2tf(rb0.z); e0[3]=f2tf(rb0.w);
            unsigned* e1 = (unsigned*)&sm->Bs[nb][(bk+8)*BS_STR2 + bnc];
            e1[0]=f2tf(rb1.x); e1[1]=f2tf(rb1.y); e1[2]=f2tf(rb1.z); e1[3]=f2tf(rb1.w);
            __syncthreads();
            buf = nb;
        }
    }
}

// QKV GEMM: C(4096 x 3072) = xn @ [Wq | Wkv], scatter epilogue into q/k/v
__global__ __launch_bounds__(256)
void gemm_qkv_tc(const float* __restrict__ Wq, const float* __restrict__ Wkv) {
    __shared__ GemmSmem sm;
    const int tid = threadIdx.x;
    const int wid = tid >> 5, lane = tid & 31;
    const int gid = lane >> 2, tig = lane & 3;
    const int wm = wid & 3, wn = wid >> 2;
    const int bm = blockIdx.y * 128, bn = blockIdx.x * 128;
    const float* Bp; int ldb, cb;
    if (bn < 1024) { Bp = Wq;  ldb = 1024; cb = bn; }
    else           { Bp = Wkv; ldb = 2048; cb = bn - 1024; }

    float acc[2][8][4] = {};
    gemm_main_loop(g_xn, Bp, ldb, cb, bm, &sm, wm, wn, gid, tig, acc);

    #pragma unroll
    for (int mt = 0; mt < 2; mt++) {
        #pragma unroll
        for (int i = 0; i < 2; i++) {
            const int row = bm + wm*32 + mt*16 + gid + i*8;
            const int bidx = row >> 11, n = row & 2047;
            #pragma unroll
            for (int nt = 0; nt < 8; nt++) {
                const int col = bn + wn*64 + nt*8 + 2*tig;
                if (col < 1024) {
                    const int hh = col >> 6, d = col & 63;
                    *(float2*)&g_q[(((size_t)(bidx*H_ + hh))*N_ + n)*DH_ + d] =
                        make_float2(acc[mt][nt][i*2], acc[mt][nt][i*2+1]);
                } else if (col < 2048) {
                    const int cc = col - 1024, hh = cc >> 6, d = cc & 63;
                    *(float2*)&g_k[(((size_t)(bidx*H_ + hh))*NK_ + n + 1)*DH_ + d] =
                        make_float2(acc[mt][nt][i*2], acc[mt][nt][i*2+1]);
                } else {
                    // v: pre-round to tf32 (PV MMA consumes tf32 anyway — identical numerics)
                    const int cc = col - 2048, hh = cc >> 6, d = cc & 63;
                    *(float2*)&g_v[(((size_t)(bidx*H_ + hh))*NK_ + n + 1)*DH_ + d] =
                        make_float2(f2tff(acc[mt][nt][i*2]), f2tff(acc[mt][nt][i*2+1]));
                }
            }
        }
    }
}

// Output GEMM: d_out(4096 x 1024) = g_ao @ Wout
__global__ __launch_bounds__(256)
void gemm_out_tc(const float* __restrict__ Wout, float* __restrict__ out) {
    __shared__ GemmSmem sm;
    const int tid = threadIdx.x;
    const int wid = tid >> 5, lane = tid & 31;
    const int gid = lane >> 2, tig = lane & 3;
    const int wm = wid & 3, wn = wid >> 2;
    const int bm = blockIdx.y * 128, bn = blockIdx.x * 128;

    float acc[2][8][4] = {};
    gemm_main_loop(g_ao, Wout, 1024, bn, bm, &sm, wm, wn, gid, tig, acc);

    #pragma unroll
    for (int mt = 0; mt < 2; mt++) {
        #pragma unroll
        for (int i = 0; i < 2; i++) {
            const int row = bm + wm*32 + mt*16 + gid + i*8;
            #pragma unroll
            for (int nt = 0; nt < 8; nt++) {
                const int col = bn + wn*64 + nt*8 + 2*tig;
                *(float2*)&out[(size_t)row*1024 + col] =
                    make_float2(acc[mt][nt][i*2], acc[mt][nt][i*2+1]);
            }
        }
    }
}

// ---------------------------------------------------------------------------
// l2norm + scales + null kv fill. Writes tf32-PREROUNDED q and k (identical
// numerics to rounding at attention staging; norms computed in full fp32).
// ---------------------------------------------------------------------------
__global__ void norm_kernel(const float* __restrict__ null_kv,
                            const float* __restrict__ q_scale,
                            const float* __restrict__ k_scale) {
    const int gw   = (blockIdx.x * blockDim.x + threadIdx.x) >> 5;
    const int lane = threadIdx.x & 31;
    if (gw >= BH_ * NK_) return;
    const int bh = gw / NK_, j = gw - bh * NK_;
    const int h  = bh & 15;
    const int d0 = lane, d1 = lane + 32;
    const float ks0 = k_scale[d0], ks1 = k_scale[d1];

    if (j == 0) {
        const float k0 = null_kv[h*DH_ + d0], k1 = null_kv[h*DH_ + d1];
        const float v0 = null_kv[H_*DH_ + h*DH_ + d0];
        const float v1 = null_kv[H_*DH_ + h*DH_ + d1];
        float ss = k0*k0 + k1*k1;
        #pragma unroll
        for (int o = 16; o > 0; o >>= 1) ss += __shfl_xor_sync(0xFFFFFFFFu, ss, o);
        const float inv = 1.0f / fmaxf(sqrtf(ss), 1e-12f);
        float* kp = g_k + (size_t)bh * NK_ * DH_;
        float* vp = g_v + (size_t)bh * NK_ * DH_;
        kp[d0] = f2tff(k0*inv*ks0); kp[d1] = f2tff(k1*inv*ks1);
        vp[d0] = f2tff(v0);         vp[d1] = f2tff(v1);
    } else {
        float* kp = g_k + ((size_t)bh * NK_ + j) * DH_;
        float* qp = g_q + ((size_t)bh * N_ + (j-1)) * DH_;
        const float k0 = kp[d0], k1 = kp[d1];
        const float q0 = qp[d0], q1 = qp[d1];
        float ssk = k0*k0 + k1*k1;
        float ssq = q0*q0 + q1*q1;
        #pragma unroll
        for (int o = 16; o > 0; o >>= 1) {
            ssk += __shfl_xor_sync(0xFFFFFFFFu, ssk, o);
            ssq += __shfl_xor_sync(0xFFFFFFFFu, ssq, o);
        }
        const float invk = 1.0f / fmaxf(sqrtf(ssk), 1e-12f);
        const float invq = 1.0f / fmaxf(sqrtf(ssq), 1e-12f);
        const float qs0 = q_scale[d0], qs1 = q_scale[d1];
        kp[d0] = f2tff(k0*invk*ks0); kp[d1] = f2tff(k1*invk*ks1);
        qp[d0] = f2tff(q0*invq*qs0); qp[d1] = f2tff(q1*invq*qs1);
    }
}

// ---------------------------------------------------------------------------
// tf32 tensor-core flash attention v2:
// 256 threads (8 warps), 128 q-rows per block, grid = BH*16 = 512.
// K/V double-buffered via cp.async (pre-rounded tf32 in gmem → raw copy).
// Bias prefetched into registers (hidden under S-MMA); mask precomputed once.
// Smem: K[2][64*68] V[2][64*72] P[8][16*68] msk[2112B] = 108608 B.
// ---------------------------------------------------------------------------
#define KS_STR 68
#define VS_STR 72
#define PS_STR 68

__global__ __launch_bounds__(256)
void attn_tc2(const float* __restrict__ attn_bias,
              const void*  __restrict__ cmask) {
    extern __shared__ float smf[];
    float* Ksf = smf;                       // 2 * 64*68 = 8704 floats
    float* Vsf = smf + 8704;                // 2 * 64*72 = 9216 floats
    float* Psf = smf + 17920;               // 8 * 16*68 = 8704 floats
    unsigned char* msk = (unsigned char*)(smf + 26624);  // 2112 bytes

    const int tid = threadIdx.x;
    const int wid = tid >> 5, lane = tid & 31;
    const int gid = lane >> 2, tig = lane & 3;
    const int qt = blockIdx.x & 15, bh = blockIdx.x >> 4;
    const int b = bh >> 4, h = bh & 15;
    const int i0 = qt * 128;
    const int mode = g_mask_mode;
    const unsigned char* m8  = (const unsigned char*)cmask;
    const unsigned*      m32 = (const unsigned*)cmask;

    // precompute mask byte per column jg in [0, 2112)
    for (int j = tid; j < 2112; j += 256) {
        int val = 0;
        if (j == 0) val = 1;
        else if (j <= N_)
            val = mode ? (m8[b*N_ + j-1] != 0) : (m32[b*N_ + j-1] != 0u);
        msk[j] = (unsigned char)val;
    }

    // Q fragments: pre-rounded tf32 bits, register-resident
    unsigned qa[8][4];
    {
        const float* qb = g_q + ((size_t)bh*N_ + i0 + wid*16)*DH_;
        #pragma unroll
        for (int ks = 0; ks < 8; ks++) {
            qa[ks][0] = __float_as_uint(qb[gid*64 + ks*8 + tig]);
            qa[ks][1] = __float_as_uint(qb[(gid+8)*64 + ks*8 + tig]);
            qa[ks][2] = __float_as_uint(qb[gid*64 + ks*8 + tig + 4]);
            qa[ks][3] = __float_as_uint(qb[(gid+8)*64 + ks*8 + tig + 4]);
        }
    }

    float O[8][4];
    #pragma unroll
    for (int nt = 0; nt < 8; nt++)
        #pragma unroll
        for (int i = 0; i < 4; i++) O[nt][i] = 0.f;
    float m0 = -FLT_MAX, m1 = -FLT_MAX, l0 = 0.f, l1 = 0.f;

    const float* kb = g_k + (size_t)bh * NK_ * DH_;
    const float* vb = g_v + (size_t)bh * NK_ * DH_;
    unsigned* Pu = (unsigned*)Psf;
    unsigned* pw = Pu + wid * (16 * PS_STR);
    const float* biasA = attn_bias + (size_t)(C_ + i0 + wid*16 + gid)*LDBIAS_ + (C_ - 1);
    const float* biasB = biasA + (size_t)8*LDBIAS_;

    const unsigned ks_s0 = (unsigned)__cvta_generic_to_shared(Ksf);
    const unsigned vs_s0 = (unsigned)__cvta_generic_to_shared(Vsf);
    const int cpr = tid >> 4, cpc = (tid & 15) * 4;   // this thread's 4 chunk rows start

    // prefetch tile t into buffer (t&1)
    auto prefetch = [&](int t) {
        const int jb = t * 64;
        const unsigned kdst = ks_s0 + (unsigned)((t & 1) * 4352 * 4);
        const unsigned vdst = vs_s0 + (unsigned)((t & 1) * 4608 * 4);
        #pragma unroll
        for (int i = 0; i < 4; i++) {
            const int r = cpr + i*16;
            const int ok = (jb + r) < NK_;
            cpa16(kdst + (unsigned)(r*KS_STR + cpc)*4, kb + (size_t)(jb + r)*64 + cpc, ok);
            cpa16(vdst + (unsigned)(r*VS_STR + cpc)*4, vb + (size_t)(jb + r)*64 + cpc, ok);
        }
    };

    prefetch(0);
    cpa_commit();
    __syncthreads();   // also covers msk writes

    for (int t = 0; t < 33; t++) {
        const int buf = t & 1;
        const int jb = t * 64;
        if (t < 32) prefetch(t + 1);
        cpa_commit();

        // ---- bias prefetch into registers (consumed after S MMAs) ----
        float bA[8][2], bB[8][2];
        #pragma unroll
        for (int nt = 0; nt < 8; nt++) {
            const int jg0 = jb + nt*8 + 2*tig;
            const int jg1 = jg0 + 1;
            const bool ok0 = (jg0 >= 1) && (jg0 <= N_);
            const bool ok1 = (jg1 >= 1) && (jg1 <= N_);
            const int o0 = ok0 ? jg0 : 0;
            const int o1 = ok1 ? jg1 : 0;
            bA[nt][0] = ok0 ? __ldg(biasA + o0) : 0.f;
            bA[nt][1] = ok1 ? __ldg(biasA + o1) : 0.f;
            bB[nt][0] = ok0 ? __ldg(biasB + o0) : 0.f;
            bB[nt][1] = ok1 ? __ldg(biasB + o1) : 0.f;
        }

        cpa_wait1();
        __syncthreads();

        const unsigned* Ku = (const unsigned*)(Ksf + buf*4352);
        const unsigned* Vu = (const unsigned*)(Vsf + buf*4608);

        // ---- S = Q K^T ----
        float sc[8][4];
        #pragma unroll
        for (int nt = 0; nt < 8; nt++)
            #pragma unroll
            for (int i = 0; i < 4; i++) sc[nt][i] = 0.f;
        #pragma unroll
        for (int ks = 0; ks < 8; ks++)
            #pragma unroll
            for (int nt = 0; nt < 8; nt++) {
                unsigned bb2[2];
                bb2[0] = Ku[(nt*8 + gid)*KS_STR + ks*8 + tig];
                bb2[1] = Ku[(nt*8 + gid)*KS_STR + ks*8 + tig + 4];
                mma8(sc[nt], qa[ks], bb2);
            }

        // ---- scale + bias + mask, online softmax in registers ----
        float mx0 = -FLT_MAX, mx1 = -FLT_MAX;
        #pragma unroll
        for (int nt = 0; nt < 8; nt++) {
            const int c0 = nt*8 + 2*tig;
            const int v0 = msk[jb + c0], v1 = msk[jb + c0 + 1];
            sc[nt][0] = v0 ? sc[nt][0]*8.f + bA[nt][0] : -FLT_MAX;
            sc[nt][1] = v1 ? sc[nt][1]*8.f + bA[nt][1] : -FLT_MAX;
            sc[nt][2] = v0 ? sc[nt][2]*8.f + bB[nt][0] : -FLT_MAX;
            sc[nt][3] = v1 ? sc[nt][3]*8.f + bB[nt][1] : -FLT_MAX;
            mx0 = fmaxf(mx0, fmaxf(sc[nt][0], sc[nt][1]));
            mx1 = fmaxf(mx1, fmaxf(sc[nt][2], sc[nt][3]));
        }
        mx0 = fmaxf(mx0, __shfl_xor_sync(0xFFFFFFFFu, mx0, 1));
        mx0 = fmaxf(mx0, __shfl_xor_sync(0xFFFFFFFFu, mx0, 2));
        mx1 = fmaxf(mx1, __shfl_xor_sync(0xFFFFFFFFu, mx1, 1));
        mx1 = fmaxf(mx1, __shfl_xor_sync(0xFFFFFFFFu, mx1, 2));
        const float mn0 = fmaxf(m0, mx0), mn1 = fmaxf(m1, mx1);
        const float f0 = __expf(m0 - mn0), f1 = __expf(m1 - mn1);
        float s0 = 0.f, s1 = 0.f;
        #pragma unroll
        for (int nt = 0; nt < 8; nt++) {
            const float p0 = __expf(sc[nt][0] - mn0);
            const float p1 = __expf(sc[nt][1] - mn0);
            const float p2 = __expf(sc[nt][2] - mn1);
            const float p3 = __expf(sc[nt][3] - mn1);
            s0 += p0 + p1; s1 += p2 + p3;
            const int c0 = nt*8 + 2*tig;
            *(uint2*)(pw + gid*PS_STR + c0)     = make_uint2(f2tf(p0), f2tf(p1));
            *(uint2*)(pw + (gid+8)*PS_STR + c0) = make_uint2(f2tf(p2), f2tf(p3));
        }
        s0 += __shfl_xor_sync(0xFFFFFFFFu, s0, 1);
        s0 += __shfl_xor_sync(0xFFFFFFFFu, s0, 2);
        s1 += __shfl_xor_sync(0xFFFFFFFFu, s1, 1);
        s1 += __shfl_xor_sync(0xFFFFFFFFu, s1, 2);
        l0 = l0 * f0 + s0; l1 = l1 * f1 + s1;
        m0 = mn0; m1 = mn1;
        #pragma unroll
        for (int nt = 0; nt < 8; nt++) {
            O[nt][0] *= f0; O[nt][1] *= f0;
            O[nt][2] *= f1; O[nt][3] *= f1;
        }
        __syncwarp();

        // ---- O += P V ----
        #pragma unroll
        for (int ks = 0; ks < 8; ks++) {
            unsigned pa[4];
            pa[0] = pw[gid*PS_STR + ks*8 + tig];
            pa[1] = pw[(gid+8)*PS_STR + ks*8 + tig];
            pa[2] = pw[gid*PS_STR + ks*8 + tig + 4];
            pa[3] = pw[(gid+8)*PS_STR + ks*8 + tig + 4];
            #pragma unroll
            for (int nt = 0; nt < 8; nt++) {
                unsigned bb2[2];
                bb2[0] = Vu[(ks*8 + tig)*VS_STR + nt*8 + gid];
                bb2[1] = Vu[(ks*8 + tig + 4)*VS_STR + nt*8 + gid];
                mma8(O[nt], pa, bb2);
            }
        }
        __syncthreads();   // all warps done with buf before it is overwritten
    }

    const float inv0 = 1.f / l0, inv1 = 1.f / l1;
    float* ob = g_ao + ((size_t)b*N_ + i0 + wid*16)*1024 + h*64;
    #pragma unroll
    for (int nt = 0; nt < 8; nt++) {
        const int c0 = nt*8 + 2*tig;
        *(float2*)(ob + (size_t)gid*1024 + c0) =
            make_float2(f2tff(O[nt][0]*inv0), f2tff(O[nt][1]*inv0));
        *(float2*)(ob + (size_t)(gid+8)*1024 + c0) =
            make_float2(f2tff(O[nt][2]*inv1), f2tff(O[nt][3]*inv1));
    }
}

// ---------------------------------------------------------------------------
extern "C" void kernel_launch(void* const* d_in, const int* in_sizes, int n_in,
                              void* d_out, int out_size) {
    const float* x         = (const float*)d_in[0];
    const float* attn_bias = (const float*)d_in[1];
    const void*  cmask     = (const void*) d_in[2];
    const float* gamma     = (const float*)d_in[3];
    const float* null_kv   = (const float*)d_in[4];
    const float* Wq        = (const float*)d_in[5];
    const float* Wkv       = (const float*)d_in[6];
    const float* q_scale   = (const float*)d_in[7];
    const float* k_scale   = (const float*)d_in[8];
    const float* Wout      = (const float*)d_in[9];
    float* out = (float*)d_out;

    static const int attn_smem = 108608;   // bytes
    cudaFuncSetAttribute(attn_tc2,
                         cudaFuncAttributeMaxDynamicSharedMemorySize,
                         attn_smem);

    detect_mask_kernel<<<1, 256>>>((const unsigned char*)cmask);
    ln_kernel<<<ROWS_, 256>>>(x, gamma);
    gemm_qkv_tc<<<dim3(24, 32), 256>>>(Wq, Wkv);
    {
        const int total_warps = BH_ * NK_;
        const int blocks = (total_warps * 32 + 255) / 256;
        norm_kernel<<<blocks, 256>>>(null_kv, q_scale, k_scale);
    }
    attn_tc2<<<BH_ * 16, 256, attn_smem>>>(attn_bias, cmask);
    gemm_out_tc<<<dim3(8, 32), 256>>>(Wout, out);
}

// round 5
// speedup vs baseline: 1.3081x; 1.3081x over previous
#include <cuda_runtime.h>
#include <math.h>
#include <float.h>

// Problem dims
#define B_   2
#define N_   2048
#define D_   1024
#define H_   16
#define DH_  64
#define C_   64
#define NK_  2049            // N+1 (null kv prepended)
#define BH_  (B_*H_)         // 32
#define ROWS_ (B_*N_)        // 4096
#define LDBIAS_ (C_+N_)      // 2112

// Scratch (device globals: allocation-free rule)
__device__ float g_xn[ROWS_*D_];        // layernormed x
__device__ float g_q [BH_*N_ *DH_];     // head-major q (l2normed+scaled, tf32)
__device__ float g_k [BH_*NK_*DH_];     // head-major COMPACTED k (row 0 = null, tf32)
__device__ float g_v [BH_*NK_*DH_];     // head-major COMPACTED v (row 0 = null, tf32)
__device__ float g_ao[ROWS_*D_];        // attention output (b,n,h*64+d)
__device__ int   g_mask_mode;           // 1 = 1-byte mask, 0 = 4-byte mask
__device__ int   g_cnt[2];              // compacted kv count per batch (incl null)
__device__ int   g_rank[2][2048];       // n -> compacted row (or -1)
__device__ int   g_jmap[2][2144];       // compacted row -> original j (0..2048), -1 pad

// ---------------------------------------------------------------------------
// tf32 helpers
// ---------------------------------------------------------------------------
__device__ __forceinline__ unsigned f2tf(float f) {
    unsigned u;
    asm("cvt.rna.tf32.f32 %0, %1;" : "=r"(u) : "f"(f));
    return u;
}
__device__ __forceinline__ float f2tff(float f) { return __uint_as_float(f2tf(f)); }

__device__ __forceinline__ void mma8(float* c, const unsigned* a, const unsigned* b) {
    asm volatile(
        "mma.sync.aligned.m16n8k8.row.col.f32.tf32.tf32.f32 "
        "{%0,%1,%2,%3}, {%4,%5,%6,%7}, {%8,%9}, {%0,%1,%2,%3};"
        : "+f"(c[0]), "+f"(c[1]), "+f"(c[2]), "+f"(c[3])
        : "r"(a[0]), "r"(a[1]), "r"(a[2]), "r"(a[3]), "r"(b[0]), "r"(b[1]));
}

__device__ __forceinline__ void cpa16(unsigned dst, const void* src, int ok) {
    asm volatile("cp.async.ca.shared.global [%0], [%1], 16, %2;"
                 :: "r"(dst), "l"(src), "r"(ok ? 16 : 0));
}
__device__ __forceinline__ void cpa_commit() {
    asm volatile("cp.async.commit_group;");
}
__device__ __forceinline__ void cpa_wait1() {
    asm volatile("cp.async.wait_group 1;");
}

// ---------------------------------------------------------------------------
// prep: mask-mode detect, per-batch compaction scan, null-kv row 0.
// One block, 256 threads.
// ---------------------------------------------------------------------------
__global__ void prep_kernel(const unsigned char* __restrict__ cm,
                            const float* __restrict__ null_kv,
                            const float* __restrict__ k_scale) {
    __shared__ int flag;
    __shared__ int thsum[256];
    __shared__ int pref[257];
    const int tid = threadIdx.x;
    const int wid = tid >> 5, lane = tid & 31;

    if (tid == 0) flag = 0;
    __syncthreads();
    int any = 0;
    for (int i = tid; i < 1024; i += 256)
        if (cm[4*i + 1] != 0) any = 1;
    if (any) atomicOr(&flag, 1);
    __syncthreads();
    const int mode = flag;
    if (tid == 0) g_mask_mode = mode;
    const unsigned* m32 = (const unsigned*)cm;

    for (int b = 0; b < 2; b++) {
        int f[8], ls = 0;
        #pragma unroll
        for (int k = 0; k < 8; k++) {
            const int n = tid*8 + k;
            f[k] = mode ? (cm[b*N_ + n] != 0) : (m32[b*N_ + n] != 0u);
            ls += f[k];
        }
        thsum[tid] = ls;
        __syncthreads();
        if (tid == 0) {
            int s = 0;
            for (int i = 0; i < 256; i++) { pref[i] = s; s += thsum[i]; }
            pref[256] = s;
        }
        __syncthreads();
        int r = 1 + pref[tid];       // compacted rows start at 1 (0 = null)
        #pragma unroll
        for (int k = 0; k < 8; k++) {
            const int n = tid*8 + k;
            if (f[k]) { g_rank[b][n] = r; g_jmap[b][r] = n + 1; r++; }
            else        g_rank[b][n] = -1;
        }
        const int cnt = 1 + pref[256];
        if (tid == 0) { g_cnt[b] = cnt; g_jmap[b][0] = 0; }
        for (int i = cnt + tid; i < 2144; i += 256) g_jmap[b][i] = -1;
        __syncthreads();
    }

    // null kv -> compacted row 0 for all (b, h); k l2normed * k_scale, tf32
    for (int h = wid; h < H_; h += 8) {
        const int d0 = lane, d1 = lane + 32;
        const float k0 = null_kv[h*DH_ + d0], k1 = null_kv[h*DH_ + d1];
        const float v0 = null_kv[H_*DH_ + h*DH_ + d0];
        const float v1 = null_kv[H_*DH_ + h*DH_ + d1];
        float ss = k0*k0 + k1*k1;
        #pragma unroll
        for (int o = 16; o > 0; o >>= 1) ss += __shfl_xor_sync(0xFFFFFFFFu, ss, o);
        const float inv = 1.0f / fmaxf(sqrtf(ss), 1e-12f);
        const float ks0 = k_scale[d0], ks1 = k_scale[d1];
        #pragma unroll
        for (int b = 0; b < 2; b++) {
            const int bh = b*H_ + h;
            float* kp = g_k + (size_t)bh * NK_ * DH_;
            float* vp = g_v + (size_t)bh * NK_ * DH_;
            kp[d0] = f2tff(k0*inv*ks0); kp[d1] = f2tff(k1*inv*ks1);
            vp[d0] = f2tff(v0);         vp[d1] = f2tff(v1);
        }
    }
}

// ---------------------------------------------------------------------------
// LayerNorm
// ---------------------------------------------------------------------------
__global__ void ln_kernel(const float* __restrict__ x,
                          const float* __restrict__ gamma) {
    const int row = blockIdx.x;
    const int tid = threadIdx.x;
    const float4 a = ((const float4*)(x + (size_t)row * D_))[tid];
    float s  = a.x + a.y + a.z + a.w;
    float s2 = a.x*a.x + a.y*a.y + a.z*a.z + a.w*a.w;
    #pragma unroll
    for (int o = 16; o > 0; o >>= 1) {
        s  += __shfl_xor_sync(0xFFFFFFFFu, s,  o);
        s2 += __shfl_xor_sync(0xFFFFFFFFu, s2, o);
    }
    __shared__ float rs[8], rs2[8];
    if ((tid & 31) == 0) { rs[tid >> 5] = s; rs2[tid >> 5] = s2; }
    __syncthreads();
    float S = 0.f, S2 = 0.f;
    #pragma unroll
    for (int i = 0; i < 8; i++) { S += rs[i]; S2 += rs2[i]; }
    const float mu  = S * (1.0f / D_);
    const float var = S2 * (1.0f / D_) - mu * mu;
    const float inv = rsqrtf(var + 1e-5f);
    const float4 g = ((const float4*)gamma)[tid];
    float4 o;
    o.x = (a.x - mu) * inv * g.x;
    o.y = (a.y - mu) * inv * g.y;
    o.z = (a.z - mu) * inv * g.z;
    o.w = (a.w - mu) * inv * g.w;
    ((float4*)(g_xn + (size_t)row * D_))[tid] = o;
}

// ---------------------------------------------------------------------------
// tf32 tensor-core GEMM core: 128x128 tile, BK=16, 256 threads (8 warps 4x2).
// ---------------------------------------------------------------------------
#define AS_STR 20
#define BS_STR2 136

struct GemmSmem {
    float As[2][128*AS_STR];
    float Bs[2][16*BS_STR2];
};

__device__ __forceinline__ void gemm_core_compute(
    const GemmSmem* sm, int buf, int wm, int wn, int gid, int tig,
    float acc[2][8][4])
{
    const unsigned* ab = (const unsigned*)sm->As[buf];
    const unsigned* bb = (const unsigned*)sm->Bs[buf];
    #pragma unroll
    for (int kk = 0; kk < 2; kk++) {
        unsigned afr[2][4];
        #pragma unroll
        for (int mt = 0; mt < 2; mt++) {
            const int r = wm*32 + mt*16 + gid;
            const int c = kk*8 + tig;
            afr[mt][0] = ab[(size_t)r*AS_STR + c];
            afr[mt][1] = ab[(size_t)(r+8)*AS_STR + c];
            afr[mt][2] = ab[(size_t)r*AS_STR + c + 4];
            afr[mt][3] = ab[(size_t)(r+8)*AS_STR + c + 4];
        }
        unsigned bfr[8][2];
        #pragma unroll
        for (int nt = 0; nt < 8; nt++) {
            const int k = kk*8 + tig;
            const int n = wn*64 + nt*8 + gid;
            bfr[nt][0] = bb[(size_t)k*BS_STR2 + n];
            bfr[nt][1] = bb[(size_t)(k+4)*BS_STR2 + n];
        }
        #pragma unroll
        for (int mt = 0; mt < 2; mt++)
            #pragma unroll
            for (int nt = 0; nt < 8; nt++)
                mma8(acc[mt][nt], afr[mt], bfr[nt]);
    }
}

__device__ __forceinline__ void gemm_main_loop(
    const float* __restrict__ A, const float* __restrict__ Bp,
    int ldb, int cb, int bm, GemmSmem* sm,
    int wm, int wn, int gid, int tig, float acc[2][8][4])
{
    const int tid = threadIdx.x;
    const int ar = tid >> 2, akc = (tid & 3) * 4;
    const int bk = tid >> 5, bnc = (tid & 31) * 4;

    float4 ra0, ra1, rb0, rb1;
    ra0 = *(const float4*)(A + (size_t)(bm + ar) * 1024 + akc);
    ra1 = *(const float4*)(A + (size_t)(bm + ar + 64) * 1024 + akc);
    rb0 = *(const float4*)(Bp + (size_t)bk * ldb + cb + bnc);
    rb1 = *(const float4*)(Bp + (size_t)(bk + 8) * ldb + cb + bnc);
    {
        unsigned* d0 = (unsigned*)&sm->As[0][ar*AS_STR + akc];
        d0[0]=f2tf(ra0.x); d0[1]=f2tf(ra0.y); d0[2]=f2tf(ra0.z); d0[3]=f2tf(ra0.w);
        unsigned* d1 = (unsigned*)&sm->As[0][(ar+64)*AS_STR + akc];
        d1[0]=f2tf(ra1.x); d1[1]=f2tf(ra1.y); d1[2]=f2tf(ra1.z); d1[3]=f2tf(ra1.w);
        unsigned* e0 = (unsigned*)&sm->Bs[0][bk*BS_STR2 + bnc];
        e0[0]=f2tf(rb0.x); e0[1]=f2tf(rb0.y); e0[2]=f2tf(rb0.z); e0[3]=f2tf(rb0.w);
        unsigned* e1 = (unsigned*)&sm->Bs[0][(bk+8)*BS_STR2 + bnc];
        e1[0]=f2tf(rb1.x); e1[1]=f2tf(rb1.y); e1[2]=f2tf(rb1.z); e1[3]=f2tf(rb1.w);
    }
    __syncthreads();

    int buf = 0;
    for (int kt = 0; kt < 64; kt++) {
        if (kt < 63) {
            const int k0 = (kt + 1) * 16;
            ra0 = *(const float4*)(A + (size_t)(bm + ar) * 1024 + k0 + akc);
            ra1 = *(const float4*)(A + (size_t)(bm + ar + 64) * 1024 + k0 + akc);
            rb0 = *(const float4*)(Bp + (size_t)(k0 + bk) * ldb + cb + bnc);
            rb1 = *(const float4*)(Bp + (size_t)(k0 + bk + 8) * ldb + cb + bnc);
        }
        gemm_core_compute(sm, buf, wm, wn, gid, tig, acc);
        if (kt < 63) {
            const int nb = buf ^ 1;
            unsigned* d0 = (unsigned*)&sm->As[nb][ar*AS_STR + akc];
            d0[0]=f2tf(ra0.x); d0[1]=f2tf(ra0.y); d0[2]=f2tf(ra0.z); d0[3]=f2tf(ra0.w);
            unsigned* d1 = (unsigned*)&sm->As[nb][(ar+64)*AS_STR + akc];
            d1[0]=f2tf(ra1.x); d1[1]=f2tf(ra1.y); d1[2]=f2tf(ra1.z); d1[3]=f2tf(ra1.w);
            unsigned* e0 = (unsigned*)&sm->Bs[nb][bk*BS_STR2 + bnc];
            e0[0]=f2tf(rb0.x); e0[1]=f2tf(rb0.y); e0[2]=f2tf(rb0.z); e0[3]=f2tf(rb0.w);
            unsigned* e1 = (unsigned*)&sm->Bs[nb][(bk+8)*BS_STR2 + bnc];
            e1[0]=f2tf(rb1.x); e1[1]=f2tf(rb1.y); e1[2]=f2tf(rb1.z); e1[3]=f2tf(rb1.w);
            __syncthreads();
            buf = nb;
        }
    }
}

// ---------------------------------------------------------------------------
// QKV GEMM with FUSED l2norm/scale + compaction scatter.
// Each warp owns full head rows (64 cols within one wn) -> row sum-of-squares
// via 2 shfl_xor over the tig lanes. k/v rows scatter to compacted slots.
// ---------------------------------------------------------------------------
__global__ __launch_bounds__(256)
void gemm_qkv_tc(const float* __restrict__ Wq, const float* __restrict__ Wkv,
                 const float* __restrict__ q_scale,
                 const float* __restrict__ k_scale) {
    __shared__ GemmSmem sm;
    const int tid = threadIdx.x;
    const int wid = tid >> 5, lane = tid & 31;
    const int gid = lane >> 2, tig = lane & 3;
    const int wm = wid & 3, wn = wid >> 2;
    const int bm = blockIdx.y * 128, bn = blockIdx.x * 128;
    const float* Bp; int ldb, cb;
    if (bn < 1024) { Bp = Wq;  ldb = 1024; cb = bn; }
    else           { Bp = Wkv; ldb = 2048; cb = bn - 1024; }

    float acc[2][8][4] = {};
    gemm_main_loop(g_xn, Bp, ldb, cb, bm, &sm, wm, wn, gid, tig, acc);

    const int hv = (bn + wn*64) >> 6;   // 0..15 q, 16..31 k, 32..47 v

    #pragma unroll
    for (int mt = 0; mt < 2; mt++) {
        #pragma unroll
        for (int i = 0; i < 2; i++) {
            const int row = bm + wm*32 + mt*16 + gid + i*8;
            const int bidx = row >> 11, n = row & 2047;
            // row sum of squares over the 64 head cols (4 tig lanes)
            float ss = 0.f;
            #pragma unroll
            for (int nt = 0; nt < 8; nt++)
                ss += acc[mt][nt][i*2]*acc[mt][nt][i*2]
                    + acc[mt][nt][i*2+1]*acc[mt][nt][i*2+1];
            ss += __shfl_xor_sync(0xFFFFFFFFu, ss, 1);
            ss += __shfl_xor_sync(0xFFFFFFFFu, ss, 2);

            if (hv < 16) {
                const float inv = 1.0f / fmaxf(sqrtf(ss), 1e-12f);
                float* dst = g_q + (((size_t)(bidx*H_ + hv))*N_ + n)*DH_;
                #pragma unroll
                for (int nt = 0; nt < 8; nt++) {
                    const int d = nt*8 + 2*tig;
                    *(float2*)(dst + d) = make_float2(
                        f2tff(acc[mt][nt][i*2]   * inv * q_scale[d]),
                        f2tff(acc[mt][nt][i*2+1] * inv * q_scale[d+1]));
                }
            } else if (hv < 32) {
                const int r = g_rank[bidx][n];
                if (r >= 0) {
                    const float inv = 1.0f / fmaxf(sqrtf(ss), 1e-12f);
                    float* dst = g_k + (((size_t)(bidx*H_ + hv-16))*NK_ + r)*DH_;
                    #pragma unroll
                    for (int nt = 0; nt < 8; nt++) {
                        const int d = nt*8 + 2*tig;
                        *(float2*)(dst + d) = make_float2(
                            f2tff(acc[mt][nt][i*2]   * inv * k_scale[d]),
                            f2tff(acc[mt][nt][i*2+1] * inv * k_scale[d+1]));
                    }
                }
            } else {
                const int r = g_rank[bidx][n];
                if (r >= 0) {
                    float* dst = g_v + (((size_t)(bidx*H_ + hv-32))*NK_ + r)*DH_;
                    #pragma unroll
                    for (int nt = 0; nt < 8; nt++) {
                        const int d = nt*8 + 2*tig;
                        *(float2*)(dst + d) = make_float2(
                            f2tff(acc[mt][nt][i*2]),
                            f2tff(acc[mt][nt][i*2+1]));
                    }
                }
            }
        }
    }
}

// Output GEMM: d_out(4096 x 1024) = g_ao @ Wout
__global__ __launch_bounds__(256)
void gemm_out_tc(const float* __restrict__ Wout, float* __restrict__ out) {
    __shared__ GemmSmem sm;
    const int tid = threadIdx.x;
    const int wid = tid >> 5, lane = tid & 31;
    const int gid = lane >> 2, tig = lane & 3;
    const int wm = wid & 3, wn = wid >> 2;
    const int bm = blockIdx.y * 128, bn = blockIdx.x * 128;

    float acc[2][8][4] = {};
    gemm_main_loop(g_ao, Wout, 1024, bn, bm, &sm, wm, wn, gid, tig, acc);

    #pragma unroll
    for (int mt = 0; mt < 2; mt++) {
        #pragma unroll
        for (int i = 0; i < 2; i++) {
            const int row = bm + wm*32 + mt*16 + gid + i*8;
            #pragma unroll
            for (int nt = 0; nt < 8; nt++) {
                const int col = bn + wn*64 + nt*8 + 2*tig;
                *(float2*)&out[(size_t)row*1024 + col] =
                    make_float2(acc[mt][nt][i*2], acc[mt][nt][i*2+1]);
            }
        }
    }
}

// ---------------------------------------------------------------------------
// tf32 flash attention over COMPACTED kv (tiles = ceil(cnt/64), ~17 vs 33).
// 256 threads, 128 q-rows/block, cp.async double-buffered K/V,
// bias gathered via g_jmap (register prefetch, hidden under S-MMAs).
// ---------------------------------------------------------------------------
#define KS_STR 68
#define VS_STR 72
#define PS_STR 68

__global__ __launch_bounds__(256)
void attn_tc2(const float* __restrict__ attn_bias) {
    extern __shared__ float smf[];
    float* Ksf = smf;                       // 2 * 64*68 = 8704 floats
    float* Vsf = smf + 8704;                // 2 * 64*72 = 9216 floats
    float* Psf = smf + 17920;               // 8 * 16*68 = 8704 floats

    const int tid = threadIdx.x;
    const int wid = tid >> 5, lane = tid & 31;
    const int gid = lane >> 2, tig = lane & 3;
    const int qt = blockIdx.x & 15, bh = blockIdx.x >> 4;
    const int b = bh >> 4, h = bh & 15;
    const int i0 = qt * 128;

    const int cnt   = g_cnt[b];
    const int tiles = (cnt + 63) >> 6;
    const int* jmap = g_jmap[b];

    // Q fragments: pre-rounded tf32 bits, register-resident
    unsigned qa[8][4];
    {
        const float* qb = g_q + ((size_t)bh*N_ + i0 + wid*16)*DH_;
        #pragma unroll
        for (int ks = 0; ks < 8; ks++) {
            qa[ks][0] = __float_as_uint(qb[gid*64 + ks*8 + tig]);
            qa[ks][1] = __float_as_uint(qb[(gid+8)*64 + ks*8 + tig]);
            qa[ks][2] = __float_as_uint(qb[gid*64 + ks*8 + tig + 4]);
            qa[ks][3] = __float_as_uint(qb[(gid+8)*64 + ks*8 + tig + 4]);
        }
    }

    float O[8][4];
    #pragma unroll
    for (int nt = 0; nt < 8; nt++)
        #pragma unroll
        for (int i = 0; i < 4; i++) O[nt][i] = 0.f;
    float m0 = -FLT_MAX, m1 = -FLT_MAX, l0 = 0.f, l1 = 0.f;

    const float* kb = g_k + (size_t)bh * NK_ * DH_;
    const float* vb = g_v + (size_t)bh * NK_ * DH_;
    unsigned* Pu = (unsigned*)Psf;
    unsigned* pw = Pu + wid * (16 * PS_STR);
    const float* biasA = attn_bias + (size_t)(C_ + i0 + wid*16 + gid)*LDBIAS_ + (C_ - 1);
    const float* biasB = biasA + (size_t)8*LDBIAS_;

    const unsigned ks_s0 = (unsigned)__cvta_generic_to_shared(Ksf);
    const unsigned vs_s0 = (unsigned)__cvta_generic_to_shared(Vsf);
    const int cpr = tid >> 4, cpc = (tid & 15) * 4;

    auto prefetch = [&](int t) {
        const int jb = t * 64;
        const unsigned kdst = ks_s0 + (unsigned)((t & 1) * 4352 * 4);
        const unsigned vdst = vs_s0 + (unsigned)((t & 1) * 4608 * 4);
        #pragma unroll
        for (int i = 0; i < 4; i++) {
            const int r = cpr + i*16;
            const int ok = (jb + r) < cnt;
            cpa16(kdst + (unsigned)(r*KS_STR + cpc)*4, kb + (size_t)(jb + r)*64 + cpc, ok);
            cpa16(vdst + (unsigned)(r*VS_STR + cpc)*4, vb + (size_t)(jb + r)*64 + cpc, ok);
        }
    };

    prefetch(0);
    cpa_commit();
    __syncthreads();

    for (int t = 0; t < tiles; t++) {
        const int buf = t & 1;
        const int jb = t * 64;
        if (t + 1 < tiles) prefetch(t + 1);
        cpa_commit();

        // ---- jmap + bias prefetch into registers (consumed after S MMAs) ----
        int   jg[8][2];
        float bA[8][2], bB[8][2];
        #pragma unroll
        for (int nt = 0; nt < 8; nt++) {
            const int c0 = jb + nt*8 + 2*tig;
            jg[nt][0] = __ldg(jmap + c0);
            jg[nt][1] = __ldg(jmap + c0 + 1);
            const bool ok0 = jg[nt][0] > 0;
            const bool ok1 = jg[nt][1] > 0;
            const int o0 = ok0 ? jg[nt][0] : 0;
            const int o1 = ok1 ? jg[nt][1] : 0;
            bA[nt][0] = ok0 ? __ldg(biasA + o0) : 0.f;
            bA[nt][1] = ok1 ? __ldg(biasA + o1) : 0.f;
            bB[nt][0] = ok0 ? __ldg(biasB + o0) : 0.f;
            bB[nt][1] = ok1 ? __ldg(biasB + o1) : 0.f;
        }

        cpa_wait1();
        __syncthreads();

        const unsigned* Ku = (const unsigned*)(Ksf + buf*4352);
        const unsigned* Vu = (const unsigned*)(Vsf + buf*4608);

        // ---- S = Q K^T ----
        float sc[8][4];
        #pragma unroll
        for (int nt = 0; nt < 8; nt++)
            #pragma unroll
            for (int i = 0; i < 4; i++) sc[nt][i] = 0.f;
        #pragma unroll
        for (int ks = 0; ks < 8; ks++)
            #pragma unroll
            for (int nt = 0; nt < 8; nt++) {
                unsigned bb2[2];
                bb2[0] = Ku[(nt*8 + gid)*KS_STR + ks*8 + tig];
                bb2[1] = Ku[(nt*8 + gid)*KS_STR + ks*8 + tig + 4];
                mma8(sc[nt], qa[ks], bb2);
            }

        // ---- scale + bias + validity, online softmax in registers ----
        float mx0 = -FLT_MAX, mx1 = -FLT_MAX;
        #pragma unroll
        for (int nt = 0; nt < 8; nt++) {
            const bool v0 = jg[nt][0] >= 0, v1 = jg[nt][1] >= 0;
            sc[nt][0] = v0 ? sc[nt][0]*8.f + bA[nt][0] : -FLT_MAX;
            sc[nt][1] = v1 ? sc[nt][1]*8.f + bA[nt][1] : -FLT_MAX;
            sc[nt][2] = v0 ? sc[nt][2]*8.f + bB[nt][0] : -FLT_MAX;
            sc[nt][3] = v1 ? sc[nt][3]*8.f + bB[nt][1] : -FLT_MAX;
            mx0 = fmaxf(mx0, fmaxf(sc[nt][0], sc[nt][1]));
            mx1 = fmaxf(mx1, fmaxf(sc[nt][2], sc[nt][3]));
        }
        mx0 = fmaxf(mx0, __shfl_xor_sync(0xFFFFFFFFu, mx0, 1));
        mx0 = fmaxf(mx0, __shfl_xor_sync(0xFFFFFFFFu, mx0, 2));
        mx1 = fmaxf(mx1, __shfl_xor_sync(0xFFFFFFFFu, mx1, 1));
        mx1 = fmaxf(mx1, __shfl_xor_sync(0xFFFFFFFFu, mx1, 2));
        const float mn0 = fmaxf(m0, mx0), mn1 = fmaxf(m1, mx1);
        const float f0 = __expf(m0 - mn0), f1 = __expf(m1 - mn1);
        float s0 = 0.f, s1 = 0.f;
        #pragma unroll
        for (int nt = 0; nt < 8; nt++) {
            const float p0 = __expf(sc[nt][0] - mn0);
            const float p1 = __expf(sc[nt][1] - mn0);
            const float p2 = __expf(sc[nt][2] - mn1);
            const float p3 = __expf(sc[nt][3] - mn1);
            s0 += p0 + p1; s1 += p2 + p3;
            const int c0 = nt*8 + 2*tig;
            *(uint2*)(pw + gid*PS_STR + c0)     = make_uint2(f2tf(p0), f2tf(p1));
            *(uint2*)(pw + (gid+8)*PS_STR + c0) = make_uint2(f2tf(p2), f2tf(p3));
        }
        s0 += __shfl_xor_sync(0xFFFFFFFFu, s0, 1);
        s0 += __shfl_xor_sync(0xFFFFFFFFu, s0, 2);
        s1 += __shfl_xor_sync(0xFFFFFFFFu, s1, 1);
        s1 += __shfl_xor_sync(0xFFFFFFFFu, s1, 2);
        l0 = l0 * f0 + s0; l1 = l1 * f1 + s1;
        m0 = mn0; m1 = mn1;
        #pragma unroll
        for (int nt = 0; nt < 8; nt++) {
            O[nt][0] *= f0; O[nt][1] *= f0;
            O[nt][2] *= f1; O[nt][3] *= f1;
        }
        __syncwarp();

        // ---- O += P V ----
        #pragma unroll
        for (int ks = 0; ks < 8; ks++) {
            unsigned pa[4];
            pa[0] = pw[gid*PS_STR + ks*8 + tig];
            pa[1] = pw[(gid+8)*PS_STR + ks*8 + tig];
            pa[2] = pw[gid*PS_STR + ks*8 + tig + 4];
            pa[3] = pw[(gid+8)*PS_STR + ks*8 + tig + 4];
            #pragma unroll
            for (int nt = 0; nt < 8; nt++) {
                unsigned bb2[2];
                bb2[0] = Vu[(ks*8 + tig)*VS_STR + nt*8 + gid];
                bb2[1] = Vu[(ks*8 + tig + 4)*VS_STR + nt*8 + gid];
                mma8(O[nt], pa, bb2);
            }
        }
        __syncthreads();
    }

    const float inv0 = 1.f / l0, inv1 = 1.f / l1;
    float* ob = g_ao + ((size_t)b*N_ + i0 + wid*16)*1024 + h*64;
    #pragma unroll
    for (int nt = 0; nt < 8; nt++) {
        const int c0 = nt*8 + 2*tig;
        *(float2*)(ob + (size_t)gid*1024 + c0) =
            make_float2(f2tff(O[nt][0]*inv0), f2tff(O[nt][1]*inv0));
        *(float2*)(ob + (size_t)(gid+8)*1024 + c0) =
            make_float2(f2tff(O[nt][2]*inv1), f2tff(O[nt][3]*inv1));
    }
}

// ---------------------------------------------------------------------------
extern "C" void kernel_launch(void* const* d_in, const int* in_sizes, int n_in,
                              void* d_out, int out_size) {
    const float* x         = (const float*)d_in[0];
    const float* attn_bias = (const float*)d_in[1];
    const void*  cmask     = (const void*) d_in[2];
    const float* gamma     = (const float*)d_in[3];
    const float* null_kv   = (const float*)d_in[4];
    const float* Wq        = (const float*)d_in[5];
    const float* Wkv       = (const float*)d_in[6];
    const float* q_scale   = (const float*)d_in[7];
    const float* k_scale   = (const float*)d_in[8];
    const float* Wout      = (const float*)d_in[9];
    float* out = (float*)d_out;

    static const int attn_smem = 26624 * 4;   // 106496 B
    cudaFuncSetAttribute(attn_tc2,
                         cudaFuncAttributeMaxDynamicSharedMemorySize,
                         attn_smem);

    prep_kernel<<<1, 256>>>((const unsigned char*)cmask, null_kv, k_scale);
    ln_kernel<<<ROWS_, 256>>>(x, gamma);
    gemm_qkv_tc<<<dim3(24, 32), 256>>>(Wq, Wkv, q_scale, k_scale);
    attn_tc2<<<BH_ * 16, 256, attn_smem>>>(attn_bias);
    gemm_out_tc<<<dim3(8, 32), 256>>>(Wout, out);
}

// round 9
// speedup vs baseline: 1.3817x; 1.0563x over previous
#include <cuda_runtime.h>
#include <math.h>
#include <float.h>

// Problem dims
#define B_   2
#define N_   2048
#define D_   1024
#define H_   16
#define DH_  64
#define C_   64
#define NK_  2049            // N+1 (null kv prepended)
#define VTS_ 2052            // Vt row stride (floats), 16B-aligned (2052*4=8208=513*16)
#define BH_  (B_*H_)         // 32
#define ROWS_ (B_*N_)        // 4096
#define LDBIAS_ (C_+N_)      // 2112

// Scratch (device globals: allocation-free rule)
__device__ float g_xn[ROWS_*D_];        // layernormed x
__device__ float g_q [BH_*N_ *DH_];     // head-major q (l2normed+scaled, tf32)
__device__ float g_k [BH_*NK_*DH_];     // head-major COMPACTED k (row 0 = null, tf32)
__device__ float g_vt[BH_*DH_*VTS_];    // head-major COMPACTED v TRANSPOSED [bh][d][j], tf32
__device__ float g_ao[ROWS_*D_];        // attention output (b,n,h*64+d)
__device__ int   g_mask_mode;           // 1 = 1-byte mask, 0 = 4-byte mask
__device__ int   g_cnt[2];              // compacted kv count per batch (incl null)
__device__ int   g_rank[2][2048];       // n -> compacted row (or -1)
__device__ int   g_jmap[2][2144];       // compacted row -> original j (0..2048), -1 pad

// ---------------------------------------------------------------------------
// tf32 / mma / ldmatrix helpers
// ---------------------------------------------------------------------------
__device__ __forceinline__ unsigned f2tf(float f) {
    unsigned u;
    asm("cvt.rna.tf32.f32 %0, %1;" : "=r"(u) : "f"(f));
    return u;
}
__device__ __forceinline__ float f2tff(float f) { return __uint_as_float(f2tf(f)); }

__device__ __forceinline__ void mma8(float* c, const unsigned* a, const unsigned* b) {
    asm volatile(
        "mma.sync.aligned.m16n8k8.row.col.f32.tf32.tf32.f32 "
        "{%0,%1,%2,%3}, {%4,%5,%6,%7}, {%8,%9}, {%0,%1,%2,%3};"
        : "+f"(c[0]), "+f"(c[1]), "+f"(c[2]), "+f"(c[3])
        : "r"(a[0]), "r"(a[1]), "r"(a[2]), "r"(a[3]), "r"(b[0]), "r"(b[1]));
}

__device__ __forceinline__ void ldmx4(unsigned& r0, unsigned& r1,
                                      unsigned& r2, unsigned& r3, unsigned addr) {
    asm volatile("ldmatrix.sync.aligned.m8n8.x4.shared.b16 {%0,%1,%2,%3}, [%4];"
                 : "=r"(r0), "=r"(r1), "=r"(r2), "=r"(r3) : "r"(addr));
}

__device__ __forceinline__ void cpa16(unsigned dst, const void* src, int ok) {
    asm volatile("cp.async.ca.shared.global [%0], [%1], 16, %2;"
                 :: "r"(dst), "l"(src), "r"(ok ? 16 : 0));
}
__device__ __forceinline__ void cpa_commit() {
    asm volatile("cp.async.commit_group;");
}
__device__ __forceinline__ void cpa_wait1() {
    asm volatile("cp.async.wait_group 1;");
}

// ---------------------------------------------------------------------------
// prep: mask-mode detect, per-batch compaction scan, null-kv row 0.
// ---------------------------------------------------------------------------
__global__ void prep_kernel(const unsigned char* __restrict__ cm,
                            const float* __restrict__ null_kv,
                            const float* __restrict__ k_scale) {
    __shared__ int flag;
    __shared__ int thsum[256];
    __shared__ int pref[257];
    const int tid = threadIdx.x;
    const int wid = tid >> 5, lane = tid & 31;

    if (tid == 0) flag = 0;
    __syncthreads();
    int any = 0;
    for (int i = tid; i < 1024; i += 256)
        if (cm[4*i + 1] != 0) any = 1;
    if (any) atomicOr(&flag, 1);
    __syncthreads();
    const int mode = flag;
    if (tid == 0) g_mask_mode = mode;
    const unsigned* m32 = (const unsigned*)cm;

    for (int b = 0; b < 2; b++) {
        int f[8], ls = 0;
        #pragma unroll
        for (int k = 0; k < 8; k++) {
            const int n = tid*8 + k;
            f[k] = mode ? (cm[b*N_ + n] != 0) : (m32[b*N_ + n] != 0u);
            ls += f[k];
        }
        thsum[tid] = ls;
        __syncthreads();
        if (tid == 0) {
            int s = 0;
            for (int i = 0; i < 256; i++) { pref[i] = s; s += thsum[i]; }
            pref[256] = s;
        }
        __syncthreads();
        int r = 1 + pref[tid];       // compacted rows start at 1 (0 = null)
        #pragma unroll
        for (int k = 0; k < 8; k++) {
            const int n = tid*8 + k;
            if (f[k]) { g_rank[b][n] = r; g_jmap[b][r] = n + 1; r++; }
            else        g_rank[b][n] = -1;
        }
        const int cnt = 1 + pref[256];
        if (tid == 0) { g_cnt[b] = cnt; g_jmap[b][0] = 0; }
        for (int i = cnt + tid; i < 2144; i += 256) g_jmap[b][i] = -1;
        __syncthreads();
    }

    // null kv -> compacted row 0 for all (b, h)
    for (int h = wid; h < H_; h += 8) {
        const int d0 = lane, d1 = lane + 32;
        const float k0 = null_kv[h*DH_ + d0], k1 = null_kv[h*DH_ + d1];
        const float v0 = null_kv[H_*DH_ + h*DH_ + d0];
        const float v1 = null_kv[H_*DH_ + h*DH_ + d1];
        float ss = k0*k0 + k1*k1;
        #pragma unroll
        for (int o = 16; o > 0; o >>= 1) ss += __shfl_xor_sync(0xFFFFFFFFu, ss, o);
        const float inv = 1.0f / fmaxf(sqrtf(ss), 1e-12f);
        const float ks0 = k_scale[d0], ks1 = k_scale[d1];
        #pragma unroll
        for (int b = 0; b < 2; b++) {
            const int bh = b*H_ + h;
            float* kp = g_k  + (size_t)bh * NK_ * DH_;
            float* vp = g_vt + (size_t)bh * DH_ * VTS_;
            kp[d0] = f2tff(k0*inv*ks0); kp[d1] = f2tff(k1*inv*ks1);
            vp[(size_t)d0*VTS_] = f2tff(v0);
            vp[(size_t)d1*VTS_] = f2tff(v1);
        }
    }
}

// ---------------------------------------------------------------------------
// LayerNorm
// ---------------------------------------------------------------------------
__global__ void ln_kernel(const float* __restrict__ x,
                          const float* __restrict__ gamma) {
    const int row = blockIdx.x;
    const int tid = threadIdx.x;
    const float4 a = ((const float4*)(x + (size_t)row * D_))[tid];
    float s  = a.x + a.y + a.z + a.w;
    float s2 = a.x*a.x + a.y*a.y + a.z*a.z + a.w*a.w;
    #pragma unroll
    for (int o = 16; o > 0; o >>= 1) {
        s  += __shfl_xor_sync(0xFFFFFFFFu, s,  o);
        s2 += __shfl_xor_sync(0xFFFFFFFFu, s2, o);
    }
    __shared__ float rs[8], rs2[8];
    if ((tid & 31) == 0) { rs[tid >> 5] = s; rs2[tid >> 5] = s2; }
    __syncthreads();
    float S = 0.f, S2 = 0.f;
    #pragma unroll
    for (int i = 0; i < 8; i++) { S += rs[i]; S2 += rs2[i]; }
    const float mu  = S * (1.0f / D_);
    const float var = S2 * (1.0f / D_) - mu * mu;
    const float inv = rsqrtf(var + 1e-5f);
    const float4 g = ((const float4*)gamma)[tid];
    float4 o;
    o.x = (a.x - mu) * inv * g.x;
    o.y = (a.y - mu) * inv * g.y;
    o.z = (a.z - mu) * inv * g.z;
    o.w = (a.w - mu) * inv * g.w;
    ((float4*)(g_xn + (size_t)row * D_))[tid] = o;
}

// ---------------------------------------------------------------------------
// tf32 tensor-core GEMM core: 128x128 tile, BK=16, 256 threads (8 warps 4x2).
// A-fragments loaded via ldmatrix.x4.
// ---------------------------------------------------------------------------
#define AS_STR 20
#define BS_STR2 136

struct __align__(16) GemmSmem {
    float As[2][128*AS_STR];
    float Bs[2][16*BS_STR2];
};

__device__ __forceinline__ void gemm_core_compute(
    const GemmSmem* sm, int buf, int wm, int wn, int gid, int tig,
    float acc[2][8][4])
{
    const unsigned* bb = (const unsigned*)sm->Bs[buf];
    const unsigned au = (unsigned)__cvta_generic_to_shared(&sm->As[buf][0]);
    const int lane = threadIdx.x & 31;
    const int mi = lane >> 3, mr = lane & 7;
    const unsigned a_off = (unsigned)((((mi & 1)*8 + mr)*AS_STR + (mi >> 1)*4) * 4);

    #pragma unroll
    for (int kk = 0; kk < 2; kk++) {
        unsigned afr[2][4];
        #pragma unroll
        for (int mt = 0; mt < 2; mt++) {
            ldmx4(afr[mt][0], afr[mt][1], afr[mt][2], afr[mt][3],
                  au + a_off + (unsigned)(((wm*32 + mt*16)*AS_STR + kk*8) * 4));
        }
        unsigned bfr[8][2];
        #pragma unroll
        for (int nt = 0; nt < 8; nt++) {
            const int k = kk*8 + tig;
            const int n = wn*64 + nt*8 + gid;
            bfr[nt][0] = bb[(size_t)k*BS_STR2 + n];
            bfr[nt][1] = bb[(size_t)(k+4)*BS_STR2 + n];
        }
        #pragma unroll
        for (int mt = 0; mt < 2; mt++)
            #pragma unroll
            for (int nt = 0; nt < 8; nt++)
                mma8(acc[mt][nt], afr[mt], bfr[nt]);
    }
}

__device__ __forceinline__ void gemm_main_loop(
    const float* __restrict__ A, const float* __restrict__ Bp,
    int ldb, int cb, int bm, GemmSmem* sm,
    int wm, int wn, int gid, int tig, float acc[2][8][4])
{
    const int tid = threadIdx.x;
    const int ar = tid >> 2, akc = (tid & 3) * 4;
    const int bk = tid >> 5, bnc = (tid & 31) * 4;

    float4 ra0, ra1, rb0, rb1;
    ra0 = *(const float4*)(A + (size_t)(bm + ar) * 1024 + akc);
    ra1 = *(const float4*)(A + (size_t)(bm + ar + 64) * 1024 + akc);
    rb0 = *(const float4*)(Bp + (size_t)bk * ldb + cb + bnc);
    rb1 = *(const float4*)(Bp + (size_t)(bk + 8) * ldb + cb + bnc);
    {
        unsigned* d0 = (unsigned*)&sm->As[0][ar*AS_STR + akc];
        d0[0]=f2tf(ra0.x); d0[1]=f2tf(ra0.y); d0[2]=f2tf(ra0.z); d0[3]=f2tf(ra0.w);
        unsigned* d1 = (unsigned*)&sm->As[0][(ar+64)*AS_STR + akc];
        d1[0]=f2tf(ra1.x); d1[1]=f2tf(ra1.y); d1[2]=f2tf(ra1.z); d1[3]=f2tf(ra1.w);
        unsigned* e0 = (unsigned*)&sm->Bs[0][bk*BS_STR2 + bnc];
        e0[0]=f2tf(rb0.x); e0[1]=f2tf(rb0.y); e0[2]=f2tf(rb0.z); e0[3]=f2tf(rb0.w);
        unsigned* e1 = (unsigned*)&sm->Bs[0][(bk+8)*BS_STR2 + bnc];
        e1[0]=f2tf(rb1.x); e1[1]=f2tf(rb1.y); e1[2]=f2tf(rb1.z); e1[3]=f2tf(rb1.w);
    }
    __syncthreads();

    int buf = 0;
    for (int kt = 0; kt < 64; kt++) {
        if (kt < 63) {
            const int k0 = (kt + 1) * 16;
            ra0 = *(const float4*)(A + (size_t)(bm + ar) * 1024 + k0 + akc);
            ra1 = *(const float4*)(A + (size_t)(bm + ar + 64) * 1024 + k0 + akc);
            rb0 = *(const float4*)(Bp + (size_t)(k0 + bk) * ldb + cb + bnc);
            rb1 = *(const float4*)(Bp + (size_t)(k0 + bk + 8) * ldb + cb + bnc);
        }
        gemm_core_compute(sm, buf, wm, wn, gid, tig, acc);
        if (kt < 63) {
            const int nb = buf ^ 1;
            unsigned* d0 = (unsigned*)&sm->As[nb][ar*AS_STR + akc];
            d0[0]=f2tf(ra0.x); d0[1]=f2tf(ra0.y); d0[2]=f2tf(ra0.z); d0[3]=f2tf(ra0.w);
            unsigned* d1 = (unsigned*)&sm->As[nb][(ar+64)*AS_STR + akc];
            d1[0]=f2tf(ra1.x); d1[1]=f2tf(ra1.y); d1[2]=f2tf(ra1.z); d1[3]=f2tf(ra1.w);
            unsigned* e0 = (unsigned*)&sm->Bs[nb][bk*BS_STR2 + bnc];
            e0[0]=f2tf(rb0.x); e0[1]=f2tf(rb0.y); e0[2]=f2tf(rb0.z); e0[3]=f2tf(rb0.w);
            unsigned* e1 = (unsigned*)&sm->Bs[nb][(bk+8)*BS_STR2 + bnc];
            e1[0]=f2tf(rb1.x); e1[1]=f2tf(rb1.y); e1[2]=f2tf(rb1.z); e1[3]=f2tf(rb1.w);
            __syncthreads();
            buf = nb;
        }
    }
}

// ---------------------------------------------------------------------------
// QKV GEMM with FUSED l2norm/scale + compaction scatter (v transposed).
// ---------------------------------------------------------------------------
__global__ __launch_bounds__(256)
void gemm_qkv_tc(const float* __restrict__ Wq, const float* __restrict__ Wkv,
                 const float* __restrict__ q_scale,
                 const float* __restrict__ k_scale) {
    __shared__ GemmSmem sm;
    const int tid = threadIdx.x;
    const int wid = tid >> 5, lane = tid & 31;
    const int gid = lane >> 2, tig = lane & 3;
    const int wm = wid & 3, wn = wid >> 2;
    const int bm = blockIdx.y * 128, bn = blockIdx.x * 128;
    const float* Bp; int ldb, cb;
    if (bn < 1024) { Bp = Wq;  ldb = 1024; cb = bn; }
    else           { Bp = Wkv; ldb = 2048; cb = bn - 1024; }

    float acc[2][8][4] = {};
    gemm_main_loop(g_xn, Bp, ldb, cb, bm, &sm, wm, wn, gid, tig, acc);

    const int hv = (bn + wn*64) >> 6;   // 0..15 q, 16..31 k, 32..47 v

    #pragma unroll
    for (int mt = 0; mt < 2; mt++) {
        #pragma unroll
        for (int i = 0; i < 2; i++) {
            const int row = bm + wm*32 + mt*16 + gid + i*8;
            const int bidx = row >> 11, n = row & 2047;
            float ss = 0.f;
            #pragma unroll
            for (int nt = 0; nt < 8; nt++)
                ss += acc[mt][nt][i*2]*acc[mt][nt][i*2]
                    + acc[mt][nt][i*2+1]*acc[mt][nt][i*2+1];
            ss += __shfl_xor_sync(0xFFFFFFFFu, ss, 1);
            ss += __shfl_xor_sync(0xFFFFFFFFu, ss, 2);

            if (hv < 16) {
                const float inv = 1.0f / fmaxf(sqrtf(ss), 1e-12f);
                float* dst = g_q + (((size_t)(bidx*H_ + hv))*N_ + n)*DH_;
                #pragma unroll
                for (int nt = 0; nt < 8; nt++) {
                    const int d = nt*8 + 2*tig;
                    *(float2*)(dst + d) = make_float2(
                        f2tff(acc[mt][nt][i*2]   * inv * q_scale[d]),
                        f2tff(acc[mt][nt][i*2+1] * inv * q_scale[d+1]));
                }
            } else if (hv < 32) {
                const int r = g_rank[bidx][n];
                if (r >= 0) {
                    const float inv = 1.0f / fmaxf(sqrtf(ss), 1e-12f);
                    float* dst = g_k + (((size_t)(bidx*H_ + hv-16))*NK_ + r)*DH_;
                    #pragma unroll
                    for (int nt = 0; nt < 8; nt++) {
                        const int d = nt*8 + 2*tig;
                        *(float2*)(dst + d) = make_float2(
                            f2tff(acc[mt][nt][i*2]   * inv * k_scale[d]),
                            f2tff(acc[mt][nt][i*2+1] * inv * k_scale[d+1]));
                    }
                }
            } else {
                const int r = g_rank[bidx][n];
                if (r >= 0) {
                    // transposed store: g_vt[bh][d][r]
                    float* dst = g_vt + ((size_t)(bidx*H_ + hv-32))*DH_*VTS_ + r;
                    #pragma unroll
                    for (int nt = 0; nt < 8; nt++) {
                        const int d = nt*8 + 2*tig;
                        dst[(size_t)d*VTS_]     = f2tff(acc[mt][nt][i*2]);
                        dst[(size_t)(d+1)*VTS_] = f2tff(acc[mt][nt][i*2+1]);
                    }
                }
            }
        }
    }
}

// Output GEMM: d_out(4096 x 1024) = g_ao @ Wout
__global__ __launch_bounds__(256)
void gemm_out_tc(const float* __restrict__ Wout, float* __restrict__ out) {
    __shared__ GemmSmem sm;
    const int tid = threadIdx.x;
    const int wid = tid >> 5, lane = tid & 31;
    const int gid = lane >> 2, tig = lane & 3;
    const int wm = wid & 3, wn = wid >> 2;
    const int bm = blockIdx.y * 128, bn = blockIdx.x * 128;

    float acc[2][8][4] = {};
    gemm_main_loop(g_ao, Wout, 1024, bn, bm, &sm, wm, wn, gid, tig, acc);

    #pragma unroll
    for (int mt = 0; mt < 2; mt++) {
        #pragma unroll
        for (int i = 0; i < 2; i++) {
            const int row = bm + wm*32 + mt*16 + gid + i*8;
            #pragma unroll
            for (int nt = 0; nt < 8; nt++) {
                const int col = bn + wn*64 + nt*8 + 2*tig;
                *(float2*)&out[(size_t)row*1024 + col] =
                    make_float2(acc[mt][nt][i*2], acc[mt][nt][i*2+1]);
            }
        }
    }
}

// ---------------------------------------------------------------------------
// tf32 flash attention over COMPACTED kv, ldmatrix fragment loads.
// 256 threads, 128 q-rows/block. K smem [j][d], Vt smem [d][j], P [16][68]/warp.
// ---------------------------------------------------------------------------
#define KS_STR 68
#define VT_STR 68
#define PS_STR 68

__device__ __forceinline__ void attn_prefetch_tile(
    int t, int cnt, int cpr, int cpc,
    unsigned ks_s0, unsigned vt_s0,
    const float* __restrict__ kb, const float* __restrict__ vtb)
{
    const int jb = t * 64;
    const unsigned kdst = ks_s0 + (unsigned)((t & 1) * 4352 * 4);
    const unsigned vdst = vt_s0 + (unsigned)((t & 1) * 4352 * 4);
    #pragma unroll
    for (int i = 0; i < 4; i++) {
        const int r = cpr + i*16;
        // K: rows are j (validity by row); Vt: rows are d (validity by col)
        const int okk = (jb + r) < cnt;
        const int okv = (jb + cpc) < cnt;
        cpa16(kdst + (unsigned)(r*KS_STR + cpc)*4, kb  + (size_t)(jb + r)*64 + cpc, okk);
        cpa16(vdst + (unsigned)(r*VT_STR + cpc)*4, vtb + (size_t)r*VTS_ + jb + cpc, okv);
    }
}

__global__ __launch_bounds__(256)
void attn_tc2(const float* __restrict__ attn_bias) {
    extern __shared__ __align__(16) float smf[];
    float* Ksf = smf;                       // 2 * 64*68 = 8704 floats
    float* Vtf = smf + 8704;                // 2 * 64*68 = 8704 floats
    float* Psf = smf + 17408;               // 8 * 16*68 = 8704 floats

    const int tid = threadIdx.x;
    const int wid = tid >> 5, lane = tid & 31;
    const int gid = lane >> 2, tig = lane & 3;
    const int qt = blockIdx.x & 15, bh = blockIdx.x >> 4;
    const int b = bh >> 4, h = bh & 15;
    const int i0 = qt * 128;

    const int cnt   = g_cnt[b];
    const int tiles = (cnt + 63) >> 6;
    const int* jmap = g_jmap[b];

    // ldmatrix per-thread offsets
    const int mi = lane >> 3, mr = lane & 7;
    const unsigned kv_off = (unsigned)((((mi >> 1)*8 + mr)*KS_STR + (mi & 1)*4) * 4);
    const unsigned p_off  = (unsigned)((((mi & 1)*8 + mr)*PS_STR + (mi >> 1)*4) * 4);

    // Q fragments: pre-rounded tf32 bits, register-resident
    unsigned qa[8][4];
    {
        const float* qb = g_q + ((size_t)bh*N_ + i0 + wid*16)*DH_;
        #pragma unroll
        for (int ks = 0; ks < 8; ks++) {
            qa[ks][0] = __float_as_uint(qb[gid*64 + ks*8 + tig]);
            qa[ks][1] = __float_as_uint(qb[(gid+8)*64 + ks*8 + tig]);
            qa[ks][2] = __float_as_uint(qb[gid*64 + ks*8 + tig + 4]);
            qa[ks][3] = __float_as_uint(qb[(gid+8)*64 + ks*8 + tig + 4]);
        }
    }

    float O[8][4];
    #pragma unroll
    for (int nt = 0; nt < 8; nt++)
        #pragma unroll
        for (int i = 0; i < 4; i++) O[nt][i] = 0.f;
    float m0 = -FLT_MAX, m1 = -FLT_MAX, l0 = 0.f, l1 = 0.f;

    const float* kb  = g_k  + (size_t)bh * NK_ * DH_;
    const float* vtb = g_vt + (size_t)bh * DH_ * VTS_;
    float* pw = Psf + wid * (16 * PS_STR);

    const unsigned ks_s0 = (unsigned)__cvta_generic_to_shared(Ksf);
    const unsigned vt_s0 = (unsigned)__cvta_generic_to_shared(Vtf);
    const unsigned pw_s0 = (unsigned)__cvta_generic_to_shared(pw);
    const int cpr = tid >> 4, cpc = (tid & 15) * 4;

    attn_prefetch_tile(0, cnt, cpr, cpc, ks_s0, vt_s0, kb, vtb);
    cpa_commit();
    __syncthreads();

    for (int t = 0; t < tiles; t++) {
        const int buf = t & 1;
        const int jb = t * 64;
        if (t + 1 < tiles)
            attn_prefetch_tile(t + 1, cnt, cpr, cpc, ks_s0, vt_s0, kb, vtb);
        cpa_commit();

        // ---- jmap + bias prefetch into registers (consumed after S MMAs) ----
        const float* biasA = attn_bias + (size_t)(C_ + i0 + wid*16 + gid)*LDBIAS_ + (C_ - 1);
        const float* biasB = biasA + (size_t)8*LDBIAS_;
        int   jg[8][2];
        float bA[8][2], bB[8][2];
        #pragma unroll
        for (int nt = 0; nt < 8; nt++) {
            const int c0 = jb + nt*8 + 2*tig;
            jg[nt][0] = __ldg(jmap + c0);
            jg[nt][1] = __ldg(jmap + c0 + 1);
            const bool ok0 = jg[nt][0] > 0;
            const bool ok1 = jg[nt][1] > 0;
            const int o0 = ok0 ? jg[nt][0] : 0;
            const int o1 = ok1 ? jg[nt][1] : 0;
            bA[nt][0] = ok0 ? __ldg(biasA + o0) : 0.f;
            bA[nt][1] = ok1 ? __ldg(biasA + o1) : 0.f;
            bB[nt][0] = ok0 ? __ldg(biasB + o0) : 0.f;
            bB[nt][1] = ok1 ? __ldg(biasB + o1) : 0.f;
        }

        cpa_wait1();
        __syncthreads();

        const unsigned kbase = ks_s0 + (unsigned)(buf * 4352 * 4) + kv_off;
        const unsigned vbase = vt_s0 + (unsigned)(buf * 4352 * 4) + kv_off;

        // ---- S = Q K^T (K frags via ldmatrix) ----
        float sc[8][4];
        #pragma unroll
        for (int nt = 0; nt < 8; nt++)
            #pragma unroll
            for (int i = 0; i < 4; i++) sc[nt][i] = 0.f;
        #pragma unroll
        for (int ks = 0; ks < 8; ks++) {
            unsigned kf[8][2];
            #pragma unroll
            for (int np = 0; np < 4; np++)
                ldmx4(kf[2*np][0], kf[2*np][1], kf[2*np+1][0], kf[2*np+1][1],
                      kbase + (unsigned)(((2*np)*8*KS_STR + ks*8) * 4));
            #pragma unroll
            for (int nt = 0; nt < 8; nt++)
                mma8(sc[nt], qa[ks], kf[nt]);
        }

        // ---- scale + bias + validity, online softmax in registers ----
        float mx0 = -FLT_MAX, mx1 = -FLT_MAX;
        #pragma unroll
        for (int nt = 0; nt < 8; nt++) {
            const bool v0 = jg[nt][0] >= 0, v1 = jg[nt][1] >= 0;
            sc[nt][0] = v0 ? sc[nt][0]*8.f + bA[nt][0] : -FLT_MAX;
            sc[nt][1] = v1 ? sc[nt][1]*8.f + bA[nt][1] : -FLT_MAX;
            sc[nt][2] = v0 ? sc[nt][2]*8.f + bB[nt][0] : -FLT_MAX;
            sc[nt][3] = v1 ? sc[nt][3]*8.f + bB[nt][1] : -FLT_MAX;
            mx0 = fmaxf(mx0, fmaxf(sc[nt][0], sc[nt][1]));
            mx1 = fmaxf(mx1, fmaxf(sc[nt][2], sc[nt][3]));
        }
        mx0 = fmaxf(mx0, __shfl_xor_sync(0xFFFFFFFFu, mx0, 1));
        mx0 = fmaxf(mx0, __shfl_xor_sync(0xFFFFFFFFu, mx0, 2));
        mx1 = fmaxf(mx1, __shfl_xor_sync(0xFFFFFFFFu, mx1, 1));
        mx1 = fmaxf(mx1, __shfl_xor_sync(0xFFFFFFFFu, mx1, 2));
        const float mn0 = fmaxf(m0, mx0), mn1 = fmaxf(m1, mx1);
        const float f0 = __expf(m0 - mn0), f1 = __expf(m1 - mn1);
        float s0 = 0.f, s1 = 0.f;
        unsigned* pwu = (unsigned*)pw;
        #pragma unroll
        for (int nt = 0; nt < 8; nt++) {
            const float p0 = __expf(sc[nt][0] - mn0);
            const float p1 = __expf(sc[nt][1] - mn0);
            const float p2 = __expf(sc[nt][2] - mn1);
            const float p3 = __expf(sc[nt][3] - mn1);
            s0 += p0 + p1; s1 += p2 + p3;
            const int c0 = nt*8 + 2*tig;
            *(uint2*)(pwu + gid*PS_STR + c0)     = make_uint2(f2tf(p0), f2tf(p1));
            *(uint2*)(pwu + (gid+8)*PS_STR + c0) = make_uint2(f2tf(p2), f2tf(p3));
        }
        s0 += __shfl_xor_sync(0xFFFFFFFFu, s0, 1);
        s0 += __shfl_xor_sync(0xFFFFFFFFu, s0, 2);
        s1 += __shfl_xor_sync(0xFFFFFFFFu, s1, 1);
        s1 += __shfl_xor_sync(0xFFFFFFFFu, s1, 2);
        l0 = l0 * f0 + s0; l1 = l1 * f1 + s1;
        m0 = mn0; m1 = mn1;
        #pragma unroll
        for (int nt = 0; nt < 8; nt++) {
            O[nt][0] *= f0; O[nt][1] *= f0;
            O[nt][2] *= f1; O[nt][3] *= f1;
        }
        __syncwarp();

        // ---- O += P V (P a-frags + Vt b-frags via ldmatrix) ----
        #pragma unroll
        for (int ks = 0; ks < 8; ks++) {
            unsigned pa[4];
            ldmx4(pa[0], pa[1], pa[2], pa[3], pw_s0 + p_off + (unsigned)(ks*8*4));
            unsigned vf[8][2];
            #pragma unroll
            for (int np = 0; np < 4; np++)
                ldmx4(vf[2*np][0], vf[2*np][1], vf[2*np+1][0], vf[2*np+1][1],
                      vbase + (unsigned)(((2*np)*8*VT_STR + ks*8) * 4));
            #pragma unroll
            for (int nt = 0; nt < 8; nt++)
                mma8(O[nt], pa, vf[nt]);
        }
        __syncthreads();
    }

    const float inv0 = 1.f / l0, inv1 = 1.f / l1;
    float* ob = g_ao + ((size_t)b*N_ + i0 + wid*16)*1024 + h*64;
    #pragma unroll
    for (int nt = 0; nt < 8; nt++) {
        const int c0 = nt*8 + 2*tig;
        *(float2*)(ob + (size_t)gid*1024 + c0) =
            make_float2(f2tff(O[nt][0]*inv0), f2tff(O[nt][1]*inv0));
        *(float2*)(ob + (size_t)(gid+8)*1024 + c0) =
            make_float2(f2tff(O[nt][2]*inv1), f2tff(O[nt][3]*inv1));
    }
}

// ---------------------------------------------------------------------------
extern "C" void kernel_launch(void* const* d_in, const int* in_sizes, int n_in,
                              void* d_out, int out_size) {
    const float* x         = (const float*)d_in[0];
    const float* attn_bias = (const float*)d_in[1];
    const void*  cmask     = (const void*) d_in[2];
    const float* gamma     = (const float*)d_in[3];
    const float* null_kv   = (const float*)d_in[4];
    const float* Wq        = (const float*)d_in[5];
    const float* Wkv       = (const float*)d_in[6];
    const float* q_scale   = (const float*)d_in[7];
    const float* k_scale   = (const float*)d_in[8];
    const float* Wout      = (const float*)d_in[9];
    float* out = (float*)d_out;

    static const int attn_smem = 26112 * 4;   // 104448 B
    cudaFuncSetAttribute(attn_tc2,
                         cudaFuncAttributeMaxDynamicSharedMemorySize,
                         attn_smem);

    prep_kernel<<<1, 256>>>((const unsigned char*)cmask, null_kv, k_scale);
    ln_kernel<<<ROWS_, 256>>>(x, gamma);
    gemm_qkv_tc<<<dim3(24, 32), 256>>>(Wq, Wkv, q_scale, k_scale);
    attn_tc2<<<BH_ * 16, 256, attn_smem>>>(attn_bias);
    gemm_out_tc<<<dim3(8, 32), 256>>>(Wout, out);
}

// round 10
// speedup vs baseline: 1.5136x; 1.0955x over previous
#include <cuda_runtime.h>
#include <math.h>
#include <float.h>

// Problem dims
#define B_   2
#define N_   2048
#define D_   1024
#define H_   16
#define DH_  64
#define C_   64
#define NK_  2049            // N+1 (null kv prepended)
#define VTS_ 2052            // Vt row stride (floats), 16B-aligned
#define BCS_ 2144            // compacted-bias row stride (floats), 16B-aligned
#define BH_  (B_*H_)         // 32
#define ROWS_ (B_*N_)        // 4096
#define LDBIAS_ (C_+N_)      // 2112

// Scratch (device globals: allocation-free rule)
__device__ float g_xn[ROWS_*D_];        // layernormed x
__device__ float g_q [BH_*N_ *DH_];     // head-major q (l2normed+scaled, tf32)
__device__ float g_k [BH_*NK_*DH_];     // head-major COMPACTED k (row 0 = null, tf32)
__device__ float g_vt[BH_*DH_*VTS_];    // head-major COMPACTED v TRANSPOSED [bh][d][j], tf32
__device__ float g_ao[ROWS_*D_];        // attention output (b,n,h*64+d)
__device__ float g_biasc[(size_t)ROWS_*BCS_];  // compacted bias [b*N+i][r]
__device__ int   g_mask_mode;           // 1 = 1-byte mask, 0 = 4-byte mask
__device__ int   g_cnt[2];              // compacted kv count per batch (incl null)
__device__ int   g_rank[2][2048];       // n -> compacted row (or -1)
__device__ int   g_jmap[2][2144];       // compacted row -> original j (0..2048), -1 pad

// ---------------------------------------------------------------------------
// tf32 / mma / ldmatrix helpers
// ---------------------------------------------------------------------------
__device__ __forceinline__ unsigned f2tf(float f) {
    unsigned u;
    asm("cvt.rna.tf32.f32 %0, %1;" : "=r"(u) : "f"(f));
    return u;
}
__device__ __forceinline__ float f2tff(float f) { return __uint_as_float(f2tf(f)); }

__device__ __forceinline__ void mma8(float* c, const unsigned* a, const unsigned* b) {
    asm volatile(
        "mma.sync.aligned.m16n8k8.row.col.f32.tf32.tf32.f32 "
        "{%0,%1,%2,%3}, {%4,%5,%6,%7}, {%8,%9}, {%0,%1,%2,%3};"
        : "+f"(c[0]), "+f"(c[1]), "+f"(c[2]), "+f"(c[3])
        : "r"(a[0]), "r"(a[1]), "r"(a[2]), "r"(a[3]), "r"(b[0]), "r"(b[1]));
}

__device__ __forceinline__ void ldmx4(unsigned& r0, unsigned& r1,
                                      unsigned& r2, unsigned& r3, unsigned addr) {
    asm volatile("ldmatrix.sync.aligned.m8n8.x4.shared.b16 {%0,%1,%2,%3}, [%4];"
                 : "=r"(r0), "=r"(r1), "=r"(r2), "=r"(r3) : "r"(addr));
}

__device__ __forceinline__ void cpa16(unsigned dst, const void* src, int ok) {
    asm volatile("cp.async.ca.shared.global [%0], [%1], 16, %2;"
                 :: "r"(dst), "l"(src), "r"(ok ? 16 : 0));
}
__device__ __forceinline__ void cpa_commit() {
    asm volatile("cp.async.commit_group;");
}
__device__ __forceinline__ void cpa_wait1() {
    asm volatile("cp.async.wait_group 1;");
}

// ---------------------------------------------------------------------------
// prep: mask-mode detect, per-batch compaction scan, null-kv row 0.
// ---------------------------------------------------------------------------
__global__ void prep_kernel(const unsigned char* __restrict__ cm,
                            const float* __restrict__ null_kv,
                            const float* __restrict__ k_scale) {
    __shared__ int flag;
    __shared__ int thsum[256];
    __shared__ int pref[257];
    const int tid = threadIdx.x;
    const int wid = tid >> 5, lane = tid & 31;

    if (tid == 0) flag = 0;
    __syncthreads();
    int any = 0;
    for (int i = tid; i < 1024; i += 256)
        if (cm[4*i + 1] != 0) any = 1;
    if (any) atomicOr(&flag, 1);
    __syncthreads();
    const int mode = flag;
    if (tid == 0) g_mask_mode = mode;
    const unsigned* m32 = (const unsigned*)cm;

    for (int b = 0; b < 2; b++) {
        int f[8], ls = 0;
        #pragma unroll
        for (int k = 0; k < 8; k++) {
            const int n = tid*8 + k;
            f[k] = mode ? (cm[b*N_ + n] != 0) : (m32[b*N_ + n] != 0u);
            ls += f[k];
        }
        thsum[tid] = ls;
        __syncthreads();
        if (tid == 0) {
            int s = 0;
            for (int i = 0; i < 256; i++) { pref[i] = s; s += thsum[i]; }
            pref[256] = s;
        }
        __syncthreads();
        int r = 1 + pref[tid];       // compacted rows start at 1 (0 = null)
        #pragma unroll
        for (int k = 0; k < 8; k++) {
            const int n = tid*8 + k;
            if (f[k]) { g_rank[b][n] = r; g_jmap[b][r] = n + 1; r++; }
            else        g_rank[b][n] = -1;
        }
        const int cnt = 1 + pref[256];
        if (tid == 0) { g_cnt[b] = cnt; g_jmap[b][0] = 0; }
        for (int i = cnt + tid; i < 2144; i += 256) g_jmap[b][i] = -1;
        __syncthreads();
    }

    // null kv -> compacted row 0 for all (b, h)
    for (int h = wid; h < H_; h += 8) {
        const int d0 = lane, d1 = lane + 32;
        const float k0 = null_kv[h*DH_ + d0], k1 = null_kv[h*DH_ + d1];
        const float v0 = null_kv[H_*DH_ + h*DH_ + d0];
        const float v1 = null_kv[H_*DH_ + h*DH_ + d1];
        float ss = k0*k0 + k1*k1;
        #pragma unroll
        for (int o = 16; o > 0; o >>= 1) ss += __shfl_xor_sync(0xFFFFFFFFu, ss, o);
        const float inv = 1.0f / fmaxf(sqrtf(ss), 1e-12f);
        const float ks0 = k_scale[d0], ks1 = k_scale[d1];
        #pragma unroll
        for (int b = 0; b < 2; b++) {
            const int bh = b*H_ + h;
            float* kp = g_k  + (size_t)bh * NK_ * DH_;
            float* vp = g_vt + (size_t)bh * DH_ * VTS_;
            kp[d0] = f2tff(k0*inv*ks0); kp[d1] = f2tff(k1*inv*ks1);
            vp[(size_t)d0*VTS_] = f2tff(v0);
            vp[(size_t)d1*VTS_] = f2tff(v1);
        }
    }
}

// ---------------------------------------------------------------------------
// bias gather into compacted layout: g_biasc[b*N+i][r] = bias[C+i][C-1+jmap[r]]
// (r=0 / padding -> 0). jmap monotone => gathers are L2/sector friendly.
// ---------------------------------------------------------------------------
__global__ void bias_gather(const float* __restrict__ attn_bias) {
    const int row = blockIdx.x;        // 0..4095
    const int b = row >> 11, i = row & 2047;
    const int* jm = g_jmap[b];
    const float* src = attn_bias + (size_t)(C_ + i)*LDBIAS_ + (C_ - 1);
    float* dst = g_biasc + (size_t)row * BCS_;
    for (int r = threadIdx.x; r < BCS_; r += 256) {
        const int off = jm[r];
        dst[r] = (off > 0) ? __ldg(src + off) : 0.f;
    }
}

// ---------------------------------------------------------------------------
// LayerNorm
// ---------------------------------------------------------------------------
__global__ void ln_kernel(const float* __restrict__ x,
                          const float* __restrict__ gamma) {
    const int row = blockIdx.x;
    const int tid = threadIdx.x;
    const float4 a = ((const float4*)(x + (size_t)row * D_))[tid];
    float s  = a.x + a.y + a.z + a.w;
    float s2 = a.x*a.x + a.y*a.y + a.z*a.z + a.w*a.w;
    #pragma unroll
    for (int o = 16; o > 0; o >>= 1) {
        s  += __shfl_xor_sync(0xFFFFFFFFu, s,  o);
        s2 += __shfl_xor_sync(0xFFFFFFFFu, s2, o);
    }
    __shared__ float rs[8], rs2[8];
    if ((tid & 31) == 0) { rs[tid >> 5] = s; rs2[tid >> 5] = s2; }
    __syncthreads();
    float S = 0.f, S2 = 0.f;
    #pragma unroll
    for (int i = 0; i < 8; i++) { S += rs[i]; S2 += rs2[i]; }
    const float mu  = S * (1.0f / D_);
    const float var = S2 * (1.0f / D_) - mu * mu;
    const float inv = rsqrtf(var + 1e-5f);
    const float4 g = ((const float4*)gamma)[tid];
    float4 o;
    o.x = (a.x - mu) * inv * g.x;
    o.y = (a.y - mu) * inv * g.y;
    o.z = (a.z - mu) * inv * g.z;
    o.w = (a.w - mu) * inv * g.w;
    ((float4*)(g_xn + (size_t)row * D_))[tid] = o;
}

// ---------------------------------------------------------------------------
// tf32 tensor-core GEMM core: 128x128 tile, BK=16, 256 threads (8 warps 4x2).
// ---------------------------------------------------------------------------
#define AS_STR 20
#define BS_STR2 136

struct __align__(16) GemmSmem {
    float As[2][128*AS_STR];
    float Bs[2][16*BS_STR2];
};

__device__ __forceinline__ void gemm_core_compute(
    const GemmSmem* sm, int buf, int wm, int wn, int gid, int tig,
    float acc[2][8][4])
{
    const unsigned* bb = (const unsigned*)sm->Bs[buf];
    const unsigned au = (unsigned)__cvta_generic_to_shared(&sm->As[buf][0]);
    const int lane = threadIdx.x & 31;
    const int mi = lane >> 3, mr = lane & 7;
    const unsigned a_off = (unsigned)((((mi & 1)*8 + mr)*AS_STR + (mi >> 1)*4) * 4);

    #pragma unroll
    for (int kk = 0; kk < 2; kk++) {
        unsigned afr[2][4];
        #pragma unroll
        for (int mt = 0; mt < 2; mt++) {
            ldmx4(afr[mt][0], afr[mt][1], afr[mt][2], afr[mt][3],
                  au + a_off + (unsigned)(((wm*32 + mt*16)*AS_STR + kk*8) * 4));
        }
        unsigned bfr[8][2];
        #pragma unroll
        for (int nt = 0; nt < 8; nt++) {
            const int k = kk*8 + tig;
            const int n = wn*64 + nt*8 + gid;
            bfr[nt][0] = bb[(size_t)k*BS_STR2 + n];
            bfr[nt][1] = bb[(size_t)(k+4)*BS_STR2 + n];
        }
        #pragma unroll
        for (int mt = 0; mt < 2; mt++)
            #pragma unroll
            for (int nt = 0; nt < 8; nt++)
                mma8(acc[mt][nt], afr[mt], bfr[nt]);
    }
}

__device__ __forceinline__ void gemm_main_loop(
    const float* __restrict__ A, const float* __restrict__ Bp,
    int ldb, int cb, int bm, GemmSmem* sm,
    int wm, int wn, int gid, int tig, float acc[2][8][4])
{
    const int tid = threadIdx.x;
    const int ar = tid >> 2, akc = (tid & 3) * 4;
    const int bk = tid >> 5, bnc = (tid & 31) * 4;

    float4 ra0, ra1, rb0, rb1;
    ra0 = *(const float4*)(A + (size_t)(bm + ar) * 1024 + akc);
    ra1 = *(const float4*)(A + (size_t)(bm + ar + 64) * 1024 + akc);
    rb0 = *(const float4*)(Bp + (size_t)bk * ldb + cb + bnc);
    rb1 = *(const float4*)(Bp + (size_t)(bk + 8) * ldb + cb + bnc);
    {
        unsigned* d0 = (unsigned*)&sm->As[0][ar*AS_STR + akc];
        d0[0]=f2tf(ra0.x); d0[1]=f2tf(ra0.y); d0[2]=f2tf(ra0.z); d0[3]=f2tf(ra0.w);
        unsigned* d1 = (unsigned*)&sm->As[0][(ar+64)*AS_STR + akc];
        d1[0]=f2tf(ra1.x); d1[1]=f2tf(ra1.y); d1[2]=f2tf(ra1.z); d1[3]=f2tf(ra1.w);
        unsigned* e0 = (unsigned*)&sm->Bs[0][bk*BS_STR2 + bnc];
        e0[0]=f2tf(rb0.x); e0[1]=f2tf(rb0.y); e0[2]=f2tf(rb0.z); e0[3]=f2tf(rb0.w);
        unsigned* e1 = (unsigned*)&sm->Bs[0][(bk+8)*BS_STR2 + bnc];
        e1[0]=f2tf(rb1.x); e1[1]=f2tf(rb1.y); e1[2]=f2tf(rb1.z); e1[3]=f2tf(rb1.w);
    }
    __syncthreads();

    int buf = 0;
    for (int kt = 0; kt < 64; kt++) {
        if (kt < 63) {
            const int k0 = (kt + 1) * 16;
            ra0 = *(const float4*)(A + (size_t)(bm + ar) * 1024 + k0 + akc);
            ra1 = *(const float4*)(A + (size_t)(bm + ar + 64) * 1024 + k0 + akc);
            rb0 = *(const float4*)(Bp + (size_t)(k0 + bk) * ldb + cb + bnc);
            rb1 = *(const float4*)(Bp + (size_t)(k0 + bk + 8) * ldb + cb + bnc);
        }
        gemm_core_compute(sm, buf, wm, wn, gid, tig, acc);
        if (kt < 63) {
            const int nb = buf ^ 1;
            unsigned* d0 = (unsigned*)&sm->As[nb][ar*AS_STR + akc];
            d0[0]=f2tf(ra0.x); d0[1]=f2tf(ra0.y); d0[2]=f2tf(ra0.z); d0[3]=f2tf(ra0.w);
            unsigned* d1 = (unsigned*)&sm->As[nb][(ar+64)*AS_STR + akc];
            d1[0]=f2tf(ra1.x); d1[1]=f2tf(ra1.y); d1[2]=f2tf(ra1.z); d1[3]=f2tf(ra1.w);
            unsigned* e0 = (unsigned*)&sm->Bs[nb][bk*BS_STR2 + bnc];
            e0[0]=f2tf(rb0.x); e0[1]=f2tf(rb0.y); e0[2]=f2tf(rb0.z); e0[3]=f2tf(rb0.w);
            unsigned* e1 = (unsigned*)&sm->Bs[nb][(bk+8)*BS_STR2 + bnc];
            e1[0]=f2tf(rb1.x); e1[1]=f2tf(rb1.y); e1[2]=f2tf(rb1.z); e1[3]=f2tf(rb1.w);
            __syncthreads();
            buf = nb;
        }
    }
}

// ---------------------------------------------------------------------------
// QKV GEMM with FUSED l2norm/scale + compaction scatter (v transposed).
// ---------------------------------------------------------------------------
__global__ __launch_bounds__(256)
void gemm_qkv_tc(const float* __restrict__ Wq, const float* __restrict__ Wkv,
                 const float* __restrict__ q_scale,
                 const float* __restrict__ k_scale) {
    __shared__ GemmSmem sm;
    const int tid = threadIdx.x;
    const int wid = tid >> 5, lane = tid & 31;
    const int gid = lane >> 2, tig = lane & 3;
    const int wm = wid & 3, wn = wid >> 2;
    const int bm = blockIdx.y * 128, bn = blockIdx.x * 128;
    const float* Bp; int ldb, cb;
    if (bn < 1024) { Bp = Wq;  ldb = 1024; cb = bn; }
    else           { Bp = Wkv; ldb = 2048; cb = bn - 1024; }

    float acc[2][8][4] = {};
    gemm_main_loop(g_xn, Bp, ldb, cb, bm, &sm, wm, wn, gid, tig, acc);

    const int hv = (bn + wn*64) >> 6;   // 0..15 q, 16..31 k, 32..47 v

    #pragma unroll
    for (int mt = 0; mt < 2; mt++) {
        #pragma unroll
        for (int i = 0; i < 2; i++) {
            const int row = bm + wm*32 + mt*16 + gid + i*8;
            const int bidx = row >> 11, n = row & 2047;
            float ss = 0.f;
            #pragma unroll
            for (int nt = 0; nt < 8; nt++)
                ss += acc[mt][nt][i*2]*acc[mt][nt][i*2]
                    + acc[mt][nt][i*2+1]*acc[mt][nt][i*2+1];
            ss += __shfl_xor_sync(0xFFFFFFFFu, ss, 1);
            ss += __shfl_xor_sync(0xFFFFFFFFu, ss, 2);

            if (hv < 16) {
                const float inv = 1.0f / fmaxf(sqrtf(ss), 1e-12f);
                float* dst = g_q + (((size_t)(bidx*H_ + hv))*N_ + n)*DH_;
                #pragma unroll
                for (int nt = 0; nt < 8; nt++) {
                    const int d = nt*8 + 2*tig;
                    *(float2*)(dst + d) = make_float2(
                        f2tff(acc[mt][nt][i*2]   * inv * q_scale[d]),
                        f2tff(acc[mt][nt][i*2+1] * inv * q_scale[d+1]));
                }
            } else if (hv < 32) {
                const int r = g_rank[bidx][n];
                if (r >= 0) {
                    const float inv = 1.0f / fmaxf(sqrtf(ss), 1e-12f);
                    float* dst = g_k + (((size_t)(bidx*H_ + hv-16))*NK_ + r)*DH_;
                    #pragma unroll
                    for (int nt = 0; nt < 8; nt++) {
                        const int d = nt*8 + 2*tig;
                        *(float2*)(dst + d) = make_float2(
                            f2tff(acc[mt][nt][i*2]   * inv * k_scale[d]),
                            f2tff(acc[mt][nt][i*2+1] * inv * k_scale[d+1]));
                    }
                }
            } else {
                const int r = g_rank[bidx][n];
                if (r >= 0) {
                    // transposed store: g_vt[bh][d][r]
                    float* dst = g_vt + ((size_t)(bidx*H_ + hv-32))*DH_*VTS_ + r;
                    #pragma unroll
                    for (int nt = 0; nt < 8; nt++) {
                        const int d = nt*8 + 2*tig;
                        dst[(size_t)d*VTS_]     = f2tff(acc[mt][nt][i*2]);
                        dst[(size_t)(d+1)*VTS_] = f2tff(acc[mt][nt][i*2+1]);
                    }
                }
            }
        }
    }
}

// Output GEMM: d_out(4096 x 1024) = g_ao @ Wout
__global__ __launch_bounds__(256)
void gemm_out_tc(const float* __restrict__ Wout, float* __restrict__ out) {
    __shared__ GemmSmem sm;
    const int tid = threadIdx.x;
    const int wid = tid >> 5, lane = tid & 31;
    const int gid = lane >> 2, tig = lane & 3;
    const int wm = wid & 3, wn = wid >> 2;
    const int bm = blockIdx.y * 128, bn = blockIdx.x * 128;

    float acc[2][8][4] = {};
    gemm_main_loop(g_ao, Wout, 1024, bn, bm, &sm, wm, wn, gid, tig, acc);

    #pragma unroll
    for (int mt = 0; mt < 2; mt++) {
        #pragma unroll
        for (int i = 0; i < 2; i++) {
            const int row = bm + wm*32 + mt*16 + gid + i*8;
            #pragma unroll
            for (int nt = 0; nt < 8; nt++) {
                const int col = bn + wn*64 + nt*8 + 2*tig;
                *(float2*)&out[(size_t)row*1024 + col] =
                    make_float2(acc[mt][nt][i*2], acc[mt][nt][i*2+1]);
            }
        }
    }
}

// ---------------------------------------------------------------------------
// tf32 flash attention over COMPACTED kv, ldmatrix fragment loads,
// 2 CTAs/SM (launch_bounds 256,2). Bias from compacted g_biasc (inline float2).
// Validity from cnt compare. K smem [j][d], Vt smem [d][j], P [16][68]/warp.
// ---------------------------------------------------------------------------
#define KS_STR 68
#define VT_STR 68
#define PS_STR 68

__device__ __forceinline__ void attn_prefetch_tile(
    int t, int cnt, int cpr, int cpc,
    unsigned ks_s0, unsigned vt_s0,
    const float* __restrict__ kb, const float* __restrict__ vtb)
{
    const int jb = t * 64;
    const unsigned kdst = ks_s0 + (unsigned)((t & 1) * 4352 * 4);
    const unsigned vdst = vt_s0 + (unsigned)((t & 1) * 4352 * 4);
    #pragma unroll
    for (int i = 0; i < 4; i++) {
        const int r = cpr + i*16;
        // K: rows are j (validity by row); Vt: rows are d (validity by col).
        // ok=0 -> src-size 0 -> smem zero-filled (tail stays exact zeros).
        const int okk = (jb + r) < cnt;
        const int okv = (jb + cpc) < cnt;
        cpa16(kdst + (unsigned)(r*KS_STR + cpc)*4, kb  + (size_t)(jb + r)*64 + cpc, okk);
        cpa16(vdst + (unsigned)(r*VT_STR + cpc)*4, vtb + (size_t)r*VTS_ + jb + cpc, okv);
    }
}

__global__ __launch_bounds__(256, 2)
void attn_tc2() {
    extern __shared__ __align__(16) float smf[];
    float* Ksf = smf;                       // 2 * 64*68 = 8704 floats
    float* Vtf = smf + 8704;                // 2 * 64*68 = 8704 floats
    float* Psf = smf + 17408;               // 8 * 16*68 = 8704 floats

    const int tid = threadIdx.x;
    const int wid = tid >> 5, lane = tid & 31;
    const int gid = lane >> 2, tig = lane & 3;
    const int qt = blockIdx.x & 15, bh = blockIdx.x >> 4;
    const int b = bh >> 4, h = bh & 15;
    const int i0 = qt * 128;

    const int cnt   = g_cnt[b];
    const int tiles = (cnt + 63) >> 6;

    // ldmatrix per-thread offsets
    const int mi = lane >> 3, mr = lane & 7;
    const unsigned kv_off = (unsigned)((((mi >> 1)*8 + mr)*KS_STR + (mi & 1)*4) * 4);
    const unsigned p_off  = (unsigned)((((mi & 1)*8 + mr)*PS_STR + (mi >> 1)*4) * 4);

    // Q fragments: pre-rounded tf32 bits, register-resident
    unsigned qa[8][4];
    {
        const float* qb = g_q + ((size_t)bh*N_ + i0 + wid*16)*DH_;
        #pragma unroll
        for (int ks = 0; ks < 8; ks++) {
            qa[ks][0] = __float_as_uint(qb[gid*64 + ks*8 + tig]);
            qa[ks][1] = __float_as_uint(qb[(gid+8)*64 + ks*8 + tig]);
            qa[ks][2] = __float_as_uint(qb[gid*64 + ks*8 + tig + 4]);
            qa[ks][3] = __float_as_uint(qb[(gid+8)*64 + ks*8 + tig + 4]);
        }
    }

    float O[8][4];
    #pragma unroll
    for (int nt = 0; nt < 8; nt++)
        #pragma unroll
        for (int i = 0; i < 4; i++) O[nt][i] = 0.f;
    float m0 = -FLT_MAX, m1 = -FLT_MAX, l0 = 0.f, l1 = 0.f;

    const float* kb  = g_k  + (size_t)bh * NK_ * DH_;
    const float* vtb = g_vt + (size_t)bh * DH_ * VTS_;
    const float* bcA = g_biasc + (size_t)(b*N_ + i0 + wid*16 + gid) * BCS_;
    const float* bcB = bcA + (size_t)8 * BCS_;
    float* pw = Psf + wid * (16 * PS_STR);

    const unsigned ks_s0 = (unsigned)__cvta_generic_to_shared(Ksf);
    const unsigned vt_s0 = (unsigned)__cvta_generic_to_shared(Vtf);
    const unsigned pw_s0 = (unsigned)__cvta_generic_to_shared(pw);
    const int cpr = tid >> 4, cpc = (tid & 15) * 4;

    attn_prefetch_tile(0, cnt, cpr, cpc, ks_s0, vt_s0, kb, vtb);
    cpa_commit();
    __syncthreads();

    for (int t = 0; t < tiles; t++) {
        const int buf = t & 1;
        const int jb = t * 64;
        if (t + 1 < tiles)
            attn_prefetch_tile(t + 1, cnt, cpr, cpc, ks_s0, vt_s0, kb, vtb);
        cpa_commit();

        cpa_wait1();
        __syncthreads();

        const unsigned kbase = ks_s0 + (unsigned)(buf * 4352 * 4) + kv_off;
        const unsigned vbase = vt_s0 + (unsigned)(buf * 4352 * 4) + kv_off;

        // ---- S = Q K^T (K frags via ldmatrix) ----
        float sc[8][4];
        #pragma unroll
        for (int nt = 0; nt < 8; nt++)
            #pragma unroll
            for (int i = 0; i < 4; i++) sc[nt][i] = 0.f;
        #pragma unroll
        for (int ks = 0; ks < 8; ks++) {
            unsigned kf[8][2];
            #pragma unroll
            for (int np = 0; np < 4; np++)
                ldmx4(kf[2*np][0], kf[2*np][1], kf[2*np+1][0], kf[2*np+1][1],
                      kbase + (unsigned)(((2*np)*8*KS_STR + ks*8) * 4));
            #pragma unroll
            for (int nt = 0; nt < 8; nt++)
                mma8(sc[nt], qa[ks], kf[nt]);
        }

        // ---- scale + bias (compacted, inline float2) + validity, softmax ----
        float mx0 = -FLT_MAX, mx1 = -FLT_MAX;
        #pragma unroll
        for (int nt = 0; nt < 8; nt++) {
            const int c0 = jb + nt*8 + 2*tig;
            const bool v0 = c0 < cnt, v1 = (c0 + 1) < cnt;
            const float2 ba = *(const float2*)(bcA + c0);
            const float2 bb2 = *(const float2*)(bcB + c0);
            sc[nt][0] = v0 ? sc[nt][0]*8.f + ba.x  : -FLT_MAX;
            sc[nt][1] = v1 ? sc[nt][1]*8.f + ba.y  : -FLT_MAX;
            sc[nt][2] = v0 ? sc[nt][2]*8.f + bb2.x : -FLT_MAX;
            sc[nt][3] = v1 ? sc[nt][3]*8.f + bb2.y : -FLT_MAX;
            mx0 = fmaxf(mx0, fmaxf(sc[nt][0], sc[nt][1]));
            mx1 = fmaxf(mx1, fmaxf(sc[nt][2], sc[nt][3]));
        }
        mx0 = fmaxf(mx0, __shfl_xor_sync(0xFFFFFFFFu, mx0, 1));
        mx0 = fmaxf(mx0, __shfl_xor_sync(0xFFFFFFFFu, mx0, 2));
        mx1 = fmaxf(mx1, __shfl_xor_sync(0xFFFFFFFFu, mx1, 1));
        mx1 = fmaxf(mx1, __shfl_xor_sync(0xFFFFFFFFu, mx1, 2));
        const float mn0 = fmaxf(m0, mx0), mn1 = fmaxf(m1, mx1);
        const float f0 = __expf(m0 - mn0), f1 = __expf(m1 - mn1);
        float s0 = 0.f, s1 = 0.f;
        unsigned* pwu = (unsigned*)pw;
        #pragma unroll
        for (int nt = 0; nt < 8; nt++) {
            const float p0 = __expf(sc[nt][0] - mn0);
            const float p1 = __expf(sc[nt][1] - mn0);
            const float p2 = __expf(sc[nt][2] - mn1);
            const float p3 = __expf(sc[nt][3] - mn1);
            s0 += p0 + p1; s1 += p2 + p3;
            const int c0 = nt*8 + 2*tig;
            *(uint2*)(pwu + gid*PS_STR + c0)     = make_uint2(f2tf(p0), f2tf(p1));
            *(uint2*)(pwu + (gid+8)*PS_STR + c0) = make_uint2(f2tf(p2), f2tf(p3));
        }
        s0 += __shfl_xor_sync(0xFFFFFFFFu, s0, 1);
        s0 += __shfl_xor_sync(0xFFFFFFFFu, s0, 2);
        s1 += __shfl_xor_sync(0xFFFFFFFFu, s1, 1);
        s1 += __shfl_xor_sync(0xFFFFFFFFu, s1, 2);
        l0 = l0 * f0 + s0; l1 = l1 * f1 + s1;
        m0 = mn0; m1 = mn1;
        #pragma unroll
        for (int nt = 0; nt < 8; nt++) {
            O[nt][0] *= f0; O[nt][1] *= f0;
            O[nt][2] *= f1; O[nt][3] *= f1;
        }
        __syncwarp();

        // ---- O += P V (P a-frags + Vt b-frags via ldmatrix) ----
        #pragma unroll
        for (int ks = 0; ks < 8; ks++) {
            unsigned pa[4];
            ldmx4(pa[0], pa[1], pa[2], pa[3], pw_s0 + p_off + (unsigned)(ks*8*4));
            unsigned vf[8][2];
            #pragma unroll
            for (int np = 0; np < 4; np++)
                ldmx4(vf[2*np][0], vf[2*np][1], vf[2*np+1][0], vf[2*np+1][1],
                      vbase + (unsigned)(((2*np)*8*VT_STR + ks*8) * 4));
            #pragma unroll
            for (int nt = 0; nt < 8; nt++)
                mma8(O[nt], pa, vf[nt]);
        }
        __syncthreads();
    }

    const float inv0 = 1.f / l0, inv1 = 1.f / l1;
    float* ob = g_ao + ((size_t)b*N_ + i0 + wid*16)*1024 + h*64;
    #pragma unroll
    for (int nt = 0; nt < 8; nt++) {
        const int c0 = nt*8 + 2*tig;
        *(float2*)(ob + (size_t)gid*1024 + c0) =
            make_float2(f2tff(O[nt][0]*inv0), f2tff(O[nt][1]*inv0));
        *(float2*)(ob + (size_t)(gid+8)*1024 + c0) =
            make_float2(f2tff(O[nt][2]*inv1), f2tff(O[nt][3]*inv1));
    }
}

// ---------------------------------------------------------------------------
extern "C" void kernel_launch(void* const* d_in, const int* in_sizes, int n_in,
                              void* d_out, int out_size) {
    const float* x         = (const float*)d_in[0];
    const float* attn_bias = (const float*)d_in[1];
    const void*  cmask     = (const void*) d_in[2];
    const float* gamma     = (const float*)d_in[3];
    const float* null_kv   = (const float*)d_in[4];
    const float* Wq        = (const float*)d_in[5];
    const float* Wkv       = (const float*)d_in[6];
    const float* q_scale   = (const float*)d_in[7];
    const float* k_scale   = (const float*)d_in[8];
    const float* Wout      = (const float*)d_in[9];
    float* out = (float*)d_out;

    static const int attn_smem = 26112 * 4;   // 104448 B (2 CTAs/SM fit in 227KB)
    cudaFuncSetAttribute(attn_tc2,
                         cudaFuncAttributeMaxDynamicSharedMemorySize,
                         attn_smem);

    prep_kernel<<<1, 256>>>((const unsigned char*)cmask, null_kv, k_scale);
    bias_gather<<<ROWS_, 256>>>(attn_bias);
    ln_kernel<<<ROWS_, 256>>>(x, gamma);
    gemm_qkv_tc<<<dim3(24, 32), 256>>>(Wq, Wkv, q_scale, k_scale);
    attn_tc2<<<BH_ * 16, 256, attn_smem>>>();
    gemm_out_tc<<<dim3(8, 32), 256>>>(Wout, out);
}

// round 11
// speedup vs baseline: 1.5479x; 1.0226x over previous
#include <cuda_runtime.h>
#include <math.h>
#include <float.h>

// Problem dims
#define B_   2
#define N_   2048
#define D_   1024
#define H_   16
#define DH_  64
#define C_   64
#define NK_  2049            // N+1 (null kv prepended)
#define VTS_ 2052            // Vt row stride (floats), 16B-aligned
#define BCS_ 2144            // compacted-bias row stride (floats), 16B-aligned
#define BH_  (B_*H_)         // 32
#define ROWS_ (B_*N_)        // 4096
#define LDBIAS_ (C_+N_)      // 2112

// Scratch (device globals: allocation-free rule)
__device__ float g_xn[ROWS_*D_];        // layernormed x (tf32-rounded)
__device__ float g_q [BH_*N_ *DH_];     // head-major q (l2normed+scaled, tf32)
__device__ float g_k [BH_*NK_*DH_];     // head-major COMPACTED k (row 0 = null, tf32)
__device__ float g_vt[BH_*DH_*VTS_];    // head-major COMPACTED v TRANSPOSED [bh][d][j], tf32
__device__ float g_ao[ROWS_*D_];        // attention output (tf32-rounded)
__device__ float g_biasc[(size_t)ROWS_*BCS_];  // compacted bias [b*N+i][r]
__device__ float g_wqkv[(size_t)D_*3072];      // [Wq|Wkv] fused, tf32-rounded
__device__ float g_wo[(size_t)D_*D_];          // Wout, tf32-rounded
__device__ int   g_mask_mode;           // 1 = 1-byte mask, 0 = 4-byte mask
__device__ int   g_cnt[2];              // compacted kv count per batch (incl null)
__device__ int   g_rank[2][2048];       // n -> compacted row (or -1)
__device__ int   g_jmap[2][2144];       // compacted row -> original j (0..2048), -1 pad

// ---------------------------------------------------------------------------
// tf32 / mma / ldmatrix helpers
// ---------------------------------------------------------------------------
__device__ __forceinline__ unsigned f2tf(float f) {
    unsigned u;
    asm("cvt.rna.tf32.f32 %0, %1;" : "=r"(u) : "f"(f));
    return u;
}
__device__ __forceinline__ float f2tff(float f) { return __uint_as_float(f2tf(f)); }

__device__ __forceinline__ void mma8(float* c, const unsigned* a, const unsigned* b) {
    asm volatile(
        "mma.sync.aligned.m16n8k8.row.col.f32.tf32.tf32.f32 "
        "{%0,%1,%2,%3}, {%4,%5,%6,%7}, {%8,%9}, {%0,%1,%2,%3};"
        : "+f"(c[0]), "+f"(c[1]), "+f"(c[2]), "+f"(c[3])
        : "r"(a[0]), "r"(a[1]), "r"(a[2]), "r"(a[3]), "r"(b[0]), "r"(b[1]));
}

__device__ __forceinline__ void ldmx4(unsigned& r0, unsigned& r1,
                                      unsigned& r2, unsigned& r3, unsigned addr) {
    asm volatile("ldmatrix.sync.aligned.m8n8.x4.shared.b16 {%0,%1,%2,%3}, [%4];"
                 : "=r"(r0), "=r"(r1), "=r"(r2), "=r"(r3) : "r"(addr));
}

__device__ __forceinline__ void cpa16(unsigned dst, const void* src, int ok) {
    asm volatile("cp.async.ca.shared.global [%0], [%1], 16, %2;"
                 :: "r"(dst), "l"(src), "r"(ok ? 16 : 0));
}
__device__ __forceinline__ void cpa_commit() {
    asm volatile("cp.async.commit_group;");
}
__device__ __forceinline__ void cpa_wait1() {
    asm volatile("cp.async.wait_group 1;");
}
__device__ __forceinline__ void cpa_wait2() {
    asm volatile("cp.async.wait_group 2;");
}

// ---------------------------------------------------------------------------
// prep: mask-mode detect, per-batch compaction scan, null-kv row 0.
// ---------------------------------------------------------------------------
__global__ void prep_kernel(const unsigned char* __restrict__ cm,
                            const float* __restrict__ null_kv,
                            const float* __restrict__ k_scale) {
    __shared__ int flag;
    __shared__ int thsum[256];
    __shared__ int pref[257];
    const int tid = threadIdx.x;
    const int wid = tid >> 5, lane = tid & 31;

    if (tid == 0) flag = 0;
    __syncthreads();
    int any = 0;
    for (int i = tid; i < 1024; i += 256)
        if (cm[4*i + 1] != 0) any = 1;
    if (any) atomicOr(&flag, 1);
    __syncthreads();
    const int mode = flag;
    if (tid == 0) g_mask_mode = mode;
    const unsigned* m32 = (const unsigned*)cm;

    for (int b = 0; b < 2; b++) {
        int f[8], ls = 0;
        #pragma unroll
        for (int k = 0; k < 8; k++) {
            const int n = tid*8 + k;
            f[k] = mode ? (cm[b*N_ + n] != 0) : (m32[b*N_ + n] != 0u);
            ls += f[k];
        }
        thsum[tid] = ls;
        __syncthreads();
        if (tid == 0) {
            int s = 0;
            for (int i = 0; i < 256; i++) { pref[i] = s; s += thsum[i]; }
            pref[256] = s;
        }
        __syncthreads();
        int r = 1 + pref[tid];       // compacted rows start at 1 (0 = null)
        #pragma unroll
        for (int k = 0; k < 8; k++) {
            const int n = tid*8 + k;
            if (f[k]) { g_rank[b][n] = r; g_jmap[b][r] = n + 1; r++; }
            else        g_rank[b][n] = -1;
        }
        const int cnt = 1 + pref[256];
        if (tid == 0) { g_cnt[b] = cnt; g_jmap[b][0] = 0; }
        for (int i = cnt + tid; i < 2144; i += 256) g_jmap[b][i] = -1;
        __syncthreads();
    }

    // null kv -> compacted row 0 for all (b, h)
    for (int h = wid; h < H_; h += 8) {
        const int d0 = lane, d1 = lane + 32;
        const float k0 = null_kv[h*DH_ + d0], k1 = null_kv[h*DH_ + d1];
        const float v0 = null_kv[H_*DH_ + h*DH_ + d0];
        const float v1 = null_kv[H_*DH_ + h*DH_ + d1];
        float ss = k0*k0 + k1*k1;
        #pragma unroll
        for (int o = 16; o > 0; o >>= 1) ss += __shfl_xor_sync(0xFFFFFFFFu, ss, o);
        const float inv = 1.0f / fmaxf(sqrtf(ss), 1e-12f);
        const float ks0 = k_scale[d0], ks1 = k_scale[d1];
        #pragma unroll
        for (int b = 0; b < 2; b++) {
            const int bh = b*H_ + h;
            float* kp = g_k  + (size_t)bh * NK_ * DH_;
            float* vp = g_vt + (size_t)bh * DH_ * VTS_;
            kp[d0] = f2tff(k0*inv*ks0); kp[d1] = f2tff(k1*inv*ks1);
            vp[(size_t)d0*VTS_] = f2tff(v0);
            vp[(size_t)d1*VTS_] = f2tff(v1);
        }
    }
}

// ---------------------------------------------------------------------------
// bias gather into compacted layout
// ---------------------------------------------------------------------------
__global__ void bias_gather(const float* __restrict__ attn_bias) {
    const int row = blockIdx.x;        // 0..4095
    const int b = row >> 11, i = row & 2047;
    const int* jm = g_jmap[b];
    const float* src = attn_bias + (size_t)(C_ + i)*LDBIAS_ + (C_ - 1);
    float* dst = g_biasc + (size_t)row * BCS_;
    for (int r = threadIdx.x; r < BCS_; r += 256) {
        const int off = jm[r];
        dst[r] = (off > 0) ? __ldg(src + off) : 0.f;
    }
}

// ---------------------------------------------------------------------------
// round weights to tf32: g_wqkv[k][n] = [Wq|Wkv], g_wo = Wout.
// grid = 4096 blocks x 256 thr, float4 per thread.
// ---------------------------------------------------------------------------
__global__ void round_w(const float* __restrict__ Wq,
                        const float* __restrict__ Wkv,
                        const float* __restrict__ Wout) {
    const size_t i = (size_t)blockIdx.x * 256 + threadIdx.x;   // float4 index
    if (i < 786432) {                 // wqkv: 1024 rows x 3072 cols / 4
        const int k = (int)(i / 768), rem = (int)(i % 768);
        const int n4 = rem * 4;
        float4 v;
        if (n4 < 1024) v = *(const float4*)(Wq  + (size_t)k*1024 + n4);
        else           v = *(const float4*)(Wkv + (size_t)k*2048 + (n4 - 1024));
        float4 o;
        o.x = f2tff(v.x); o.y = f2tff(v.y); o.z = f2tff(v.z); o.w = f2tff(v.w);
        *(float4*)(g_wqkv + i*4) = o;
    } else {                          // wo: 1024x1024/4 = 262144
        const size_t j = i - 786432;
        float4 v = *(const float4*)(Wout + j*4);
        float4 o;
        o.x = f2tff(v.x); o.y = f2tff(v.y); o.z = f2tff(v.z); o.w = f2tff(v.w);
        *(float4*)(g_wo + j*4) = o;
    }
}

// ---------------------------------------------------------------------------
// LayerNorm (writes tf32-rounded xn — identical numerics to staging-time cvt)
// ---------------------------------------------------------------------------
__global__ void ln_kernel(const float* __restrict__ x,
                          const float* __restrict__ gamma) {
    const int row = blockIdx.x;
    const int tid = threadIdx.x;
    const float4 a = ((const float4*)(x + (size_t)row * D_))[tid];
    float s  = a.x + a.y + a.z + a.w;
    float s2 = a.x*a.x + a.y*a.y + a.z*a.z + a.w*a.w;
    #pragma unroll
    for (int o = 16; o > 0; o >>= 1) {
        s  += __shfl_xor_sync(0xFFFFFFFFu, s,  o);
        s2 += __shfl_xor_sync(0xFFFFFFFFu, s2, o);
    }
    __shared__ float rs[8], rs2[8];
    if ((tid & 31) == 0) { rs[tid >> 5] = s; rs2[tid >> 5] = s2; }
    __syncthreads();
    float S = 0.f, S2 = 0.f;
    #pragma unroll
    for (int i = 0; i < 8; i++) { S += rs[i]; S2 += rs2[i]; }
    const float mu  = S * (1.0f / D_);
    const float var = S2 * (1.0f / D_) - mu * mu;
    const float inv = rsqrtf(var + 1e-5f);
    const float4 g = ((const float4*)gamma)[tid];
    float4 o;
    o.x = f2tff((a.x - mu) * inv * g.x);
    o.y = f2tff((a.y - mu) * inv * g.y);
    o.z = f2tff((a.z - mu) * inv * g.z);
    o.w = f2tff((a.w - mu) * inv * g.w);
    ((float4*)(g_xn + (size_t)row * D_))[tid] = o;
}

// ---------------------------------------------------------------------------
// tf32 GEMM v2: 128x128 tile, BK=16, 4-stage cp.async pipeline, 2 CTAs/SM.
// Operands pre-rounded tf32 in gmem -> staging is raw cp.async (no cvt).
// ---------------------------------------------------------------------------
#define AS_STR 20
#define BS_STR2 136
#define GS 4
#define AS_FL (128*AS_STR)     // 2560 floats per A stage
#define BS_FL (16*BS_STR2)     // 2176 floats per B stage
#define GEMM_SMEM ((GS*(AS_FL+BS_FL))*4)   // 75776 bytes

__device__ __forceinline__ void gemm_stage(
    unsigned as_u, unsigned bs_u, int s,
    const float* __restrict__ A, const float* __restrict__ Bp,
    int ldb, int bn, int bm, int k0)
{
    const int tid = threadIdx.x;
    #pragma unroll
    for (int i = 0; i < 2; i++) {
        const int idx = tid + i*256;
        const int r = idx >> 2, c4 = (idx & 3) * 4;
        cpa16(as_u + (unsigned)((s*AS_FL + r*AS_STR + c4)*4),
              A + (size_t)(bm + r)*1024 + k0 + c4, 1);
        const int k = idx >> 5, n4 = (idx & 31) * 4;
        cpa16(bs_u + (unsigned)((s*BS_FL + k*BS_STR2 + n4)*4),
              Bp + (size_t)(k0 + k)*ldb + bn + n4, 1);
    }
}

__device__ __forceinline__ void gemm_main_loop2(
    const float* __restrict__ A, const float* __restrict__ Bp,
    int ldb, int bn, int bm, float* smemf,
    int wm, int wn, int gid, int tig, float acc[2][8][4])
{
    const unsigned as_u = (unsigned)__cvta_generic_to_shared(smemf);
    const unsigned bs_u = as_u + (unsigned)(GS*AS_FL*4);
    const int lane = threadIdx.x & 31;
    const int mi = lane >> 3, mr = lane & 7;
    const unsigned a_off = (unsigned)((((mi & 1)*8 + mr)*AS_STR + (mi >> 1)*4) * 4);

    #pragma unroll
    for (int s = 0; s < GS-1; s++) {
        gemm_stage(as_u, bs_u, s, A, Bp, ldb, bn, bm, s*16);
        cpa_commit();
    }

    for (int kt = 0; kt < 64; kt++) {
        cpa_wait2();          // groups pending: kt..kt+2 -> group kt done
        __syncthreads();      // cross-thread visibility; all done with kt-1 compute
        if (kt + GS - 1 < 64)
            gemm_stage(as_u, bs_u, (kt + GS - 1) & 3, A, Bp, ldb, bn, bm, (kt + GS - 1)*16);
        cpa_commit();

        const int buf = kt & 3;
        const unsigned abuf = as_u + (unsigned)(buf*AS_FL*4) + a_off;
        const unsigned* bb = (const unsigned*)(smemf + GS*AS_FL + buf*BS_FL);

        #pragma unroll
        for (int kk = 0; kk < 2; kk++) {
            unsigned afr[2][4];
            #pragma unroll
            for (int mt = 0; mt < 2; mt++) {
                ldmx4(afr[mt][0], afr[mt][1], afr[mt][2], afr[mt][3],
                      abuf + (unsigned)(((wm*32 + mt*16)*AS_STR + kk*8) * 4));
            }
            unsigned bfr[8][2];
            #pragma unroll
            for (int nt = 0; nt < 8; nt++) {
                const int k = kk*8 + tig;
                const int n = wn*64 + nt*8 + gid;
                bfr[nt][0] = bb[(size_t)k*BS_STR2 + n];
                bfr[nt][1] = bb[(size_t)(k+4)*BS_STR2 + n];
            }
            #pragma unroll
            for (int mt = 0; mt < 2; mt++)
                #pragma unroll
                for (int nt = 0; nt < 8; nt++)
                    mma8(acc[mt][nt], afr[mt], bfr[nt]);
        }
    }
}

// ---------------------------------------------------------------------------
// QKV GEMM with FUSED l2norm/scale + compaction scatter (v transposed).
// ---------------------------------------------------------------------------
__global__ __launch_bounds__(256, 2)
void gemm_qkv_tc(const float* __restrict__ q_scale,
                 const float* __restrict__ k_scale) {
    extern __shared__ __align__(16) float gsm[];
    const int tid = threadIdx.x;
    const int wid = tid >> 5, lane = tid & 31;
    const int gid = lane >> 2, tig = lane & 3;
    const int wm = wid & 3, wn = wid >> 2;
    const int bm = blockIdx.y * 128, bn = blockIdx.x * 128;

    float acc[2][8][4] = {};
    gemm_main_loop2(g_xn, g_wqkv, 3072, bn, bm, gsm, wm, wn, gid, tig, acc);

    const int hv = (bn + wn*64) >> 6;   // 0..15 q, 16..31 k, 32..47 v

    #pragma unroll
    for (int mt = 0; mt < 2; mt++) {
        #pragma unroll
        for (int i = 0; i < 2; i++) {
            const int row = bm + wm*32 + mt*16 + gid + i*8;
            const int bidx = row >> 11, n = row & 2047;
            float ss = 0.f;
            #pragma unroll
            for (int nt = 0; nt < 8; nt++)
                ss += acc[mt][nt][i*2]*acc[mt][nt][i*2]
                    + acc[mt][nt][i*2+1]*acc[mt][nt][i*2+1];
            ss += __shfl_xor_sync(0xFFFFFFFFu, ss, 1);
            ss += __shfl_xor_sync(0xFFFFFFFFu, ss, 2);

            if (hv < 16) {
                const float inv = 1.0f / fmaxf(sqrtf(ss), 1e-12f);
                float* dst = g_q + (((size_t)(bidx*H_ + hv))*N_ + n)*DH_;
                #pragma unroll
                for (int nt = 0; nt < 8; nt++) {
                    const int d = nt*8 + 2*tig;
                    *(float2*)(dst + d) = make_float2(
                        f2tff(acc[mt][nt][i*2]   * inv * q_scale[d]),
                        f2tff(acc[mt][nt][i*2+1] * inv * q_scale[d+1]));
                }
            } else if (hv < 32) {
                const int r = g_rank[bidx][n];
                if (r >= 0) {
                    const float inv = 1.0f / fmaxf(sqrtf(ss), 1e-12f);
                    float* dst = g_k + (((size_t)(bidx*H_ + hv-16))*NK_ + r)*DH_;
                    #pragma unroll
                    for (int nt = 0; nt < 8; nt++) {
                        const int d = nt*8 + 2*tig;
                        *(float2*)(dst + d) = make_float2(
                            f2tff(acc[mt][nt][i*2]   * inv * k_scale[d]),
                            f2tff(acc[mt][nt][i*2+1] * inv * k_scale[d+1]));
                    }
                }
            } else {
                const int r = g_rank[bidx][n];
                if (r >= 0) {
                    float* dst = g_vt + ((size_t)(bidx*H_ + hv-32))*DH_*VTS_ + r;
                    #pragma unroll
                    for (int nt = 0; nt < 8; nt++) {
                        const int d = nt*8 + 2*tig;
                        dst[(size_t)d*VTS_]     = f2tff(acc[mt][nt][i*2]);
                        dst[(size_t)(d+1)*VTS_] = f2tff(acc[mt][nt][i*2+1]);
                    }
                }
            }
        }
    }
}

// Output GEMM: d_out(4096 x 1024) = g_ao @ g_wo
__global__ __launch_bounds__(256, 2)
void gemm_out_tc(float* __restrict__ out) {
    extern __shared__ __align__(16) float gsm[];
    const int tid = threadIdx.x;
    const int wid = tid >> 5, lane = tid & 31;
    const int gid = lane >> 2, tig = lane & 3;
    const int wm = wid & 3, wn = wid >> 2;
    const int bm = blockIdx.y * 128, bn = blockIdx.x * 128;

    float acc[2][8][4] = {};
    gemm_main_loop2(g_ao, g_wo, 1024, bn, bm, gsm, wm, wn, gid, tig, acc);

    #pragma unroll
    for (int mt = 0; mt < 2; mt++) {
        #pragma unroll
        for (int i = 0; i < 2; i++) {
            const int row = bm + wm*32 + mt*16 + gid + i*8;
            #pragma unroll
            for (int nt = 0; nt < 8; nt++) {
                const int col = bn + wn*64 + nt*8 + 2*tig;
                *(float2*)&out[(size_t)row*1024 + col] =
                    make_float2(acc[mt][nt][i*2], acc[mt][nt][i*2+1]);
            }
        }
    }
}

// ---------------------------------------------------------------------------
// tf32 flash attention (unchanged from Round 10)
// ---------------------------------------------------------------------------
#define KS_STR 68
#define VT_STR 68
#define PS_STR 68

__device__ __forceinline__ void attn_prefetch_tile(
    int t, int cnt, int cpr, int cpc,
    unsigned ks_s0, unsigned vt_s0,
    const float* __restrict__ kb, const float* __restrict__ vtb)
{
    const int jb = t * 64;
    const unsigned kdst = ks_s0 + (unsigned)((t & 1) * 4352 * 4);
    const unsigned vdst = vt_s0 + (unsigned)((t & 1) * 4352 * 4);
    #pragma unroll
    for (int i = 0; i < 4; i++) {
        const int r = cpr + i*16;
        const int okk = (jb + r) < cnt;
        const int okv = (jb + cpc) < cnt;
        cpa16(kdst + (unsigned)(r*KS_STR + cpc)*4, kb  + (size_t)(jb + r)*64 + cpc, okk);
        cpa16(vdst + (unsigned)(r*VT_STR + cpc)*4, vtb + (size_t)r*VTS_ + jb + cpc, okv);
    }
}

__global__ __launch_bounds__(256, 2)
void attn_tc2() {
    extern __shared__ __align__(16) float smf[];
    float* Ksf = smf;                       // 2 * 64*68
    float* Vtf = smf + 8704;                // 2 * 64*68
    float* Psf = smf + 17408;               // 8 * 16*68

    const int tid = threadIdx.x;
    const int wid = tid >> 5, lane = tid & 31;
    const int gid = lane >> 2, tig = lane & 3;
    const int qt = blockIdx.x & 15, bh = blockIdx.x >> 4;
    const int b = bh >> 4, h = bh & 15;
    const int i0 = qt * 128;

    const int cnt   = g_cnt[b];
    const int tiles = (cnt + 63) >> 6;

    const int mi = lane >> 3, mr = lane & 7;
    const unsigned kv_off = (unsigned)((((mi >> 1)*8 + mr)*KS_STR + (mi & 1)*4) * 4);
    const unsigned p_off  = (unsigned)((((mi & 1)*8 + mr)*PS_STR + (mi >> 1)*4) * 4);

    unsigned qa[8][4];
    {
        const float* qb = g_q + ((size_t)bh*N_ + i0 + wid*16)*DH_;
        #pragma unroll
        for (int ks = 0; ks < 8; ks++) {
            qa[ks][0] = __float_as_uint(qb[gid*64 + ks*8 + tig]);
            qa[ks][1] = __float_as_uint(qb[(gid+8)*64 + ks*8 + tig]);
            qa[ks][2] = __float_as_uint(qb[gid*64 + ks*8 + tig + 4]);
            qa[ks][3] = __float_as_uint(qb[(gid+8)*64 + ks*8 + tig + 4]);
        }
    }

    float O[8][4];
    #pragma unroll
    for (int nt = 0; nt < 8; nt++)
        #pragma unroll
        for (int i = 0; i < 4; i++) O[nt][i] = 0.f;
    float m0 = -FLT_MAX, m1 = -FLT_MAX, l0 = 0.f, l1 = 0.f;

    const float* kb  = g_k  + (size_t)bh * NK_ * DH_;
    const float* vtb = g_vt + (size_t)bh * DH_ * VTS_;
    const float* bcA = g_biasc + (size_t)(b*N_ + i0 + wid*16 + gid) * BCS_;
    const float* bcB = bcA + (size_t)8 * BCS_;
    float* pw = Psf + wid * (16 * PS_STR);

    const unsigned ks_s0 = (unsigned)__cvta_generic_to_shared(Ksf);
    const unsigned vt_s0 = (unsigned)__cvta_generic_to_shared(Vtf);
    const unsigned pw_s0 = (unsigned)__cvta_generic_to_shared(pw);
    const int cpr = tid >> 4, cpc = (tid & 15) * 4;

    attn_prefetch_tile(0, cnt, cpr, cpc, ks_s0, vt_s0, kb, vtb);
    cpa_commit();
    __syncthreads();

    for (int t = 0; t < tiles; t++) {
        const int buf = t & 1;
        const int jb = t * 64;
        if (t + 1 < tiles)
            attn_prefetch_tile(t + 1, cnt, cpr, cpc, ks_s0, vt_s0, kb, vtb);
        cpa_commit();

        cpa_wait1();
        __syncthreads();

        const unsigned kbase = ks_s0 + (unsigned)(buf * 4352 * 4) + kv_off;
        const unsigned vbase = vt_s0 + (unsigned)(buf * 4352 * 4) + kv_off;

        float sc[8][4];
        #pragma unroll
        for (int nt = 0; nt < 8; nt++)
            #pragma unroll
            for (int i = 0; i < 4; i++) sc[nt][i] = 0.f;
        #pragma unroll
        for (int ks = 0; ks < 8; ks++) {
            unsigned kf[8][2];
            #pragma unroll
            for (int np = 0; np < 4; np++)
                ldmx4(kf[2*np][0], kf[2*np][1], kf[2*np+1][0], kf[2*np+1][1],
                      kbase + (unsigned)(((2*np)*8*KS_STR + ks*8) * 4));
            #pragma unroll
            for (int nt = 0; nt < 8; nt++)
                mma8(sc[nt], qa[ks], kf[nt]);
        }

        float mx0 = -FLT_MAX, mx1 = -FLT_MAX;
        #pragma unroll
        for (int nt = 0; nt < 8; nt++) {
            const int c0 = jb + nt*8 + 2*tig;
            const bool v0 = c0 < cnt, v1 = (c0 + 1) < cnt;
            const float2 ba = *(const float2*)(bcA + c0);
            const float2 bb2 = *(const float2*)(bcB + c0);
            sc[nt][0] = v0 ? sc[nt][0]*8.f + ba.x  : -FLT_MAX;
            sc[nt][1] = v1 ? sc[nt][1]*8.f + ba.y  : -FLT_MAX;
            sc[nt][2] = v0 ? sc[nt][2]*8.f + bb2.x : -FLT_MAX;
            sc[nt][3] = v1 ? sc[nt][3]*8.f + bb2.y : -FLT_MAX;
            mx0 = fmaxf(mx0, fmaxf(sc[nt][0], sc[nt][1]));
            mx1 = fmaxf(mx1, fmaxf(sc[nt][2], sc[nt][3]));
        }
        mx0 = fmaxf(mx0, __shfl_xor_sync(0xFFFFFFFFu, mx0, 1));
        mx0 = fmaxf(mx0, __shfl_xor_sync(0xFFFFFFFFu, mx0, 2));
        mx1 = fmaxf(mx1, __shfl_xor_sync(0xFFFFFFFFu, mx1, 1));
        mx1 = fmaxf(mx1, __shfl_xor_sync(0xFFFFFFFFu, mx1, 2));
        const float mn0 = fmaxf(m0, mx0), mn1 = fmaxf(m1, mx1);
        const float f0 = __expf(m0 - mn0), f1 = __expf(m1 - mn1);
        float s0 = 0.f, s1 = 0.f;
        unsigned* pwu = (unsigned*)pw;
        #pragma unroll
        for (int nt = 0; nt < 8; nt++) {
            const float p0 = __expf(sc[nt][0] - mn0);
            const float p1 = __expf(sc[nt][1] - mn0);
            const float p2 = __expf(sc[nt][2] - mn1);
            const float p3 = __expf(sc[nt][3] - mn1);
            s0 += p0 + p1; s1 += p2 + p3;
            const int c0 = nt*8 + 2*tig;
            *(uint2*)(pwu + gid*PS_STR + c0)     = make_uint2(f2tf(p0), f2tf(p1));
            *(uint2*)(pwu + (gid+8)*PS_STR + c0) = make_uint2(f2tf(p2), f2tf(p3));
        }
        s0 += __shfl_xor_sync(0xFFFFFFFFu, s0, 1);
        s0 += __shfl_xor_sync(0xFFFFFFFFu, s0, 2);
        s1 += __shfl_xor_sync(0xFFFFFFFFu, s1, 1);
        s1 += __shfl_xor_sync(0xFFFFFFFFu, s1, 2);
        l0 = l0 * f0 + s0; l1 = l1 * f1 + s1;
        m0 = mn0; m1 = mn1;
        #pragma unroll
        for (int nt = 0; nt < 8; nt++) {
            O[nt][0] *= f0; O[nt][1] *= f0;
            O[nt][2] *= f1; O[nt][3] *= f1;
        }
        __syncwarp();

        #pragma unroll
        for (int ks = 0; ks < 8; ks++) {
            unsigned pa[4];
            ldmx4(pa[0], pa[1], pa[2], pa[3], pw_s0 + p_off + (unsigned)(ks*8*4));
            unsigned vf[8][2];
            #pragma unroll
            for (int np = 0; np < 4; np++)
                ldmx4(vf[2*np][0], vf[2*np][1], vf[2*np+1][0], vf[2*np+1][1],
                      vbase + (unsigned)(((2*np)*8*VT_STR + ks*8) * 4));
            #pragma unroll
            for (int nt = 0; nt < 8; nt++)
                mma8(O[nt], pa, vf[nt]);
        }
        __syncthreads();
    }

    const float inv0 = 1.f / l0, inv1 = 1.f / l1;
    float* ob = g_ao + ((size_t)b*N_ + i0 + wid*16)*1024 + h*64;
    #pragma unroll
    for (int nt = 0; nt < 8; nt++) {
        const int c0 = nt*8 + 2*tig;
        *(float2*)(ob + (size_t)gid*1024 + c0) =
            make_float2(f2tff(O[nt][0]*inv0), f2tff(O[nt][1]*inv0));
        *(float2*)(ob + (size_t)(gid+8)*1024 + c0) =
            make_float2(f2tff(O[nt][2]*inv1), f2tff(O[nt][3]*inv1));
    }
}

// ---------------------------------------------------------------------------
extern "C" void kernel_launch(void* const* d_in, const int* in_sizes, int n_in,
                              void* d_out, int out_size) {
    const float* x         = (const float*)d_in[0];
    const float* attn_bias = (const float*)d_in[1];
    const void*  cmask     = (const void*) d_in[2];
    const float* gamma     = (const float*)d_in[3];
    const float* null_kv   = (const float*)d_in[4];
    const float* Wq        = (const float*)d_in[5];
    const float* Wkv       = (const float*)d_in[6];
    const float* q_scale   = (const float*)d_in[7];
    const float* k_scale   = (const float*)d_in[8];
    const float* Wout      = (const float*)d_in[9];
    float* out = (float*)d_out;

    static const int attn_smem = 26112 * 4;   // 104448 B
    cudaFuncSetAttribute(attn_tc2,
                         cudaFuncAttributeMaxDynamicSharedMemorySize,
                         attn_smem);
    cudaFuncSetAttribute(gemm_qkv_tc,
                         cudaFuncAttributeMaxDynamicSharedMemorySize,
                         GEMM_SMEM);
    cudaFuncSetAttribute(gemm_out_tc,
                         cudaFuncAttributeMaxDynamicSharedMemorySize,
                         GEMM_SMEM);

    prep_kernel<<<1, 256>>>((const unsigned char*)cmask, null_kv, k_scale);
    bias_gather<<<ROWS_, 256>>>(attn_bias);
    round_w<<<4096, 256>>>(Wq, Wkv, Wout);
    ln_kernel<<<ROWS_, 256>>>(x, gamma);
    gemm_qkv_tc<<<dim3(24, 32), 256, GEMM_SMEM>>>(q_scale, k_scale);
    attn_tc2<<<BH_ * 16, 256, attn_smem>>>();
    gemm_out_tc<<<dim3(8, 32), 256, GEMM_SMEM>>>(out);
}

// round 13
// speedup vs baseline: 1.5929x; 1.0291x over previous
#include <cuda_runtime.h>
#include <math.h>
#include <float.h>

// Problem dims
#define B_   2
#define N_   2048
#define D_   1024
#define H_   16
#define DH_  64
#define C_   64
#define NK_  2049            // N+1 (null kv prepended)
#define VTS_ 2052            // Vt row stride (floats), 16B-aligned
#define BCS_ 2144            // compacted-bias row stride (floats), 16B-aligned
#define BH_  (B_*H_)         // 32
#define ROWS_ (B_*N_)        // 4096
#define LDBIAS_ (C_+N_)      // 2112

// Scratch (device globals: allocation-free rule)
__device__ float g_xn[ROWS_*D_];        // layernormed x (tf32-rounded)
__device__ float g_q [BH_*N_ *DH_];     // head-major q (l2normed+scaled, tf32)
__device__ float g_k [BH_*NK_*DH_];     // head-major COMPACTED k (row 0 = null, tf32)
__device__ float g_vt[BH_*DH_*VTS_];    // head-major COMPACTED v TRANSPOSED [bh][d][j], tf32
__device__ float g_ao[ROWS_*D_];        // attention output (tf32-rounded)
__device__ float g_biasc[(size_t)ROWS_*BCS_];  // compacted bias [b*N+i][r]
__device__ float g_wqkvt[(size_t)3072*D_];     // [Wq|Wkv]^T  [n][k], tf32-rounded
__device__ float g_wot[(size_t)D_*D_];         // Wout^T      [n][k], tf32-rounded
__device__ int   g_mask_mode;
__device__ int   g_cnt[2];              // compacted kv count per batch (incl null)
__device__ int   g_rank[2][2048];       // n -> compacted row (or -1)
__device__ int   g_jmap[2][2144];       // compacted row -> original j, -1 pad

// ---------------------------------------------------------------------------
// tf32 / mma / ldmatrix helpers
// ---------------------------------------------------------------------------
__device__ __forceinline__ unsigned f2tf(float f) {
    unsigned u;
    asm("cvt.rna.tf32.f32 %0, %1;" : "=r"(u) : "f"(f));
    return u;
}
__device__ __forceinline__ float f2tff(float f) { return __uint_as_float(f2tf(f)); }

__device__ __forceinline__ void mma8(float* c, const unsigned* a, const unsigned* b) {
    asm volatile(
        "mma.sync.aligned.m16n8k8.row.col.f32.tf32.tf32.f32 "
        "{%0,%1,%2,%3}, {%4,%5,%6,%7}, {%8,%9}, {%0,%1,%2,%3};"
        : "+f"(c[0]), "+f"(c[1]), "+f"(c[2]), "+f"(c[3])
        : "r"(a[0]), "r"(a[1]), "r"(a[2]), "r"(a[3]), "r"(b[0]), "r"(b[1]));
}

__device__ __forceinline__ void ldmx4(unsigned& r0, unsigned& r1,
                                      unsigned& r2, unsigned& r3, unsigned addr) {
    asm volatile("ldmatrix.sync.aligned.m8n8.x4.shared.b16 {%0,%1,%2,%3}, [%4];"
                 : "=r"(r0), "=r"(r1), "=r"(r2), "=r"(r3) : "r"(addr));
}

__device__ __forceinline__ void cpa16(unsigned dst, const void* src, int ok) {
    asm volatile("cp.async.ca.shared.global [%0], [%1], 16, %2;"
                 :: "r"(dst), "l"(src), "r"(ok ? 16 : 0));
}
__device__ __forceinline__ void cpa_commit() {
    asm volatile("cp.async.commit_group;");
}
__device__ __forceinline__ void cpa_wait1() {
    asm volatile("cp.async.wait_group 1;");
}
__device__ __forceinline__ void cpa_wait2() {
    asm volatile("cp.async.wait_group 2;");
}

// ---------------------------------------------------------------------------
// prep: mask-mode detect, per-batch compaction scan, null-kv row 0.
// ---------------------------------------------------------------------------
__global__ void prep_kernel(const unsigned char* __restrict__ cm,
                            const float* __restrict__ null_kv,
                            const float* __restrict__ k_scale) {
    __shared__ int flag;
    __shared__ int thsum[256];
    __shared__ int pref[257];
    const int tid = threadIdx.x;
    const int wid = tid >> 5, lane = tid & 31;

    if (tid == 0) flag = 0;
    __syncthreads();
    int any = 0;
    for (int i = tid; i < 1024; i += 256)
        if (cm[4*i + 1] != 0) any = 1;
    if (any) atomicOr(&flag, 1);
    __syncthreads();
    const int mode = flag;
    if (tid == 0) g_mask_mode = mode;
    const unsigned* m32 = (const unsigned*)cm;

    for (int b = 0; b < 2; b++) {
        int f[8], ls = 0;
        #pragma unroll
        for (int k = 0; k < 8; k++) {
            const int n = tid*8 + k;
            f[k] = mode ? (cm[b*N_ + n] != 0) : (m32[b*N_ + n] != 0u);
            ls += f[k];
        }
        thsum[tid] = ls;
        __syncthreads();
        if (tid == 0) {
            int s = 0;
            for (int i = 0; i < 256; i++) { pref[i] = s; s += thsum[i]; }
            pref[256] = s;
        }
        __syncthreads();
        int r = 1 + pref[tid];
        #pragma unroll
        for (int k = 0; k < 8; k++) {
            const int n = tid*8 + k;
            if (f[k]) { g_rank[b][n] = r; g_jmap[b][r] = n + 1; r++; }
            else        g_rank[b][n] = -1;
        }
        const int cnt = 1 + pref[256];
        if (tid == 0) { g_cnt[b] = cnt; g_jmap[b][0] = 0; }
        for (int i = cnt + tid; i < 2144; i += 256) g_jmap[b][i] = -1;
        __syncthreads();
    }

    for (int h = wid; h < H_; h += 8) {
        const int d0 = lane, d1 = lane + 32;
        const float k0 = null_kv[h*DH_ + d0], k1 = null_kv[h*DH_ + d1];
        const float v0 = null_kv[H_*DH_ + h*DH_ + d0];
        const float v1 = null_kv[H_*DH_ + h*DH_ + d1];
        float ss = k0*k0 + k1*k1;
        #pragma unroll
        for (int o = 16; o > 0; o >>= 1) ss += __shfl_xor_sync(0xFFFFFFFFu, ss, o);
        const float inv = 1.0f / fmaxf(sqrtf(ss), 1e-12f);
        const float ks0 = k_scale[d0], ks1 = k_scale[d1];
        #pragma unroll
        for (int b = 0; b < 2; b++) {
            const int bh = b*H_ + h;
            float* kp = g_k  + (size_t)bh * NK_ * DH_;
            float* vp = g_vt + (size_t)bh * DH_ * VTS_;
            kp[d0] = f2tff(k0*inv*ks0); kp[d1] = f2tff(k1*inv*ks1);
            vp[(size_t)d0*VTS_] = f2tff(v0);
            vp[(size_t)d1*VTS_] = f2tff(v1);
        }
    }
}

// ---------------------------------------------------------------------------
// bias gather into compacted layout
// ---------------------------------------------------------------------------
__global__ void bias_gather(const float* __restrict__ attn_bias) {
    const int row = blockIdx.x;
    const int b = row >> 11, i = row & 2047;
    const int* jm = g_jmap[b];
    const float* src = attn_bias + (size_t)(C_ + i)*LDBIAS_ + (C_ - 1);
    float* dst = g_biasc + (size_t)row * BCS_;
    for (int r = threadIdx.x; r < BCS_; r += 256) {
        const int off = jm[r];
        dst[r] = (off > 0) ? __ldg(src + off) : 0.f;
    }
}

// ---------------------------------------------------------------------------
// weight transpose + tf32 round (tiled 32x32, smem)
// g_wqkvt[n][k] = tf32([Wq|Wkv][k][n]);  g_wot[n][k] = tf32(Wout[k][n])
// ---------------------------------------------------------------------------
__global__ void round_wt_qkv(const float* __restrict__ Wq,
                             const float* __restrict__ Wkv) {
    __shared__ float t[32][33];
    const int k0 = blockIdx.x * 32, n0 = blockIdx.y * 32;
    const int tx = threadIdx.x, ty = threadIdx.y;   // 32 x 8
    #pragma unroll
    for (int i = 0; i < 32; i += 8) {
        const int k = k0 + ty + i, n = n0 + tx;
        t[ty + i][tx] = (n < 1024) ? Wq[(size_t)k*1024 + n]
                                   : Wkv[(size_t)k*2048 + n - 1024];
    }
    __syncthreads();
    #pragma unroll
    for (int i = 0; i < 32; i += 8) {
        const int n = n0 + ty + i, k = k0 + tx;
        g_wqkvt[(size_t)n*1024 + k] = f2tff(t[tx][ty + i]);
    }
}

__global__ void round_wt_o(const float* __restrict__ Wout) {
    __shared__ float t[32][33];
    const int k0 = blockIdx.x * 32, n0 = blockIdx.y * 32;
    const int tx = threadIdx.x, ty = threadIdx.y;
    #pragma unroll
    for (int i = 0; i < 32; i += 8)
        t[ty + i][tx] = Wout[(size_t)(k0 + ty + i)*1024 + n0 + tx];
    __syncthreads();
    #pragma unroll
    for (int i = 0; i < 32; i += 8)
        g_wot[(size_t)(n0 + ty + i)*1024 + k0 + tx] = f2tff(t[tx][ty + i]);
}

// ---------------------------------------------------------------------------
// LayerNorm (writes tf32-rounded xn)
// ---------------------------------------------------------------------------
__global__ void ln_kernel(const float* __restrict__ x,
                          const float* __restrict__ gamma) {
    const int row = blockIdx.x;
    const int tid = threadIdx.x;
    const float4 a = ((const float4*)(x + (size_t)row * D_))[tid];
    float s  = a.x + a.y + a.z + a.w;
    float s2 = a.x*a.x + a.y*a.y + a.z*a.z + a.w*a.w;
    #pragma unroll
    for (int o = 16; o > 0; o >>= 1) {
        s  += __shfl_xor_sync(0xFFFFFFFFu, s,  o);
        s2 += __shfl_xor_sync(0xFFFFFFFFu, s2, o);
    }
    __shared__ float rs[8], rs2[8];
    if ((tid & 31) == 0) { rs[tid >> 5] = s; rs2[tid >> 5] = s2; }
    __syncthreads();
    float S = 0.f, S2 = 0.f;
    #pragma unroll
    for (int i = 0; i < 8; i++) { S += rs[i]; S2 += rs2[i]; }
    const float mu  = S * (1.0f / D_);
    const float var = S2 * (1.0f / D_) - mu * mu;
    const float inv = rsqrtf(var + 1e-5f);
    const float4 g = ((const float4*)gamma)[tid];
    float4 o;
    o.x = f2tff((a.x - mu) * inv * g.x);
    o.y = f2tff((a.y - mu) * inv * g.y);
    o.z = f2tff((a.z - mu) * inv * g.z);
    o.w = f2tff((a.w - mu) * inv * g.w);
    ((float4*)(g_xn + (size_t)row * D_))[tid] = o;
}

// ---------------------------------------------------------------------------
// tf32 GEMM v3: both operands [row][k] stride-20, ldmatrix A AND B frags,
// 4-stage cp.async pipeline, 2 CTAs/SM.
// ---------------------------------------------------------------------------
#define TS_STR 20
#define TS_FL (128*TS_STR)            // 2560 floats per operand stage
#define GS 4
#define GEMM_SMEM ((GS*2*TS_FL)*4)    // 81920 bytes

__device__ __forceinline__ void gemm_stage(
    unsigned as_u, unsigned bs_u, int s,
    const float* __restrict__ A, const float* __restrict__ Bt,
    int bm, int bn, int k0)
{
    const int tid = threadIdx.x;
    #pragma unroll
    for (int i = 0; i < 2; i++) {
        const int idx = tid + i*256;
        const int r = idx >> 2, c4 = (idx & 3) * 4;
        const unsigned off = (unsigned)((s*TS_FL + r*TS_STR + c4) * 4);
        cpa16(as_u + off, A  + (size_t)(bm + r)*1024 + k0 + c4, 1);
        cpa16(bs_u + off, Bt + (size_t)(bn + r)*1024 + k0 + c4, 1);
    }
}

__device__ __forceinline__ void gemm_main_loop3(
    const float* __restrict__ A, const float* __restrict__ Bt,
    int bm, int bn, float* smemf,
    int wm, int wn, float acc[2][8][4])
{
    const unsigned as_u = (unsigned)__cvta_generic_to_shared(smemf);
    const unsigned bs_u = as_u + (unsigned)(GS*TS_FL*4);
    const int lane = threadIdx.x & 31;
    const int mi = lane >> 3, mr = lane & 7;
    // A-frag map: m0 rows0-7 col+0, m1 rows8-15 col+0, m2 rows0-7 col+4, m3 rows8-15 col+4
    const unsigned a_off = (unsigned)((((mi & 1)*8 + mr)*TS_STR + (mi >> 1)*4) * 4);
    // B-frag map (as attention K): m0 rows0-7 col+0, m1 rows0-7 col+4, m2 rows8-15 col+0, m3 rows8-15 col+4
    const unsigned b_off = (unsigned)((((mi >> 1)*8 + mr)*TS_STR + (mi & 1)*4) * 4);

    #pragma unroll
    for (int s = 0; s < GS-1; s++) {
        gemm_stage(as_u, bs_u, s, A, Bt, bm, bn, s*16);
        cpa_commit();
    }

    for (int kt = 0; kt < 64; kt++) {
        cpa_wait2();
        __syncthreads();
        if (kt + GS - 1 < 64)
            gemm_stage(as_u, bs_u, (kt + GS - 1) & 3, A, Bt, bm, bn, (kt + GS - 1)*16);
        cpa_commit();

        const int buf = kt & 3;
        const unsigned abuf = as_u + (unsigned)(buf*TS_FL*4) + a_off;
        const unsigned bbuf = bs_u + (unsigned)(buf*TS_FL*4) + b_off;

        #pragma unroll
        for (int kk = 0; kk < 2; kk++) {
            unsigned afr[2][4];
            #pragma unroll
            for (int mt = 0; mt < 2; mt++)
                ldmx4(afr[mt][0], afr[mt][1], afr[mt][2], afr[mt][3],
                      abuf + (unsigned)(((wm*32 + mt*16)*TS_STR + kk*8) * 4));
            unsigned bfr[8][2];
            #pragma unroll
            for (int np = 0; np < 4; np++)
                ldmx4(bfr[2*np][0], bfr[2*np][1], bfr[2*np+1][0], bfr[2*np+1][1],
                      bbuf + (unsigned)(((wn*64 + np*16)*TS_STR + kk*8) * 4));
            #pragma unroll
            for (int mt = 0; mt < 2; mt++)
                #pragma unroll
                for (int nt = 0; nt < 8; nt++)
                    mma8(acc[mt][nt], afr[mt], bfr[nt]);
        }
    }
}

// ---------------------------------------------------------------------------
// QKV GEMM with FUSED l2norm/scale + compaction scatter (v transposed).
// ---------------------------------------------------------------------------
__global__ __launch_bounds__(256, 2)
void gemm_qkv_tc(const float* __restrict__ q_scale,
                 const float* __restrict__ k_scale) {
    extern __shared__ __align__(16) float gsm[];
    const int tid = threadIdx.x;
    const int wid = tid >> 5, lane = tid & 31;
    const int gid = lane >> 2, tig = lane & 3;
    const int wm = wid & 3, wn = wid >> 2;
    const int bm = blockIdx.y * 128, bn = blockIdx.x * 128;

    float acc[2][8][4] = {};
    gemm_main_loop3(g_xn, g_wqkvt, bm, bn, gsm, wm, wn, acc);

    const int hv = (bn + wn*64) >> 6;   // 0..15 q, 16..31 k, 32..47 v

    #pragma unroll
    for (int mt = 0; mt < 2; mt++) {
        #pragma unroll
        for (int i = 0; i < 2; i++) {
            const int row = bm + wm*32 + mt*16 + gid + i*8;
            const int bidx = row >> 11, n = row & 2047;
            float ss = 0.f;
            #pragma unroll
            for (int nt = 0; nt < 8; nt++)
                ss += acc[mt][nt][i*2]*acc[mt][nt][i*2]
                    + acc[mt][nt][i*2+1]*acc[mt][nt][i*2+1];
            ss += __shfl_xor_sync(0xFFFFFFFFu, ss, 1);
            ss += __shfl_xor_sync(0xFFFFFFFFu, ss, 2);

            if (hv < 16) {
                const float inv = 1.0f / fmaxf(sqrtf(ss), 1e-12f);
                float* dst = g_q + (((size_t)(bidx*H_ + hv))*N_ + n)*DH_;
                #pragma unroll
                for (int nt = 0; nt < 8; nt++) {
                    const int d = nt*8 + 2*tig;
                    *(float2*)(dst + d) = make_float2(
                        f2tff(acc[mt][nt][i*2]   * inv * q_scale[d]),
                        f2tff(acc[mt][nt][i*2+1] * inv * q_scale[d+1]));
                }
            } else if (hv < 32) {
                const int r = g_rank[bidx][n];
                if (r >= 0) {
                    const float inv = 1.0f / fmaxf(sqrtf(ss), 1e-12f);
                    float* dst = g_k + (((size_t)(bidx*H_ + hv-16))*NK_ + r)*DH_;
                    #pragma unroll
                    for (int nt = 0; nt < 8; nt++) {
                        const int d = nt*8 + 2*tig;
                        *(float2*)(dst + d) = make_float2(
                            f2tff(acc[mt][nt][i*2]   * inv * k_scale[d]),
                            f2tff(acc[mt][nt][i*2+1] * inv * k_scale[d+1]));
                    }
                }
            } else {
                const int r = g_rank[bidx][n];
                if (r >= 0) {
                    float* dst = g_vt + ((size_t)(bidx*H_ + hv-32))*DH_*VTS_ + r;
                    #pragma unroll
                    for (int nt = 0; nt < 8; nt++) {
                        const int d = nt*8 + 2*tig;
                        dst[(size_t)d*VTS_]     = f2tff(acc[mt][nt][i*2]);
                        dst[(size_t)(d+1)*VTS_] = f2tff(acc[mt][nt][i*2+1]);
                    }
                }
            }
        }
    }
}

// Output GEMM: d_out(4096 x 1024) = g_ao @ Wout  (Bt = g_wot)
__global__ __launch_bounds__(256, 2)
void gemm_out_tc(float* __restrict__ out) {
    extern __shared__ __align__(16) float gsm[];
    const int tid = threadIdx.x;
    const int wid = tid >> 5, lane = tid & 31;
    const int gid = lane >> 2, tig = lane & 3;
    const int wm = wid & 3, wn = wid >> 2;
    const int bm = blockIdx.y * 128, bn = blockIdx.x * 128;

    float acc[2][8][4] = {};
    gemm_main_loop3(g_ao, g_wot, bm, bn, gsm, wm, wn, acc);

    #pragma unroll
    for (int mt = 0; mt < 2; mt++) {
        #pragma unroll
        for (int i = 0; i < 2; i++) {
            const int row = bm + wm*32 + mt*16 + gid + i*8;
            #pragma unroll
            for (int nt = 0; nt < 8; nt++) {
                const int col = bn + wn*64 + nt*8 + 2*tig;
                *(float2*)&out[(size_t)row*1024 + col] =
                    make_float2(acc[mt][nt][i*2], acc[mt][nt][i*2+1]);
            }
        }
    }
}

// ---------------------------------------------------------------------------
// tf32 flash attention (unchanged from Round 10/11)
// ---------------------------------------------------------------------------
#define KS_STR 68
#define VT_STR 68
#define PS_STR 68

__device__ __forceinline__ void attn_prefetch_tile(
    int t, int cnt, int cpr, int cpc,
    unsigned ks_s0, unsigned vt_s0,
    const float* __restrict__ kb, const float* __restrict__ vtb)
{
    const int jb = t * 64;
    const unsigned kdst = ks_s0 + (unsigned)((t & 1) * 4352 * 4);
    const unsigned vdst = vt_s0 + (unsigned)((t & 1) * 4352 * 4);
    #pragma unroll
    for (int i = 0; i < 4; i++) {
        const int r = cpr + i*16;
        const int okk = (jb + r) < cnt;
        const int okv = (jb + cpc) < cnt;
        cpa16(kdst + (unsigned)(r*KS_STR + cpc)*4, kb  + (size_t)(jb + r)*64 + cpc, okk);
        cpa16(vdst + (unsigned)(r*VT_STR + cpc)*4, vtb + (size_t)r*VTS_ + jb + cpc, okv);
    }
}

__global__ __launch_bounds__(256, 2)
void attn_tc2() {
    extern __shared__ __align__(16) float smf[];
    float* Ksf = smf;
    float* Vtf = smf + 8704;
    float* Psf = smf + 17408;

    const int tid = threadIdx.x;
    const int wid = tid >> 5, lane = tid & 31;
    const int gid = lane >> 2, tig = lane & 3;
    const int qt = blockIdx.x & 15, bh = blockIdx.x >> 4;
    const int b = bh >> 4, h = bh & 15;
    const int i0 = qt * 128;

    const int cnt   = g_cnt[b];
    const int tiles = (cnt + 63) >> 6;

    const int mi = lane >> 3, mr = lane & 7;
    const unsigned kv_off = (unsigned)((((mi >> 1)*8 + mr)*KS_STR + (mi & 1)*4) * 4);
    const unsigned p_off  = (unsigned)((((mi & 1)*8 + mr)*PS_STR + (mi >> 1)*4) * 4);

    unsigned qa[8][4];
    {
        const float* qb = g_q + ((size_t)bh*N_ + i0 + wid*16)*DH_;
        #pragma unroll
        for (int ks = 0; ks < 8; ks++) {
            qa[ks][0] = __float_as_uint(qb[gid*64 + ks*8 + tig]);
            qa[ks][1] = __float_as_uint(qb[(gid+8)*64 + ks*8 + tig]);
            qa[ks][2] = __float_as_uint(qb[gid*64 + ks*8 + tig + 4]);
            qa[ks][3] = __float_as_uint(qb[(gid+8)*64 + ks*8 + tig + 4]);
        }
    }

    float O[8][4];
    #pragma unroll
    for (int nt = 0; nt < 8; nt++)
        #pragma unroll
        for (int i = 0; i < 4; i++) O[nt][i] = 0.f;
    float m0 = -FLT_MAX, m1 = -FLT_MAX, l0 = 0.f, l1 = 0.f;

    const float* kb  = g_k  + (size_t)bh * NK_ * DH_;
    const float* vtb = g_vt + (size_t)bh * DH_ * VTS_;
    const float* bcA = g_biasc + (size_t)(b*N_ + i0 + wid*16 + gid) * BCS_;
    const float* bcB = bcA + (size_t)8 * BCS_;
    float* pw = Psf + wid * (16 * PS_STR);

    const unsigned ks_s0 = (unsigned)__cvta_generic_to_shared(Ksf);
    const unsigned vt_s0 = (unsigned)__cvta_generic_to_shared(Vtf);
    const unsigned pw_s0 = (unsigned)__cvta_generic_to_shared(pw);
    const int cpr = tid >> 4, cpc = (tid & 15) * 4;

    attn_prefetch_tile(0, cnt, cpr, cpc, ks_s0, vt_s0, kb, vtb);
    cpa_commit();
    __syncthreads();

    for (int t = 0; t < tiles; t++) {
        const int buf = t & 1;
        const int jb = t * 64;
        if (t + 1 < tiles)
            attn_prefetch_tile(t + 1, cnt, cpr, cpc, ks_s0, vt_s0, kb, vtb);
        cpa_commit();

        cpa_wait1();
        __syncthreads();

        const unsigned kbase = ks_s0 + (unsigned)(buf * 4352 * 4) + kv_off;
        const unsigned vbase = vt_s0 + (unsigned)(buf * 4352 * 4) + kv_off;

        float sc[8][4];
        #pragma unroll
        for (int nt = 0; nt < 8; nt++)
            #pragma unroll
            for (int i = 0; i < 4; i++) sc[nt][i] = 0.f;
        #pragma unroll
        for (int ks = 0; ks < 8; ks++) {
            unsigned kf[8][2];
            #pragma unroll
            for (int np = 0; np < 4; np++)
                ldmx4(kf[2*np][0], kf[2*np][1], kf[2*np+1][0], kf[2*np+1][1],
                      kbase + (unsigned)(((2*np)*8*KS_STR + ks*8) * 4));
            #pragma unroll
            for (int nt = 0; nt < 8; nt++)
                mma8(sc[nt], qa[ks], kf[nt]);
        }

        float mx0 = -FLT_MAX, mx1 = -FLT_MAX;
        #pragma unroll
        for (int nt = 0; nt < 8; nt++) {
            const int c0 = jb + nt*8 + 2*tig;
            const bool v0 = c0 < cnt, v1 = (c0 + 1) < cnt;
            const float2 ba = *(const float2*)(bcA + c0);
            const float2 bb2 = *(const float2*)(bcB + c0);
            sc[nt][0] = v0 ? sc[nt][0]*8.f + ba.x  : -FLT_MAX;
            sc[nt][1] = v1 ? sc[nt][1]*8.f + ba.y  : -FLT_MAX;
            sc[nt][2] = v0 ? sc[nt][2]*8.f + bb2.x : -FLT_MAX;
            sc[nt][3] = v1 ? sc[nt][3]*8.f + bb2.y : -FLT_MAX;
            mx0 = fmaxf(mx0, fmaxf(sc[nt][0], sc[nt][1]));
            mx1 = fmaxf(mx1, fmaxf(sc[nt][2], sc[nt][3]));
        }
        mx0 = fmaxf(mx0, __shfl_xor_sync(0xFFFFFFFFu, mx0, 1));
        mx0 = fmaxf(mx0, __shfl_xor_sync(0xFFFFFFFFu, mx0, 2));
        mx1 = fmaxf(mx1, __shfl_xor_sync(0xFFFFFFFFu, mx1, 1));
        mx1 = fmaxf(mx1, __shfl_xor_sync(0xFFFFFFFFu, mx1, 2));
        const float mn0 = fmaxf(m0, mx0), mn1 = fmaxf(m1, mx1);
        const float f0 = __expf(m0 - mn0), f1 = __expf(m1 - mn1);
        float s0 = 0.f, s1 = 0.f;
        unsigned* pwu = (unsigned*)pw;
        #pragma unroll
        for (int nt = 0; nt < 8; nt++) {
            const float p0 = __expf(sc[nt][0] - mn0);
            const float p1 = __expf(sc[nt][1] - mn0);
            const float p2 = __expf(sc[nt][2] - mn1);
            const float p3 = __expf(sc[nt][3] - mn1);
            s0 += p0 + p1; s1 += p2 + p3;
            const int c0 = nt*8 + 2*tig;
            *(uint2*)(pwu + gid*PS_STR + c0)     = make_uint2(f2tf(p0), f2tf(p1));
            *(uint2*)(pwu + (gid+8)*PS_STR + c0) = make_uint2(f2tf(p2), f2tf(p3));
        }
        s0 += __shfl_xor_sync(0xFFFFFFFFu, s0, 1);
        s0 += __shfl_xor_sync(0xFFFFFFFFu, s0, 2);
        s1 += __shfl_xor_sync(0xFFFFFFFFu, s1, 1);
        s1 += __shfl_xor_sync(0xFFFFFFFFu, s1, 2);
        l0 = l0 * f0 + s0; l1 = l1 * f1 + s1;
        m0 = mn0; m1 = mn1;
        #pragma unroll
        for (int nt = 0; nt < 8; nt++) {
            O[nt][0] *= f0; O[nt][1] *= f0;
            O[nt][2] *= f1; O[nt][3] *= f1;
        }
        __syncwarp();

        #pragma unroll
        for (int ks = 0; ks < 8; ks++) {
            unsigned pa[4];
            ldmx4(pa[0], pa[1], pa[2], pa[3], pw_s0 + p_off + (unsigned)(ks*8*4));
            unsigned vf[8][2];
            #pragma unroll
            for (int np = 0; np < 4; np++)
                ldmx4(vf[2*np][0], vf[2*np][1], vf[2*np+1][0], vf[2*np+1][1],
                      vbase + (unsigned)(((2*np)*8*VT_STR + ks*8) * 4));
            #pragma unroll
            for (int nt = 0; nt < 8; nt++)
                mma8(O[nt], pa, vf[nt]);
        }
        __syncthreads();
    }

    const float inv0 = 1.f / l0, inv1 = 1.f / l1;
    float* ob = g_ao + ((size_t)b*N_ + i0 + wid*16)*1024 + h*64;
    #pragma unroll
    for (int nt = 0; nt < 8; nt++) {
        const int c0 = nt*8 + 2*tig;
        *(float2*)(ob + (size_t)gid*1024 + c0) =
            make_float2(f2tff(O[nt][0]*inv0), f2tff(O[nt][1]*inv0));
        *(float2*)(ob + (size_t)(gid+8)*1024 + c0) =
            make_float2(f2tff(O[nt][2]*inv1), f2tff(O[nt][3]*inv1));
    }
}

// ---------------------------------------------------------------------------
extern "C" void kernel_launch(void* const* d_in, const int* in_sizes, int n_in,
                              void* d_out, int out_size) {
    const float* x         = (const float*)d_in[0];
    const float* attn_bias = (const float*)d_in[1];
    const void*  cmask     = (const void*) d_in[2];
    const float* gamma     = (const float*)d_in[3];
    const float* null_kv   = (const float*)d_in[4];
    const float* Wq        = (const float*)d_in[5];
    const float* Wkv       = (const float*)d_in[6];
    const float* q_scale   = (const float*)d_in[7];
    const float* k_scale   = (const float*)d_in[8];
    const float* Wout      = (const float*)d_in[9];
    float* out = (float*)d_out;

    static const int attn_smem = 26112 * 4;   // 104448 B
    cudaFuncSetAttribute(attn_tc2,
                         cudaFuncAttributeMaxDynamicSharedMemorySize,
                         attn_smem);
    cudaFuncSetAttribute(gemm_qkv_tc,
                         cudaFuncAttributeMaxDynamicSharedMemorySize,
                         GEMM_SMEM);
    cudaFuncSetAttribute(gemm_out_tc,
                         cudaFuncAttributeMaxDynamicSharedMemorySize,
                         GEMM_SMEM);

    prep_kernel<<<1, 256>>>((const unsigned char*)cmask, null_kv, k_scale);
    bias_gather<<<ROWS_, 256>>>(attn_bias);
    round_wt_qkv<<<dim3(32, 96), dim3(32, 8)>>>(Wq, Wkv);
    round_wt_o<<<dim3(32, 32), dim3(32, 8)>>>(Wout);
    ln_kernel<<<ROWS_, 256>>>(x, gamma);
    gemm_qkv_tc<<<dim3(24, 32), 256, GEMM_SMEM>>>(q_scale, k_scale);
    attn_tc2<<<BH_ * 16, 256, attn_smem>>>();
    gemm_out_tc<<<dim3(8, 32), 256, GEMM_SMEM>>>(out);
}

// round 14
// speedup vs baseline: 1.7900x; 1.1238x over previous
#include <cuda_runtime.h>
#include <math.h>
#include <float.h>

// Problem dims
#define B_   2
#define N_   2048
#define D_   1024
#define H_   16
#define DH_  64
#define C_   64
#define NK_  2049            // N+1 (null kv prepended)
#define VTS_ 2052            // Vt row stride (floats), 16B-aligned
#define BCS_ 2144            // compacted-bias row stride (floats), 16B-aligned
#define BH_  (B_*H_)         // 32
#define ROWS_ (B_*N_)        // 4096
#define LDBIAS_ (C_+N_)      // 2112

// Scratch (device globals: allocation-free rule)
__device__ float g_xn [ROWS_*D_];       // layernormed x (tf32-rounded)
__device__ float g_xnc[(size_t)B_*2048*D_]; // COMPACTED xn rows per batch
__device__ float g_q [BH_*N_ *DH_];     // head-major q (l2normed+scaled, tf32)
__device__ float g_k [BH_*NK_*DH_];     // head-major COMPACTED k (row 0 = null, tf32)
__device__ float g_vt[BH_*DH_*VTS_];    // head-major COMPACTED v TRANSPOSED [bh][d][j], tf32
__device__ float g_ao[ROWS_*D_];        // attention output (tf32-rounded)
__device__ float g_biasc[(size_t)ROWS_*BCS_];  // compacted bias [b*N+i][r]
__device__ float g_wqkvt[(size_t)3072*D_];     // [Wq|Wkv]^T  [n][k], tf32-rounded
__device__ float g_wot[(size_t)D_*D_];         // Wout^T      [n][k], tf32-rounded
__device__ int   g_mask_mode;
__device__ int   g_cnt[2];              // compacted kv count per batch (incl null)
__device__ int   g_rank[2][2048];       // n -> compacted row (or -1)
__device__ int   g_jmap[2][2144];       // compacted row -> original j, -1 pad

// ---------------------------------------------------------------------------
// tf32 / mma / ldmatrix helpers
// ---------------------------------------------------------------------------
__device__ __forceinline__ unsigned f2tf(float f) {
    unsigned u;
    asm("cvt.rna.tf32.f32 %0, %1;" : "=r"(u) : "f"(f));
    return u;
}
__device__ __forceinline__ float f2tff(float f) { return __uint_as_float(f2tf(f)); }

__device__ __forceinline__ void mma8(float* c, const unsigned* a, const unsigned* b) {
    asm volatile(
        "mma.sync.aligned.m16n8k8.row.col.f32.tf32.tf32.f32 "
        "{%0,%1,%2,%3}, {%4,%5,%6,%7}, {%8,%9}, {%0,%1,%2,%3};"
        : "+f"(c[0]), "+f"(c[1]), "+f"(c[2]), "+f"(c[3])
        : "r"(a[0]), "r"(a[1]), "r"(a[2]), "r"(a[3]), "r"(b[0]), "r"(b[1]));
}

__device__ __forceinline__ void ldmx4(unsigned& r0, unsigned& r1,
                                      unsigned& r2, unsigned& r3, unsigned addr) {
    asm volatile("ldmatrix.sync.aligned.m8n8.x4.shared.b16 {%0,%1,%2,%3}, [%4];"
                 : "=r"(r0), "=r"(r1), "=r"(r2), "=r"(r3) : "r"(addr));
}

__device__ __forceinline__ void cpa16(unsigned dst, const void* src, int ok) {
    asm volatile("cp.async.ca.shared.global [%0], [%1], 16, %2;"
                 :: "r"(dst), "l"(src), "r"(ok ? 16 : 0));
}
__device__ __forceinline__ void cpa_commit() {
    asm volatile("cp.async.commit_group;");
}
__device__ __forceinline__ void cpa_wait1() {
    asm volatile("cp.async.wait_group 1;");
}
__device__ __forceinline__ void cpa_wait2() {
    asm volatile("cp.async.wait_group 2;");
}

// ---------------------------------------------------------------------------
// prep: mask-mode detect, per-batch compaction scan, null-kv row 0.
// ---------------------------------------------------------------------------
__global__ void prep_kernel(const unsigned char* __restrict__ cm,
                            const float* __restrict__ null_kv,
                            const float* __restrict__ k_scale) {
    __shared__ int flag;
    __shared__ int thsum[256];
    __shared__ int pref[257];
    const int tid = threadIdx.x;
    const int wid = tid >> 5, lane = tid & 31;

    if (tid == 0) flag = 0;
    __syncthreads();
    int any = 0;
    for (int i = tid; i < 1024; i += 256)
        if (cm[4*i + 1] != 0) any = 1;
    if (any) atomicOr(&flag, 1);
    __syncthreads();
    const int mode = flag;
    if (tid == 0) g_mask_mode = mode;
    const unsigned* m32 = (const unsigned*)cm;

    for (int b = 0; b < 2; b++) {
        int f[8], ls = 0;
        #pragma unroll
        for (int k = 0; k < 8; k++) {
            const int n = tid*8 + k;
            f[k] = mode ? (cm[b*N_ + n] != 0) : (m32[b*N_ + n] != 0u);
            ls += f[k];
        }
        thsum[tid] = ls;
        __syncthreads();
        if (tid == 0) {
            int s = 0;
            for (int i = 0; i < 256; i++) { pref[i] = s; s += thsum[i]; }
            pref[256] = s;
        }
        __syncthreads();
        int r = 1 + pref[tid];
        #pragma unroll
        for (int k = 0; k < 8; k++) {
            const int n = tid*8 + k;
            if (f[k]) { g_rank[b][n] = r; g_jmap[b][r] = n + 1; r++; }
            else        g_rank[b][n] = -1;
        }
        const int cnt = 1 + pref[256];
        if (tid == 0) { g_cnt[b] = cnt; g_jmap[b][0] = 0; }
        for (int i = cnt + tid; i < 2144; i += 256) g_jmap[b][i] = -1;
        __syncthreads();
    }

    for (int h = wid; h < H_; h += 8) {
        const int d0 = lane, d1 = lane + 32;
        const float k0 = null_kv[h*DH_ + d0], k1 = null_kv[h*DH_ + d1];
        const float v0 = null_kv[H_*DH_ + h*DH_ + d0];
        const float v1 = null_kv[H_*DH_ + h*DH_ + d1];
        float ss = k0*k0 + k1*k1;
        #pragma unroll
        for (int o = 16; o > 0; o >>= 1) ss += __shfl_xor_sync(0xFFFFFFFFu, ss, o);
        const float inv = 1.0f / fmaxf(sqrtf(ss), 1e-12f);
        const float ks0 = k_scale[d0], ks1 = k_scale[d1];
        #pragma unroll
        for (int b = 0; b < 2; b++) {
            const int bh = b*H_ + h;
            float* kp = g_k  + (size_t)bh * NK_ * DH_;
            float* vp = g_vt + (size_t)bh * DH_ * VTS_;
            kp[d0] = f2tff(k0*inv*ks0); kp[d1] = f2tff(k1*inv*ks1);
            vp[(size_t)d0*VTS_] = f2tff(v0);
            vp[(size_t)d1*VTS_] = f2tff(v1);
        }
    }
}

// ---------------------------------------------------------------------------
// bias gather into compacted layout
// ---------------------------------------------------------------------------
__global__ void bias_gather(const float* __restrict__ attn_bias) {
    const int row = blockIdx.x;
    const int b = row >> 11, i = row & 2047;
    const int* jm = g_jmap[b];
    const float* src = attn_bias + (size_t)(C_ + i)*LDBIAS_ + (C_ - 1);
    float* dst = g_biasc + (size_t)row * BCS_;
    for (int r = threadIdx.x; r < BCS_; r += 256) {
        const int off = jm[r];
        dst[r] = (off > 0) ? __ldg(src + off) : 0.f;
    }
}

// ---------------------------------------------------------------------------
// weight transpose + tf32 round (tiled 32x32, smem)
// ---------------------------------------------------------------------------
__global__ void round_wt_qkv(const float* __restrict__ Wq,
                             const float* __restrict__ Wkv) {
    __shared__ float t[32][33];
    const int k0 = blockIdx.x * 32, n0 = blockIdx.y * 32;
    const int tx = threadIdx.x, ty = threadIdx.y;   // 32 x 8
    #pragma unroll
    for (int i = 0; i < 32; i += 8) {
        const int k = k0 + ty + i, n = n0 + tx;
        t[ty + i][tx] = (n < 1024) ? Wq[(size_t)k*1024 + n]
                                   : Wkv[(size_t)k*2048 + n - 1024];
    }
    __syncthreads();
    #pragma unroll
    for (int i = 0; i < 32; i += 8) {
        const int n = n0 + ty + i, k = k0 + tx;
        g_wqkvt[(size_t)n*1024 + k] = f2tff(t[tx][ty + i]);
    }
}

__global__ void round_wt_o(const float* __restrict__ Wout) {
    __shared__ float t[32][33];
    const int k0 = blockIdx.x * 32, n0 = blockIdx.y * 32;
    const int tx = threadIdx.x, ty = threadIdx.y;
    #pragma unroll
    for (int i = 0; i < 32; i += 8)
        t[ty + i][tx] = Wout[(size_t)(k0 + ty + i)*1024 + n0 + tx];
    __syncthreads();
    #pragma unroll
    for (int i = 0; i < 32; i += 8)
        g_wot[(size_t)(n0 + ty + i)*1024 + k0 + tx] = f2tff(t[tx][ty + i]);
}

// ---------------------------------------------------------------------------
// LayerNorm (writes tf32-rounded xn; also compacted copy for valid kv rows)
// ---------------------------------------------------------------------------
__global__ void ln_kernel(const float* __restrict__ x,
                          const float* __restrict__ gamma) {
    const int row = blockIdx.x;
    const int tid = threadIdx.x;
    const float4 a = ((const float4*)(x + (size_t)row * D_))[tid];
    float s  = a.x + a.y + a.z + a.w;
    float s2 = a.x*a.x + a.y*a.y + a.z*a.z + a.w*a.w;
    #pragma unroll
    for (int o = 16; o > 0; o >>= 1) {
        s  += __shfl_xor_sync(0xFFFFFFFFu, s,  o);
        s2 += __shfl_xor_sync(0xFFFFFFFFu, s2, o);
    }
    __shared__ float rs[8], rs2[8];
    if ((tid & 31) == 0) { rs[tid >> 5] = s; rs2[tid >> 5] = s2; }
    __syncthreads();
    float S = 0.f, S2 = 0.f;
    #pragma unroll
    for (int i = 0; i < 8; i++) { S += rs[i]; S2 += rs2[i]; }
    const float mu  = S * (1.0f / D_);
    const float var = S2 * (1.0f / D_) - mu * mu;
    const float inv = rsqrtf(var + 1e-5f);
    const float4 g = ((const float4*)gamma)[tid];
    float4 o;
    o.x = f2tff((a.x - mu) * inv * g.x);
    o.y = f2tff((a.y - mu) * inv * g.y);
    o.z = f2tff((a.z - mu) * inv * g.z);
    o.w = f2tff((a.w - mu) * inv * g.w);
    ((float4*)(g_xn + (size_t)row * D_))[tid] = o;

    // compacted copy for valid kv rows
    const int b = row >> 11, n = row & 2047;
    const int r = g_rank[b][n];
    if (r >= 1)
        ((float4*)(g_xnc + ((size_t)b*2048 + (r-1)) * D_))[tid] = o;
}

// ---------------------------------------------------------------------------
// tf32 GEMM v3: both operands [row][k] stride-20, ldmatrix A AND B frags,
// 4-stage cp.async pipeline, 2 CTAs/SM.
// ---------------------------------------------------------------------------
#define TS_STR 20
#define TS_FL (128*TS_STR)            // 2560 floats per operand stage
#define GS 4
#define GEMM_SMEM ((GS*2*TS_FL)*4)    // 81920 bytes

__device__ __forceinline__ void gemm_stage(
    unsigned as_u, unsigned bs_u, int s,
    const float* __restrict__ A, const float* __restrict__ Bt,
    int bm, int bn, int k0)
{
    const int tid = threadIdx.x;
    #pragma unroll
    for (int i = 0; i < 2; i++) {
        const int idx = tid + i*256;
        const int r = idx >> 2, c4 = (idx & 3) * 4;
        const unsigned off = (unsigned)((s*TS_FL + r*TS_STR + c4) * 4);
        cpa16(as_u + off, A  + (size_t)(bm + r)*1024 + k0 + c4, 1);
        cpa16(bs_u + off, Bt + (size_t)(bn + r)*1024 + k0 + c4, 1);
    }
}

__device__ __forceinline__ void gemm_main_loop3(
    const float* __restrict__ A, const float* __restrict__ Bt,
    int bm, int bn, float* smemf,
    int wm, int wn, float acc[2][8][4])
{
    const unsigned as_u = (unsigned)__cvta_generic_to_shared(smemf);
    const unsigned bs_u = as_u + (unsigned)(GS*TS_FL*4);
    const int lane = threadIdx.x & 31;
    const int mi = lane >> 3, mr = lane & 7;
    const unsigned a_off = (unsigned)((((mi & 1)*8 + mr)*TS_STR + (mi >> 1)*4) * 4);
    const unsigned b_off = (unsigned)((((mi >> 1)*8 + mr)*TS_STR + (mi & 1)*4) * 4);

    #pragma unroll
    for (int s = 0; s < GS-1; s++) {
        gemm_stage(as_u, bs_u, s, A, Bt, bm, bn, s*16);
        cpa_commit();
    }

    for (int kt = 0; kt < 64; kt++) {
        cpa_wait2();
        __syncthreads();
        if (kt + GS - 1 < 64)
            gemm_stage(as_u, bs_u, (kt + GS - 1) & 3, A, Bt, bm, bn, (kt + GS - 1)*16);
        cpa_commit();

        const int buf = kt & 3;
        const unsigned abuf = as_u + (unsigned)(buf*TS_FL*4) + a_off;
        const unsigned bbuf = bs_u + (unsigned)(buf*TS_FL*4) + b_off;

        #pragma unroll
        for (int kk = 0; kk < 2; kk++) {
            unsigned afr[2][4];
            #pragma unroll
            for (int mt = 0; mt < 2; mt++)
                ldmx4(afr[mt][0], afr[mt][1], afr[mt][2], afr[mt][3],
                      abuf + (unsigned)(((wm*32 + mt*16)*TS_STR + kk*8) * 4));
            unsigned bfr[8][2];
            #pragma unroll
            for (int np = 0; np < 4; np++)
                ldmx4(bfr[2*np][0], bfr[2*np][1], bfr[2*np+1][0], bfr[2*np+1][1],
                      bbuf + (unsigned)(((wn*64 + np*16)*TS_STR + kk*8) * 4));
            #pragma unroll
            for (int mt = 0; mt < 2; mt++)
                #pragma unroll
                for (int nt = 0; nt < 8; nt++)
                    mma8(acc[mt][nt], afr[mt], bfr[nt]);
        }
    }
}

// ---------------------------------------------------------------------------
// Q GEMM: 4096 x 1024 (q cols only), fused l2norm + q_scale.
// ---------------------------------------------------------------------------
__global__ __launch_bounds__(256, 2)
void gemm_q_tc(const float* __restrict__ q_scale) {
    extern __shared__ __align__(16) float gsm[];
    const int tid = threadIdx.x;
    const int wid = tid >> 5, lane = tid & 31;
    const int gid = lane >> 2, tig = lane & 3;
    const int wm = wid & 3, wn = wid >> 2;
    const int bm = blockIdx.y * 128, bn = blockIdx.x * 128;

    float acc[2][8][4] = {};
    gemm_main_loop3(g_xn, g_wqkvt, bm, bn, gsm, wm, wn, acc);

    const int hv = (bn + wn*64) >> 6;   // 0..15
    #pragma unroll
    for (int mt = 0; mt < 2; mt++) {
        #pragma unroll
        for (int i = 0; i < 2; i++) {
            const int row = bm + wm*32 + mt*16 + gid + i*8;
            const int bidx = row >> 11, n = row & 2047;
            float ss = 0.f;
            #pragma unroll
            for (int nt = 0; nt < 8; nt++)
                ss += acc[mt][nt][i*2]*acc[mt][nt][i*2]
                    + acc[mt][nt][i*2+1]*acc[mt][nt][i*2+1];
            ss += __shfl_xor_sync(0xFFFFFFFFu, ss, 1);
            ss += __shfl_xor_sync(0xFFFFFFFFu, ss, 2);
            const float inv = 1.0f / fmaxf(sqrtf(ss), 1e-12f);
            float* dst = g_q + (((size_t)(bidx*H_ + hv))*N_ + n)*DH_;
            #pragma unroll
            for (int nt = 0; nt < 8; nt++) {
                const int d = nt*8 + 2*tig;
                *(float2*)(dst + d) = make_float2(
                    f2tff(acc[mt][nt][i*2]   * inv * q_scale[d]),
                    f2tff(acc[mt][nt][i*2+1] * inv * q_scale[d+1]));
            }
        }
    }
}

// ---------------------------------------------------------------------------
// KV GEMM over COMPACTED rows: M = cnt-1 per batch (z = batch), 2048 cols.
// Epilogue writes directly at compacted slot r = rr+1 (k l2norm / vt).
// ---------------------------------------------------------------------------
__global__ __launch_bounds__(256, 2)
void gemm_kv_tc(const float* __restrict__ k_scale) {
    const int bidx = blockIdx.z;
    const int cntm = g_cnt[bidx] - 1;       // valid rows
    const int bm = blockIdx.y * 128;
    if (bm >= cntm) return;
    const int bn = blockIdx.x * 128;        // within 2048 kv cols

    extern __shared__ __align__(16) float gsm[];
    const int tid = threadIdx.x;
    const int wid = tid >> 5, lane = tid & 31;
    const int gid = lane >> 2, tig = lane & 3;
    const int wm = wid & 3, wn = wid >> 2;

    const float* A  = g_xnc + (size_t)bidx * 2048 * D_;
    const float* Bt = g_wqkvt + (size_t)1024 * D_;   // kv weight rows

    float acc[2][8][4] = {};
    gemm_main_loop3(A, Bt, bm, bn, gsm, wm, wn, acc);

    const int hv = (bn + wn*64) >> 6;   // 0..15 k, 16..31 v
    #pragma unroll
    for (int mt = 0; mt < 2; mt++) {
        #pragma unroll
        for (int i = 0; i < 2; i++) {
            const int rr = bm + wm*32 + mt*16 + gid + i*8;
            if (rr >= cntm) continue;
            const int r = rr + 1;           // compacted slot
            float ss = 0.f;
            #pragma unroll
            for (int nt = 0; nt < 8; nt++)
                ss += acc[mt][nt][i*2]*acc[mt][nt][i*2]
                    + acc[mt][nt][i*2+1]*acc[mt][nt][i*2+1];
            ss += __shfl_xor_sync(0xFFFFFFFFu, ss, 1);
            ss += __shfl_xor_sync(0xFFFFFFFFu, ss, 2);

            if (hv < 16) {
                const float inv = 1.0f / fmaxf(sqrtf(ss), 1e-12f);
                float* dst = g_k + (((size_t)(bidx*H_ + hv))*NK_ + r)*DH_;
                #pragma unroll
                for (int nt = 0; nt < 8; nt++) {
                    const int d = nt*8 + 2*tig;
                    *(float2*)(dst + d) = make_float2(
                        f2tff(acc[mt][nt][i*2]   * inv * k_scale[d]),
                        f2tff(acc[mt][nt][i*2+1] * inv * k_scale[d+1]));
                }
            } else {
                float* dst = g_vt + ((size_t)(bidx*H_ + hv-16))*DH_*VTS_ + r;
                #pragma unroll
                for (int nt = 0; nt < 8; nt++) {
                    const int d = nt*8 + 2*tig;
                    dst[(size_t)d*VTS_]     = f2tff(acc[mt][nt][i*2]);
                    dst[(size_t)(d+1)*VTS_] = f2tff(acc[mt][nt][i*2+1]);
                }
            }
        }
    }
}

// Output GEMM: d_out(4096 x 1024) = g_ao @ Wout  (Bt = g_wot)
__global__ __launch_bounds__(256, 2)
void gemm_out_tc(float* __restrict__ out) {
    extern __shared__ __align__(16) float gsm[];
    const int tid = threadIdx.x;
    const int wid = tid >> 5, lane = tid & 31;
    const int gid = lane >> 2, tig = lane & 3;
    const int wm = wid & 3, wn = wid >> 2;
    const int bm = blockIdx.y * 128, bn = blockIdx.x * 128;

    float acc[2][8][4] = {};
    gemm_main_loop3(g_ao, g_wot, bm, bn, gsm, wm, wn, acc);

    #pragma unroll
    for (int mt = 0; mt < 2; mt++) {
        #pragma unroll
        for (int i = 0; i < 2; i++) {
            const int row = bm + wm*32 + mt*16 + gid + i*8;
            #pragma unroll
            for (int nt = 0; nt < 8; nt++) {
                const int col = bn + wn*64 + nt*8 + 2*tig;
                *(float2*)&out[(size_t)row*1024 + col] =
                    make_float2(acc[mt][nt][i*2], acc[mt][nt][i*2+1]);
            }
        }
    }
}

// ---------------------------------------------------------------------------
// tf32 flash attention (unchanged)
// ---------------------------------------------------------------------------
#define KS_STR 68
#define VT_STR 68
#define PS_STR 68

__device__ __forceinline__ void attn_prefetch_tile(
    int t, int cnt, int cpr, int cpc,
    unsigned ks_s0, unsigned vt_s0,
    const float* __restrict__ kb, const float* __restrict__ vtb)
{
    const int jb = t * 64;
    const unsigned kdst = ks_s0 + (unsigned)((t & 1) * 4352 * 4);
    const unsigned vdst = vt_s0 + (unsigned)((t & 1) * 4352 * 4);
    #pragma unroll
    for (int i = 0; i < 4; i++) {
        const int r = cpr + i*16;
        const int okk = (jb + r) < cnt;
        const int okv = (jb + cpc) < cnt;
        cpa16(kdst + (unsigned)(r*KS_STR + cpc)*4, kb  + (size_t)(jb + r)*64 + cpc, okk);
        cpa16(vdst + (unsigned)(r*VT_STR + cpc)*4, vtb + (size_t)r*VTS_ + jb + cpc, okv);
    }
}

__global__ __launch_bounds__(256, 2)
void attn_tc2() {
    extern __shared__ __align__(16) float smf[];
    float* Ksf = smf;
    float* Vtf = smf + 8704;
    float* Psf = smf + 17408;

    const int tid = threadIdx.x;
    const int wid = tid >> 5, lane = tid & 31;
    const int gid = lane >> 2, tig = lane & 3;
    const int qt = blockIdx.x & 15, bh = blockIdx.x >> 4;
    const int b = bh >> 4, h = bh & 15;
    const int i0 = qt * 128;

    const int cnt   = g_cnt[b];
    const int tiles = (cnt + 63) >> 6;

    const int mi = lane >> 3, mr = lane & 7;
    const unsigned kv_off = (unsigned)((((mi >> 1)*8 + mr)*KS_STR + (mi & 1)*4) * 4);
    const unsigned p_off  = (unsigned)((((mi & 1)*8 + mr)*PS_STR + (mi >> 1)*4) * 4);

    unsigned qa[8][4];
    {
        const float* qb = g_q + ((size_t)bh*N_ + i0 + wid*16)*DH_;
        #pragma unroll
        for (int ks = 0; ks < 8; ks++) {
            qa[ks][0] = __float_as_uint(qb[gid*64 + ks*8 + tig]);
            qa[ks][1] = __float_as_uint(qb[(gid+8)*64 + ks*8 + tig]);
            qa[ks][2] = __float_as_uint(qb[gid*64 + ks*8 + tig + 4]);
            qa[ks][3] = __float_as_uint(qb[(gid+8)*64 + ks*8 + tig + 4]);
        }
    }

    float O[8][4];
    #pragma unroll
    for (int nt = 0; nt < 8; nt++)
        #pragma unroll
        for (int i = 0; i < 4; i++) O[nt][i] = 0.f;
    float m0 = -FLT_MAX, m1 = -FLT_MAX, l0 = 0.f, l1 = 0.f;

    const float* kb  = g_k  + (size_t)bh * NK_ * DH_;
    const float* vtb = g_vt + (size_t)bh * DH_ * VTS_;
    const float* bcA = g_biasc + (size_t)(b*N_ + i0 + wid*16 + gid) * BCS_;
    const float* bcB = bcA + (size_t)8 * BCS_;
    float* pw = Psf + wid * (16 * PS_STR);

    const unsigned ks_s0 = (unsigned)__cvta_generic_to_shared(Ksf);
    const unsigned vt_s0 = (unsigned)__cvta_generic_to_shared(Vtf);
    const unsigned pw_s0 = (unsigned)__cvta_generic_to_shared(pw);
    const int cpr = tid >> 4, cpc = (tid & 15) * 4;

    attn_prefetch_tile(0, cnt, cpr, cpc, ks_s0, vt_s0, kb, vtb);
    cpa_commit();
    __syncthreads();

    for (int t = 0; t < tiles; t++) {
        const int buf = t & 1;
        const int jb = t * 64;
        if (t + 1 < tiles)
            attn_prefetch_tile(t + 1, cnt, cpr, cpc, ks_s0, vt_s0, kb, vtb);
        cpa_commit();

        cpa_wait1();
        __syncthreads();

        const unsigned kbase = ks_s0 + (unsigned)(buf * 4352 * 4) + kv_off;
        const unsigned vbase = vt_s0 + (unsigned)(buf * 4352 * 4) + kv_off;

        float sc[8][4];
        #pragma unroll
        for (int nt = 0; nt < 8; nt++)
            #pragma unroll
            for (int i = 0; i < 4; i++) sc[nt][i] = 0.f;
        #pragma unroll
        for (int ks = 0; ks < 8; ks++) {
            unsigned kf[8][2];
            #pragma unroll
            for (int np = 0; np < 4; np++)
                ldmx4(kf[2*np][0], kf[2*np][1], kf[2*np+1][0], kf[2*np+1][1],
                      kbase + (unsigned)(((2*np)*8*KS_STR + ks*8) * 4));
            #pragma unroll
            for (int nt = 0; nt < 8; nt++)
                mma8(sc[nt], qa[ks], kf[nt]);
        }

        float mx0 = -FLT_MAX, mx1 = -FLT_MAX;
        #pragma unroll
        for (int nt = 0; nt < 8; nt++) {
            const int c0 = jb + nt*8 + 2*tig;
            const bool v0 = c0 < cnt, v1 = (c0 + 1) < cnt;
            const float2 ba = *(const float2*)(bcA + c0);
            const float2 bb2 = *(const float2*)(bcB + c0);
            sc[nt][0] = v0 ? sc[nt][0]*8.f + ba.x  : -FLT_MAX;
            sc[nt][1] = v1 ? sc[nt][1]*8.f + ba.y  : -FLT_MAX;
            sc[nt][2] = v0 ? sc[nt][2]*8.f + bb2.x : -FLT_MAX;
            sc[nt][3] = v1 ? sc[nt][3]*8.f + bb2.y : -FLT_MAX;
            mx0 = fmaxf(mx0, fmaxf(sc[nt][0], sc[nt][1]));
            mx1 = fmaxf(mx1, fmaxf(sc[nt][2], sc[nt][3]));
        }
        mx0 = fmaxf(mx0, __shfl_xor_sync(0xFFFFFFFFu, mx0, 1));
        mx0 = fmaxf(mx0, __shfl_xor_sync(0xFFFFFFFFu, mx0, 2));
        mx1 = fmaxf(mx1, __shfl_xor_sync(0xFFFFFFFFu, mx1, 1));
        mx1 = fmaxf(mx1, __shfl_xor_sync(0xFFFFFFFFu, mx1, 2));
        const float mn0 = fmaxf(m0, mx0), mn1 = fmaxf(m1, mx1);
        const float f0 = __expf(m0 - mn0), f1 = __expf(m1 - mn1);
        float s0 = 0.f, s1 = 0.f;
        unsigned* pwu = (unsigned*)pw;
        #pragma unroll
        for (int nt = 0; nt < 8; nt++) {
            const float p0 = __expf(sc[nt][0] - mn0);
            const float p1 = __expf(sc[nt][1] - mn0);
            const float p2 = __expf(sc[nt][2] - mn1);
            const float p3 = __expf(sc[nt][3] - mn1);
            s0 += p0 + p1; s1 += p2 + p3;
            const int c0 = nt*8 + 2*tig;
            *(uint2*)(pwu + gid*PS_STR + c0)     = make_uint2(f2tf(p0), f2tf(p1));
            *(uint2*)(pwu + (gid+8)*PS_STR + c0) = make_uint2(f2tf(p2), f2tf(p3));
        }
        s0 += __shfl_xor_sync(0xFFFFFFFFu, s0, 1);
        s0 += __shfl_xor_sync(0xFFFFFFFFu, s0, 2);
        s1 += __shfl_xor_sync(0xFFFFFFFFu, s1, 1);
        s1 += __shfl_xor_sync(0xFFFFFFFFu, s1, 2);
        l0 = l0 * f0 + s0; l1 = l1 * f1 + s1;
        m0 = mn0; m1 = mn1;
        #pragma unroll
        for (int nt = 0; nt < 8; nt++) {
            O[nt][0] *= f0; O[nt][1] *= f0;
            O[nt][2] *= f1; O[nt][3] *= f1;
        }
        __syncwarp();

        #pragma unroll
        for (int ks = 0; ks < 8; ks++) {
            unsigned pa[4];
            ldmx4(pa[0], pa[1], pa[2], pa[3], pw_s0 + p_off + (unsigned)(ks*8*4));
            unsigned vf[8][2];
            #pragma unroll
            for (int np = 0; np < 4; np++)
                ldmx4(vf[2*np][0], vf[2*np][1], vf[2*np+1][0], vf[2*np+1][1],
                      vbase + (unsigned)(((2*np)*8*VT_STR + ks*8) * 4));
            #pragma unroll
            for (int nt = 0; nt < 8; nt++)
                mma8(O[nt], pa, vf[nt]);
        }
        __syncthreads();
    }

    const float inv0 = 1.f / l0, inv1 = 1.f / l1;
    float* ob = g_ao + ((size_t)b*N_ + i0 + wid*16)*1024 + h*64;
    #pragma unroll
    for (int nt = 0; nt < 8; nt++) {
        const int c0 = nt*8 + 2*tig;
        *(float2*)(ob + (size_t)gid*1024 + c0) =
            make_float2(f2tff(O[nt][0]*inv0), f2tff(O[nt][1]*inv0));
        *(float2*)(ob + (size_t)(gid+8)*1024 + c0) =
            make_float2(f2tff(O[nt][2]*inv1), f2tff(O[nt][3]*inv1));
    }
}

// ---------------------------------------------------------------------------
extern "C" void kernel_launch(void* const* d_in, const int* in_sizes, int n_in,
                              void* d_out, int out_size) {
    const float* x         = (const float*)d_in[0];
    const float* attn_bias = (const float*)d_in[1];
    const void*  cmask     = (const void*) d_in[2];
    const float* gamma     = (const float*)d_in[3];
    const float* null_kv   = (const float*)d_in[4];
    const float* Wq        = (const float*)d_in[5];
    const float* Wkv       = (const float*)d_in[6];
    const float* q_scale   = (const float*)d_in[7];
    const float* k_scale   = (const float*)d_in[8];
    const float* Wout      = (const float*)d_in[9];
    float* out = (float*)d_out;

    static const int attn_smem = 26112 * 4;   // 104448 B
    cudaFuncSetAttribute(attn_tc2,
                         cudaFuncAttributeMaxDynamicSharedMemorySize,
                         attn_smem);
    cudaFuncSetAttribute(gemm_q_tc,
                         cudaFuncAttributeMaxDynamicSharedMemorySize,
                         GEMM_SMEM);
    cudaFuncSetAttribute(gemm_kv_tc,
                         cudaFuncAttributeMaxDynamicSharedMemorySize,
                         GEMM_SMEM);
    cudaFuncSetAttribute(gemm_out_tc,
                         cudaFuncAttributeMaxDynamicSharedMemorySize,
                         GEMM_SMEM);

    prep_kernel<<<1, 256>>>((const unsigned char*)cmask, null_kv, k_scale);
    bias_gather<<<ROWS_, 256>>>(attn_bias);
    round_wt_qkv<<<dim3(32, 96), dim3(32, 8)>>>(Wq, Wkv);
    round_wt_o<<<dim3(32, 32), dim3(32, 8)>>>(Wout);
    ln_kernel<<<ROWS_, 256>>>(x, gamma);
    gemm_q_tc<<<dim3(8, 32), 256, GEMM_SMEM>>>(q_scale);
    gemm_kv_tc<<<dim3(16, 16, 2), 256, GEMM_SMEM>>>(k_scale);
    attn_tc2<<<BH_ * 16, 256, attn_smem>>>();
    gemm_out_tc<<<dim3(8, 32), 256, GEMM_SMEM>>>(out);
}

// round 17
// speedup vs baseline: 1.7976x; 1.0042x over previous
#include <cuda_runtime.h>
#include <math.h>
#include <float.h>

// Problem dims
#define B_   2
#define N_   2048
#define D_   1024
#define H_   16
#define DH_  64
#define C_   64
#define NK_  2049            // N+1 (null kv prepended)
#define VTS_ 2052            // Vt row stride (floats), 16B-aligned
#define BCS_ 2144            // compacted-bias row stride (floats), 16B-aligned
#define BH_  (B_*H_)         // 32
#define ROWS_ (B_*N_)        // 4096
#define LDBIAS_ (C_+N_)      // 2112

// Scratch (device globals: allocation-free rule)
__device__ float g_xn [ROWS_*D_];       // layernormed x (tf32-rounded)
__device__ float g_xnc[(size_t)B_*2048*D_]; // COMPACTED xn rows per batch
__device__ float g_q [BH_*N_ *DH_];     // head-major q (l2normed, *8*q_scale, tf32)
__device__ float g_k [BH_*NK_*DH_];     // head-major COMPACTED k (row 0 = null, tf32)
__device__ float g_vt[BH_*DH_*VTS_];    // head-major COMPACTED v TRANSPOSED [bh][d][j], tf32
__device__ float g_ao[ROWS_*D_];        // attention output (tf32-rounded)
__device__ float g_biasc[(size_t)ROWS_*BCS_];  // compacted bias [b*N+i][r]
__device__ float g_wqkvt[(size_t)3072*D_];     // [Wq|Wkv]^T  [n][k], tf32-rounded
__device__ float g_wot[(size_t)D_*D_];         // Wout^T      [n][k], tf32-rounded
__device__ int   g_mask_mode;
__device__ int   g_cnt[2];              // compacted kv count per batch (incl null)
__device__ int   g_rank[2][2048];       // n -> compacted row (or -1)
__device__ int   g_jmap[2][2144];       // compacted row -> original j, -1 pad

// ---------------------------------------------------------------------------
// tf32 / mma / ldmatrix helpers
// ---------------------------------------------------------------------------
__device__ __forceinline__ unsigned f2tf(float f) {
    unsigned u;
    asm("cvt.rna.tf32.f32 %0, %1;" : "=r"(u) : "f"(f));
    return u;
}
__device__ __forceinline__ float f2tff(float f) { return __uint_as_float(f2tf(f)); }

__device__ __forceinline__ void mma8(float* c, const unsigned* a, const unsigned* b) {
    asm volatile(
        "mma.sync.aligned.m16n8k8.row.col.f32.tf32.tf32.f32 "
        "{%0,%1,%2,%3}, {%4,%5,%6,%7}, {%8,%9}, {%0,%1,%2,%3};"
        : "+f"(c[0]), "+f"(c[1]), "+f"(c[2]), "+f"(c[3])
        : "r"(a[0]), "r"(a[1]), "r"(a[2]), "r"(a[3]), "r"(b[0]), "r"(b[1]));
}

__device__ __forceinline__ void ldmx4(unsigned& r0, unsigned& r1,
                                      unsigned& r2, unsigned& r3, unsigned addr) {
    asm volatile("ldmatrix.sync.aligned.m8n8.x4.shared.b16 {%0,%1,%2,%3}, [%4];"
                 : "=r"(r0), "=r"(r1), "=r"(r2), "=r"(r3) : "r"(addr));
}

__device__ __forceinline__ void cpa16(unsigned dst, const void* src, int ok) {
    asm volatile("cp.async.ca.shared.global [%0], [%1], 16, %2;"
                 :: "r"(dst), "l"(src), "r"(ok ? 16 : 0));
}
__device__ __forceinline__ void cpa_commit() {
    asm volatile("cp.async.commit_group;");
}
__device__ __forceinline__ void cpa_wait1() {
    asm volatile("cp.async.wait_group 1;");
}
__device__ __forceinline__ void cpa_wait2() {
    asm volatile("cp.async.wait_group 2;");
}

// ---------------------------------------------------------------------------
// prep: mask-mode detect, per-batch compaction scan, null-kv row 0.
// ---------------------------------------------------------------------------
__global__ void prep_kernel(const unsigned char* __restrict__ cm,
                            const float* __restrict__ null_kv,
                            const float* __restrict__ k_scale) {
    __shared__ int flag;
    __shared__ int thsum[256];
    __shared__ int pref[257];
    const int tid = threadIdx.x;
    const int wid = tid >> 5, lane = tid & 31;

    if (tid == 0) flag = 0;
    __syncthreads();
    int any = 0;
    for (int i = tid; i < 1024; i += 256)
        if (cm[4*i + 1] != 0) any = 1;
    if (any) atomicOr(&flag, 1);
    __syncthreads();
    const int mode = flag;
    if (tid == 0) g_mask_mode = mode;
    const unsigned* m32 = (const unsigned*)cm;

    for (int b = 0; b < 2; b++) {
        int f[8], ls = 0;
        #pragma unroll
        for (int k = 0; k < 8; k++) {
            const int n = tid*8 + k;
            f[k] = mode ? (cm[b*N_ + n] != 0) : (m32[b*N_ + n] != 0u);
            ls += f[k];
        }
        thsum[tid] = ls;
        __syncthreads();
        if (tid == 0) {
            int s = 0;
            for (int i = 0; i < 256; i++) { pref[i] = s; s += thsum[i]; }
            pref[256] = s;
        }
        __syncthreads();
        int r = 1 + pref[tid];
        #pragma unroll
        for (int k = 0; k < 8; k++) {
            const int n = tid*8 + k;
            if (f[k]) { g_rank[b][n] = r; g_jmap[b][r] = n + 1; r++; }
            else        g_rank[b][n] = -1;
        }
        const int cnt = 1 + pref[256];
        if (tid == 0) { g_cnt[b] = cnt; g_jmap[b][0] = 0; }
        for (int i = cnt + tid; i < 2144; i += 256) g_jmap[b][i] = -1;
        __syncthreads();
    }

    for (int h = wid; h < H_; h += 8) {
        const int d0 = lane, d1 = lane + 32;
        const float k0 = null_kv[h*DH_ + d0], k1 = null_kv[h*DH_ + d1];
        const float v0 = null_kv[H_*DH_ + h*DH_ + d0];
        const float v1 = null_kv[H_*DH_ + h*DH_ + d1];
        float ss = k0*k0 + k1*k1;
        #pragma unroll
        for (int o = 16; o > 0; o >>= 1) ss += __shfl_xor_sync(0xFFFFFFFFu, ss, o);
        const float inv = 1.0f / fmaxf(sqrtf(ss), 1e-12f);
        const float ks0 = k_scale[d0], ks1 = k_scale[d1];
        #pragma unroll
        for (int b = 0; b < 2; b++) {
            const int bh = b*H_ + h;
            float* kp = g_k  + (size_t)bh * NK_ * DH_;
            float* vp = g_vt + (size_t)bh * DH_ * VTS_;
            kp[d0] = f2tff(k0*inv*ks0); kp[d1] = f2tff(k1*inv*ks1);
            vp[(size_t)d0*VTS_] = f2tff(v0);
            vp[(size_t)d1*VTS_] = f2tff(v1);
        }
    }
}

// ---------------------------------------------------------------------------
// bias gather into compacted layout
// ---------------------------------------------------------------------------
__global__ void bias_gather(const float* __restrict__ attn_bias) {
    const int row = blockIdx.x;
    const int b = row >> 11, i = row & 2047;
    const int* jm = g_jmap[b];
    const float* src = attn_bias + (size_t)(C_ + i)*LDBIAS_ + (C_ - 1);
    float* dst = g_biasc + (size_t)row * BCS_;
    for (int r = threadIdx.x; r < BCS_; r += 256) {
        const int off = jm[r];
        dst[r] = (off > 0) ? __ldg(src + off) : 0.f;
    }
}

// ---------------------------------------------------------------------------
// weight transpose + tf32 round (tiled 32x32, smem)
// ---------------------------------------------------------------------------
__global__ void round_wt_qkv(const float* __restrict__ Wq,
                             const float* __restrict__ Wkv) {
    __shared__ float t[32][33];
    const int k0 = blockIdx.x * 32, n0 = blockIdx.y * 32;
    const int tx = threadIdx.x, ty = threadIdx.y;   // 32 x 8
    #pragma unroll
    for (int i = 0; i < 32; i += 8) {
        const int k = k0 + ty + i, n = n0 + tx;
        t[ty + i][tx] = (n < 1024) ? Wq[(size_t)k*1024 + n]
                                   : Wkv[(size_t)k*2048 + n - 1024];
    }
    __syncthreads();
    #pragma unroll
    for (int i = 0; i < 32; i += 8) {
        const int n = n0 + ty + i, k = k0 + tx;
        g_wqkvt[(size_t)n*1024 + k] = f2tff(t[tx][ty + i]);
    }
}

__global__ void round_wt_o(const float* __restrict__ Wout) {
    __shared__ float t[32][33];
    const int k0 = blockIdx.x * 32, n0 = blockIdx.y * 32;
    const int tx = threadIdx.x, ty = threadIdx.y;
    #pragma unroll
    for (int i = 0; i < 32; i += 8)
        t[ty + i][tx] = Wout[(size_t)(k0 + ty + i)*1024 + n0 + tx];
    __syncthreads();
    #pragma unroll
    for (int i = 0; i < 32; i += 8)
        g_wot[(size_t)(n0 + ty + i)*1024 + k0 + tx] = f2tff(t[tx][ty + i]);
}

// ---------------------------------------------------------------------------
// LayerNorm (writes tf32-rounded xn; also compacted copy for valid kv rows)
// ---------------------------------------------------------------------------
__global__ void ln_kernel(const float* __restrict__ x,
                          const float* __restrict__ gamma) {
    const int row = blockIdx.x;
    const int tid = threadIdx.x;
    const float4 a = ((const float4*)(x + (size_t)row * D_))[tid];
    float s  = a.x + a.y + a.z + a.w;
    float s2 = a.x*a.x + a.y*a.y + a.z*a.z + a.w*a.w;
    #pragma unroll
    for (int o = 16; o > 0; o >>= 1) {
        s  += __shfl_xor_sync(0xFFFFFFFFu, s,  o);
        s2 += __shfl_xor_sync(0xFFFFFFFFu, s2, o);
    }
    __shared__ float rs[8], rs2[8];
    if ((tid & 31) == 0) { rs[tid >> 5] = s; rs2[tid >> 5] = s2; }
    __syncthreads();
    float S = 0.f, S2 = 0.f;
    #pragma unroll
    for (int i = 0; i < 8; i++) { S += rs[i]; S2 += rs2[i]; }
    const float mu  = S * (1.0f / D_);
    const float var = S2 * (1.0f / D_) - mu * mu;
    const float inv = rsqrtf(var + 1e-5f);
    const float4 g = ((const float4*)gamma)[tid];
    float4 o;
    o.x = f2tff((a.x - mu) * inv * g.x);
    o.y = f2tff((a.y - mu) * inv * g.y);
    o.z = f2tff((a.z - mu) * inv * g.z);
    o.w = f2tff((a.w - mu) * inv * g.w);
    ((float4*)(g_xn + (size_t)row * D_))[tid] = o;

    const int b = row >> 11, n = row & 2047;
    const int r = g_rank[b][n];
    if (r >= 1)
        ((float4*)(g_xnc + ((size_t)b*2048 + (r-1)) * D_))[tid] = o;
}

// ---------------------------------------------------------------------------
// tf32 GEMM v3 core: both operands [row][k] stride-20, ldmatrix A+B frags,
// 4-stage cp.async pipeline, 2 CTAs/SM.
// ---------------------------------------------------------------------------
#define TS_STR 20
#define TS_FL (128*TS_STR)            // 2560 floats per operand stage
#define GS 4
#define GEMM_SMEM ((GS*2*TS_FL)*4)    // 81920 bytes

__device__ __forceinline__ void gemm_stage(
    unsigned as_u, unsigned bs_u, int s,
    const float* __restrict__ A, const float* __restrict__ Bt,
    int bm, int bn, int k0)
{
    const int tid = threadIdx.x;
    #pragma unroll
    for (int i = 0; i < 2; i++) {
        const int idx = tid + i*256;
        const int r = idx >> 2, c4 = (idx & 3) * 4;
        const unsigned off = (unsigned)((s*TS_FL + r*TS_STR + c4) * 4);
        cpa16(as_u + off, A  + (size_t)(bm + r)*1024 + k0 + c4, 1);
        cpa16(bs_u + off, Bt + (size_t)(bn + r)*1024 + k0 + c4, 1);
    }
}

__device__ __forceinline__ void gemm_main_loop3(
    const float* __restrict__ A, const float* __restrict__ Bt,
    int bm, int bn, float* smemf,
    int wm, int wn, float acc[2][8][4])
{
    const unsigned as_u = (unsigned)__cvta_generic_to_shared(smemf);
    const unsigned bs_u = as_u + (unsigned)(GS*TS_FL*4);
    const int lane = threadIdx.x & 31;
    const int mi = lane >> 3, mr = lane & 7;
    const unsigned a_off = (unsigned)((((mi & 1)*8 + mr)*TS_STR + (mi >> 1)*4) * 4);
    const unsigned b_off = (unsigned)((((mi >> 1)*8 + mr)*TS_STR + (mi & 1)*4) * 4);

    #pragma unroll
    for (int s = 0; s < GS-1; s++) {
        gemm_stage(as_u, bs_u, s, A, Bt, bm, bn, s*16);
        cpa_commit();
    }

    for (int kt = 0; kt < 64; kt++) {
        cpa_wait2();
        __syncthreads();
        if (kt + GS - 1 < 64)
            gemm_stage(as_u, bs_u, (kt + GS - 1) & 3, A, Bt, bm, bn, (kt + GS - 1)*16);
        cpa_commit();

        const int buf = kt & 3;
        const unsigned abuf = as_u + (unsigned)(buf*TS_FL*4) + a_off;
        const unsigned bbuf = bs_u + (unsigned)(buf*TS_FL*4) + b_off;

        #pragma unroll
        for (int kk = 0; kk < 2; kk++) {
            unsigned afr[2][4];
            #pragma unroll
            for (int mt = 0; mt < 2; mt++)
                ldmx4(afr[mt][0], afr[mt][1], afr[mt][2], afr[mt][3],
                      abuf + (unsigned)(((wm*32 + mt*16)*TS_STR + kk*8) * 4));
            unsigned bfr[8][2];
            #pragma unroll
            for (int np = 0; np < 4; np++)
                ldmx4(bfr[2*np][0], bfr[2*np][1], bfr[2*np+1][0], bfr[2*np+1][1],
                      bbuf + (unsigned)(((wn*64 + np*16)*TS_STR + kk*8) * 4));
            #pragma unroll
            for (int mt = 0; mt < 2; mt++)
                #pragma unroll
                for (int nt = 0; nt < 8; nt++)
                    mma8(acc[mt][nt], afr[mt], bfr[nt]);
        }
    }
}

// ---------------------------------------------------------------------------
// Merged Q + KV GEMM. 1D grid of 768 blocks:
//   bid <  256: q tiles  (bn = (bid&7)*128 in 1024, bm = (bid>>3)*128 in 4096)
//   bid >= 256: kv tiles (batch = (bid-256)>>8, r = (bid-256)&255,
//               bn = (r&15)*128 in 2048, bm = (r>>4)*128; early-exit bm>=cnt-1)
// q epilogue folds SCALE=8 into q_scale (bit-exact power-of-2).
// ---------------------------------------------------------------------------
__global__ __launch_bounds__(256, 2)
void gemm_qkv2(const float* __restrict__ q_scale,
               const float* __restrict__ k_scale) {
    extern __shared__ __align__(16) float gsm[];
    const int bid = blockIdx.x;
    const int tid = threadIdx.x;
    const int wid = tid >> 5, lane = tid & 31;
    const int gid = lane >> 2, tig = lane & 3;
    const int wm = wid & 3, wn = wid >> 2;

    if (bid < 256) {
        const int bn = (bid & 7) * 128, bm = (bid >> 3) * 128;
        float acc[2][8][4] = {};
        gemm_main_loop3(g_xn, g_wqkvt, bm, bn, gsm, wm, wn, acc);

        const int hv = (bn + wn*64) >> 6;
        #pragma unroll
        for (int mt = 0; mt < 2; mt++) {
            #pragma unroll
            for (int i = 0; i < 2; i++) {
                const int row = bm + wm*32 + mt*16 + gid + i*8;
                const int bidx = row >> 11, n = row & 2047;
                float ss = 0.f;
                #pragma unroll
                for (int nt = 0; nt < 8; nt++)
                    ss += acc[mt][nt][i*2]*acc[mt][nt][i*2]
                        + acc[mt][nt][i*2+1]*acc[mt][nt][i*2+1];
                ss += __shfl_xor_sync(0xFFFFFFFFu, ss, 1);
                ss += __shfl_xor_sync(0xFFFFFFFFu, ss, 2);
                const float inv = 1.0f / fmaxf(sqrtf(ss), 1e-12f);
                float* dst = g_q + (((size_t)(bidx*H_ + hv))*N_ + n)*DH_;
                #pragma unroll
                for (int nt = 0; nt < 8; nt++) {
                    const int d = nt*8 + 2*tig;
                    *(float2*)(dst + d) = make_float2(
                        f2tff(acc[mt][nt][i*2]   * inv * (8.f*q_scale[d])),
                        f2tff(acc[mt][nt][i*2+1] * inv * (8.f*q_scale[d+1])));
                }
            }
        }
    } else {
        const int kvid = bid - 256;
        const int bidx = kvid >> 8;
        const int rr2 = kvid & 255;
        const int cntm = g_cnt[bidx] - 1;
        const int bm = (rr2 >> 4) * 128;
        if (bm >= cntm) return;
        const int bn = (rr2 & 15) * 128;

        const float* A  = g_xnc + (size_t)bidx * 2048 * D_;
        const float* Bt = g_wqkvt + (size_t)1024 * D_;

        float acc[2][8][4] = {};
        gemm_main_loop3(A, Bt, bm, bn, gsm, wm, wn, acc);

        const int hv = (bn + wn*64) >> 6;   // 0..15 k, 16..31 v
        #pragma unroll
        for (int mt = 0; mt < 2; mt++) {
            #pragma unroll
            for (int i = 0; i < 2; i++) {
                const int rr = bm + wm*32 + mt*16 + gid + i*8;
                if (rr >= cntm) continue;
                const int r = rr + 1;
                float ss = 0.f;
                #pragma unroll
                for (int nt = 0; nt < 8; nt++)
                    ss += acc[mt][nt][i*2]*acc[mt][nt][i*2]
                        + acc[mt][nt][i*2+1]*acc[mt][nt][i*2+1];
                ss += __shfl_xor_sync(0xFFFFFFFFu, ss, 1);
                ss += __shfl_xor_sync(0xFFFFFFFFu, ss, 2);

                if (hv < 16) {
                    const float inv = 1.0f / fmaxf(sqrtf(ss), 1e-12f);
                    float* dst = g_k + (((size_t)(bidx*H_ + hv))*NK_ + r)*DH_;
                    #pragma unroll
                    for (int nt = 0; nt < 8; nt++) {
                        const int d = nt*8 + 2*tig;
                        *(float2*)(dst + d) = make_float2(
                            f2tff(acc[mt][nt][i*2]   * inv * k_scale[d]),
                            f2tff(acc[mt][nt][i*2+1] * inv * k_scale[d+1]));
                    }
                } else {
                    float* dst = g_vt + ((size_t)(bidx*H_ + hv-16))*DH_*VTS_ + r;
                    #pragma unroll
                    for (int nt = 0; nt < 8; nt++) {
                        const int d = nt*8 + 2*tig;
                        dst[(size_t)d*VTS_]     = f2tff(acc[mt][nt][i*2]);
                        dst[(size_t)(d+1)*VTS_] = f2tff(acc[mt][nt][i*2+1]);
                    }
                }
            }
        }
    }
}

// Output GEMM: d_out(4096 x 1024) = g_ao @ Wout  (Bt = g_wot)
__global__ __launch_bounds__(256, 2)
void gemm_out_tc(float* __restrict__ out) {
    extern __shared__ __align__(16) float gsm[];
    const int tid = threadIdx.x;
    const int wid = tid >> 5, lane = tid & 31;
    const int gid = lane >> 2, tig = lane & 3;
    const int wm = wid & 3, wn = wid >> 2;
    const int bm = blockIdx.y * 128, bn = blockIdx.x * 128;

    float acc[2][8][4] = {};
    gemm_main_loop3(g_ao, g_wot, bm, bn, gsm, wm, wn, acc);

    #pragma unroll
    for (int mt = 0; mt < 2; mt++) {
        #pragma unroll
        for (int i = 0; i < 2; i++) {
            const int row = bm + wm*32 + mt*16 + gid + i*8;
            #pragma unroll
            for (int nt = 0; nt < 8; nt++) {
                const int col = bn + wn*64 + nt*8 + 2*tig;
                *(float2*)&out[(size_t)row*1024 + col] =
                    make_float2(acc[mt][nt][i*2], acc[mt][nt][i*2+1]);
            }
        }
    }
}

// ---------------------------------------------------------------------------
// tf32 flash attention (SCALE folded into q; otherwise unchanged from R14)
// ---------------------------------------------------------------------------
#define KS_STR 68
#define VT_STR 68
#define PS_STR 68

__device__ __forceinline__ void attn_prefetch_tile(
    int t, int cnt, int cpr, int cpc,
    unsigned ks_s0, unsigned vt_s0,
    const float* __restrict__ kb, const float* __restrict__ vtb)
{
    const int jb = t * 64;
    const unsigned kdst = ks_s0 + (unsigned)((t & 1) * 4352 * 4);
    const unsigned vdst = vt_s0 + (unsigned)((t & 1) * 4352 * 4);
    #pragma unroll
    for (int i = 0; i < 4; i++) {
        const int r = cpr + i*16;
        const int okk = (jb + r) < cnt;
        const int okv = (jb + cpc) < cnt;
        cpa16(kdst + (unsigned)(r*KS_STR + cpc)*4, kb  + (size_t)(jb + r)*64 + cpc, okk);
        cpa16(vdst + (unsigned)(r*VT_STR + cpc)*4, vtb + (size_t)r*VTS_ + jb + cpc, okv);
    }
}

__global__ __launch_bounds__(256, 2)
void attn_tc2() {
    extern __shared__ __align__(16) float smf[];
    float* Ksf = smf;
    float* Vtf = smf + 8704;
    float* Psf = smf + 17408;

    const int tid = threadIdx.x;
    const int wid = tid >> 5, lane = tid & 31;
    const int gid = lane >> 2, tig = lane & 3;
    const int qt = blockIdx.x & 15, bh = blockIdx.x >> 4;
    const int b = bh >> 4, h = bh & 15;
    const int i0 = qt * 128;

    const int cnt   = g_cnt[b];
    const int tiles = (cnt + 63) >> 6;

    const int mi = lane >> 3, mr = lane & 7;
    const unsigned kv_off = (unsigned)((((mi >> 1)*8 + mr)*KS_STR + (mi & 1)*4) * 4);
    const unsigned p_off  = (unsigned)((((mi & 1)*8 + mr)*PS_STR + (mi >> 1)*4) * 4);

    unsigned qa[8][4];
    {
        const float* qb = g_q + ((size_t)bh*N_ + i0 + wid*16)*DH_;
        #pragma unroll
        for (int ks = 0; ks < 8; ks++) {
            qa[ks][0] = __float_as_uint(qb[gid*64 + ks*8 + tig]);
            qa[ks][1] = __float_as_uint(qb[(gid+8)*64 + ks*8 + tig]);
            qa[ks][2] = __float_as_uint(qb[gid*64 + ks*8 + tig + 4]);
            qa[ks][3] = __float_as_uint(qb[(gid+8)*64 + ks*8 + tig + 4]);
        }
    }

    float O[8][4];
    #pragma unroll
    for (int nt = 0; nt < 8; nt++)
        #pragma unroll
        for (int i = 0; i < 4; i++) O[nt][i] = 0.f;
    float m0 = -FLT_MAX, m1 = -FLT_MAX, l0 = 0.f, l1 = 0.f;

    const float* kb  = g_k  + (size_t)bh * NK_ * DH_;
    const float* vtb = g_vt + (size_t)bh * DH_ * VTS_;
    const float* bcA = g_biasc + (size_t)(b*N_ + i0 + wid*16 + gid) * BCS_;
    const float* bcB = bcA + (size_t)8 * BCS_;
    float* pw = Psf + wid * (16 * PS_STR);

    const unsigned ks_s0 = (unsigned)__cvta_generic_to_shared(Ksf);
    const unsigned vt_s0 = (unsigned)__cvta_generic_to_shared(Vtf);
    const unsigned pw_s0 = (unsigned)__cvta_generic_to_shared(pw);
    const int cpr = tid >> 4, cpc = (tid & 15) * 4;

    attn_prefetch_tile(0, cnt, cpr, cpc, ks_s0, vt_s0, kb, vtb);
    cpa_commit();
    __syncthreads();

    for (int t = 0; t < tiles; t++) {
        const int buf = t & 1;
        const int jb = t * 64;
        if (t + 1 < tiles)
            attn_prefetch_tile(t + 1, cnt, cpr, cpc, ks_s0, vt_s0, kb, vtb);
        cpa_commit();

        cpa_wait1();
        __syncthreads();

        const unsigned kbase = ks_s0 + (unsigned)(buf * 4352 * 4) + kv_off;
        const unsigned vbase = vt_s0 + (unsigned)(buf * 4352 * 4) + kv_off;

        float sc[8][4];
        #pragma unroll
        for (int nt = 0; nt < 8; nt++)
            #pragma unroll
            for (int i = 0; i < 4; i++) sc[nt][i] = 0.f;
        #pragma unroll
        for (int ks = 0; ks < 8; ks++) {
            unsigned kf[8][2];
            #pragma unroll
            for (int np = 0; np < 4; np++)
                ldmx4(kf[2*np][0], kf[2*np][1], kf[2*np+1][0], kf[2*np+1][1],
                      kbase + (unsigned)(((2*np)*8*KS_STR + ks*8) * 4));
            #pragma unroll
            for (int nt = 0; nt < 8; nt++)
                mma8(sc[nt], qa[ks], kf[nt]);
        }

        float mx0 = -FLT_MAX, mx1 = -FLT_MAX;
        #pragma unroll
        for (int nt = 0; nt < 8; nt++) {
            const int c0 = jb + nt*8 + 2*tig;
            const bool v0 = c0 < cnt, v1 = (c0 + 1) < cnt;
            const float2 ba = *(const float2*)(bcA + c0);
            const float2 bb2 = *(const float2*)(bcB + c0);
            sc[nt][0] = v0 ? sc[nt][0] + ba.x  : -FLT_MAX;
            sc[nt][1] = v1 ? sc[nt][1] + ba.y  : -FLT_MAX;
            sc[nt][2] = v0 ? sc[nt][2] + bb2.x : -FLT_MAX;
            sc[nt][3] = v1 ? sc[nt][3] + bb2.y : -FLT_MAX;
            mx0 = fmaxf(mx0, fmaxf(sc[nt][0], sc[nt][1]));
            mx1 = fmaxf(mx1, fmaxf(sc[nt][2], sc[nt][3]));
        }
        mx0 = fmaxf(mx0, __shfl_xor_sync(0xFFFFFFFFu, mx0, 1));
        mx0 = fmaxf(mx0, __shfl_xor_sync(0xFFFFFFFFu, mx0, 2));
        mx1 = fmaxf(mx1, __shfl_xor_sync(0xFFFFFFFFu, mx1, 1));
        mx1 = fmaxf(mx1, __shfl_xor_sync(0xFFFFFFFFu, mx1, 2));
        const float mn0 = fmaxf(m0, mx0), mn1 = fmaxf(m1, mx1);
        const float f0 = __expf(m0 - mn0), f1 = __expf(m1 - mn1);
        float s0 = 0.f, s1 = 0.f;
        unsigned* pwu = (unsigned*)pw;
        #pragma unroll
        for (int nt = 0; nt < 8; nt++) {
            const float p0 = __expf(sc[nt][0] - mn0);
            const float p1 = __expf(sc[nt][1] - mn0);
            const float p2 = __expf(sc[nt][2] - mn1);
            const float p3 = __expf(sc[nt][3] - mn1);
            s0 += p0 + p1; s1 += p2 + p3;
            const int c0 = nt*8 + 2*tig;
            *(uint2*)(pwu + gid*PS_STR + c0)     = make_uint2(f2tf(p0), f2tf(p1));
            *(uint2*)(pwu + (gid+8)*PS_STR + c0) = make_uint2(f2tf(p2), f2tf(p3));
        }
        s0 += __shfl_xor_sync(0xFFFFFFFFu, s0, 1);
        s0 += __shfl_xor_sync(0xFFFFFFFFu, s0, 2);
        s1 += __shfl_xor_sync(0xFFFFFFFFu, s1, 1);
        s1 += __shfl_xor_sync(0xFFFFFFFFu, s1, 2);
        l0 = l0 * f0 + s0; l1 = l1 * f1 + s1;
        m0 = mn0; m1 = mn1;
        #pragma unroll
        for (int nt = 0; nt < 8; nt++) {
            O[nt][0] *= f0; O[nt][1] *= f0;
            O[nt][2] *= f1; O[nt][3] *= f1;
        }
        __syncwarp();

        #pragma unroll
        for (int ks = 0; ks < 8; ks++) {
            unsigned pa[4];
            ldmx4(pa[0], pa[1], pa[2], pa[3], pw_s0 + p_off + (unsigned)(ks*8*4));
            unsigned vf[8][2];
            #pragma unroll
            for (int np = 0; np < 4; np++)
                ldmx4(vf[2*np][0], vf[2*np][1], vf[2*np+1][0], vf[2*np+1][1],
                      vbase + (unsigned)(((2*np)*8*VT_STR + ks*8) * 4));
            #pragma unroll
            for (int nt = 0; nt < 8; nt++)
                mma8(O[nt], pa, vf[nt]);
        }
        __syncthreads();
    }

    const float inv0 = 1.f / l0, inv1 = 1.f / l1;
    float* ob = g_ao + ((size_t)b*N_ + i0 + wid*16)*1024 + h*64;
    #pragma unroll
    for (int nt = 0; nt < 8; nt++) {
        const int c0 = nt*8 + 2*tig;
        *(float2*)(ob + (size_t)gid*1024 + c0) =
            make_float2(f2tff(O[nt][0]*inv0), f2tff(O[nt][1]*inv0));
        *(float2*)(ob + (size_t)(gid+8)*1024 + c0) =
            make_float2(f2tff(O[nt][2]*inv1), f2tff(O[nt][3]*inv1));
    }
}

// ---------------------------------------------------------------------------
extern "C" void kernel_launch(void* const* d_in, const int* in_sizes, int n_in,
                              void* d_out, int out_size) {
    const float* x         = (const float*)d_in[0];
    const float* attn_bias = (const float*)d_in[1];
    const void*  cmask     = (const void*) d_in[2];
    const float* gamma     = (const float*)d_in[3];
    const float* null_kv   = (const float*)d_in[4];
    const float* Wq        = (const float*)d_in[5];
    const float* Wkv       = (const float*)d_in[6];
    const float* q_scale   = (const float*)d_in[7];
    const float* k_scale   = (const float*)d_in[8];
    const float* Wout      = (const float*)d_in[9];
    float* out = (float*)d_out;

    static const int attn_smem = 26112 * 4;   // 104448 B
    cudaFuncSetAttribute(attn_tc2,
                         cudaFuncAttributeMaxDynamicSharedMemorySize,
                         attn_smem);
    cudaFuncSetAttribute(gemm_qkv2,
                         cudaFuncAttributeMaxDynamicSharedMemorySize,
                         GEMM_SMEM);
    cudaFuncSetAttribute(gemm_out_tc,
                         cudaFuncAttributeMaxDynamicSharedMemorySize,
                         GEMM_SMEM);

    prep_kernel<<<1, 256>>>((const unsigned char*)cmask, null_kv, k_scale);
    bias_gather<<<ROWS_, 256>>>(attn_bias);
    round_wt_qkv<<<dim3(32, 96), dim3(32, 8)>>>(Wq, Wkv);
    round_wt_o<<<dim3(32, 32), dim3(32, 8)>>>(Wout);
    ln_kernel<<<ROWS_, 256>>>(x, gamma);
    gemm_qkv2<<<768, 256, GEMM_SMEM>>>(q_scale, k_scale);
    attn_tc2<<<BH_ * 16, 256, attn_smem>>>();
    gemm_out_tc<<<dim3(8, 32), 256, GEMM_SMEM>>>(out);
}